// round 7
// baseline (speedup 1.0000x reference)
#include <cuda_runtime.h>
#include <cuda_bf16.h>
#include <math.h>

// ---------------- problem constants ----------------
#define N_NODES 50000
#define E_EDGES 300000
#define F_IN    128
#define HID     256
#define G_GRP   1000
#define NUM_GC  5
#define NH      (N_NODES * HID)          // 12,800,000

typedef unsigned long long ull;

// ---------------- scratch ----------------
// float scratch: h, q, k, v, t(gw), y(agg), kvs(64K), kssum(256), scal(16),
//                dinv(N), coef_s/t (2*5*256), cw (E)
__device__ float d_scratch[6 * (size_t)NH + 65536 + 256 + 16 + N_NODES
                           + 2 * NUM_GC * HID + E_EDGES];
// int scratch: cnt(N), off(N+1), cur(N), csrc(E)
__device__ int d_iscratch[3 * N_NODES + 1 + E_EDGES];

// ---------------- f32x2 helpers ----------------
__device__ __forceinline__ void ffma2(ull& d, ull a, ull b) {
    asm("fma.rn.f32x2 %0, %1, %2, %0;" : "+l"(d) : "l"(a), "l"(b));
}
__device__ __forceinline__ ull pack2(float x, float y) {
    ull r;
    asm("mov.b64 %0, {%1, %2};" : "=l"(r) : "f"(x), "f"(y));
    return r;
}
__device__ __forceinline__ void unpack2(float& lo, float& hi, ull v) {
    asm("mov.b64 {%0, %1}, %2;" : "=f"(lo), "=f"(hi) : "l"(v));
}

// ---------------- misc helpers ----------------
__device__ __forceinline__ float warp_sum(float v) {
#pragma unroll
    for (int o = 16; o; o >>= 1) v += __shfl_xor_sync(0xffffffffu, v, o);
    return v;
}
__device__ __forceinline__ float block_sum_256(float v, float* sh) {
    v = warp_sum(v);
    if ((threadIdx.x & 31) == 0) sh[threadIdx.x >> 5] = v;
    __syncthreads();
    if (threadIdx.x < 32) {
        float t = (threadIdx.x < 8) ? sh[threadIdx.x] : 0.f;
        t = warp_sum(t);
        if (threadIdx.x == 0) sh[8] = t;
    }
    __syncthreads();
    float r = sh[8];
    __syncthreads();
    return r;
}

__global__ void zero_kernel(float* __restrict__ p, int n) {
    int i = blockIdx.x * blockDim.x + threadIdx.x;
    if (i < n) p[i] = 0.f;
}
__global__ void zero_int_kernel(int* __restrict__ p, int n) {
    int i = blockIdx.x * blockDim.x + threadIdx.x;
    if (i < n) p[i] = 0;
}

// ============ 128x128x16 SGEMM, f32x2 FFMA2, duplicated-A smem ============
// C[M,Nn] = A[M,K] @ B[K,Nn] (+bias). 256 threads, 8x8/thread, double buffered.
// Requires Nn % 128 == 0, K % 16 == 0.
__global__ void __launch_bounds__(256, 2) sgemm128(
    const float* __restrict__ A, const float* __restrict__ B,
    const float* __restrict__ bias, float* __restrict__ C,
    int M, int Nn, int K)
{
    __shared__ __align__(16) float As[2][16][256];   // [k][2*row(+1)] duplicated
    __shared__ __align__(16) float Bs[2][16][128];

    const int tid = threadIdx.x;
    const int tx = tid & 15;
    const int ty = tid >> 4;
    const int row0 = blockIdx.y * 128;
    const int col0 = blockIdx.x * 128;

    const int arow = tid >> 1;            // 0..127
    const int ak8  = (tid & 1) * 8;       // 0 or 8
    const int brow = tid >> 5;            // 0..7 (loads k rows brow, brow+8)
    const int bc4  = (tid & 31) * 4;      // 0..124

    const int KT = K >> 4;

    ull acc[8][4];
#pragma unroll
    for (int i = 0; i < 8; i++)
#pragma unroll
        for (int j = 0; j < 4; j++) acc[i][j] = 0ull;

    float4 av0, av1, bv0, bv1;

    // prologue fetch (stage 0)
    {
        int r = row0 + arow;
        if (r < M) {
            av0 = *reinterpret_cast<const float4*>(&A[(size_t)r * K + ak8]);
            av1 = *reinterpret_cast<const float4*>(&A[(size_t)r * K + ak8 + 4]);
        } else { av0 = make_float4(0,0,0,0); av1 = av0; }
        bv0 = *reinterpret_cast<const float4*>(&B[(size_t)brow * Nn + col0 + bc4]);
        bv1 = *reinterpret_cast<const float4*>(&B[(size_t)(brow + 8) * Nn + col0 + bc4]);
        float am[8] = {av0.x, av0.y, av0.z, av0.w, av1.x, av1.y, av1.z, av1.w};
#pragma unroll
        for (int m = 0; m < 8; m++)
            *reinterpret_cast<ull*>(&As[0][ak8 + m][2 * arow]) = pack2(am[m], am[m]);
        *reinterpret_cast<float4*>(&Bs[0][brow][bc4]) = bv0;
        *reinterpret_cast<float4*>(&Bs[0][brow + 8][bc4]) = bv1;
    }
    __syncthreads();

    for (int kt = 0; kt < KT; kt++) {
        const int buf = kt & 1;
        if (kt + 1 < KT) {
            const int k0 = (kt + 1) << 4;
            int r = row0 + arow;
            if (r < M) {
                av0 = *reinterpret_cast<const float4*>(&A[(size_t)r * K + k0 + ak8]);
                av1 = *reinterpret_cast<const float4*>(&A[(size_t)r * K + k0 + ak8 + 4]);
            } else { av0 = make_float4(0,0,0,0); av1 = av0; }
            bv0 = *reinterpret_cast<const float4*>(&B[(size_t)(k0 + brow) * Nn + col0 + bc4]);
            bv1 = *reinterpret_cast<const float4*>(&B[(size_t)(k0 + brow + 8) * Nn + col0 + bc4]);
        }

#pragma unroll
        for (int k = 0; k < 16; k++) {
            // pre-packed (a,a) pairs: rows ty*4..+3 and 64+ty*4..+3
            ulonglong2 aL0 = *reinterpret_cast<const ulonglong2*>(&As[buf][k][ty * 8]);
            ulonglong2 aL1 = *reinterpret_cast<const ulonglong2*>(&As[buf][k][ty * 8 + 4]);
            ulonglong2 aH0 = *reinterpret_cast<const ulonglong2*>(&As[buf][k][128 + ty * 8]);
            ulonglong2 aH1 = *reinterpret_cast<const ulonglong2*>(&As[buf][k][128 + ty * 8 + 4]);
            ulonglong2 b0 = *reinterpret_cast<const ulonglong2*>(&Bs[buf][k][tx * 4]);
            ulonglong2 b1 = *reinterpret_cast<const ulonglong2*>(&Bs[buf][k][64 + tx * 4]);
            ull ap[8] = {aL0.x, aL0.y, aL1.x, aL1.y, aH0.x, aH0.y, aH1.x, aH1.y};
#pragma unroll
            for (int i = 0; i < 8; i++) {
                ffma2(acc[i][0], ap[i], b0.x);
                ffma2(acc[i][1], ap[i], b0.y);
                ffma2(acc[i][2], ap[i], b1.x);
                ffma2(acc[i][3], ap[i], b1.y);
            }
        }

        if (kt + 1 < KT) {
            const int nb = buf ^ 1;
            float am[8] = {av0.x, av0.y, av0.z, av0.w, av1.x, av1.y, av1.z, av1.w};
#pragma unroll
            for (int m = 0; m < 8; m++)
                *reinterpret_cast<ull*>(&As[nb][ak8 + m][2 * arow]) = pack2(am[m], am[m]);
            *reinterpret_cast<float4*>(&Bs[nb][brow][bc4]) = bv0;
            *reinterpret_cast<float4*>(&Bs[nb][brow + 8][bc4]) = bv1;
        }
        __syncthreads();
    }

    // epilogue
    float4 b_lo = make_float4(0,0,0,0), b_hi = b_lo;
    if (bias) {
        b_lo = *reinterpret_cast<const float4*>(&bias[col0 + tx * 4]);
        b_hi = *reinterpret_cast<const float4*>(&bias[col0 + 64 + tx * 4]);
    }
#pragma unroll
    for (int i = 0; i < 8; i++) {
        int row = row0 + ((i < 4) ? (ty * 4 + i) : (64 + ty * 4 + (i - 4)));
        if (row >= M) continue;
        float o0, o1, o2, o3, o4, o5, o6, o7;
        unpack2(o0, o1, acc[i][0]); unpack2(o2, o3, acc[i][1]);
        unpack2(o4, o5, acc[i][2]); unpack2(o6, o7, acc[i][3]);
        float4 lo = make_float4(o0 + b_lo.x, o1 + b_lo.y, o2 + b_lo.z, o3 + b_lo.w);
        float4 hi = make_float4(o4 + b_hi.x, o5 + b_hi.y, o6 + b_hi.z, o7 + b_hi.w);
        *reinterpret_cast<float4*>(&C[(size_t)row * Nn + col0 + tx * 4]) = lo;
        *reinterpret_cast<float4*>(&C[(size_t)row * Nn + col0 + 64 + tx * 4]) = hi;
    }
}

// ------ C[256,256] += A[L,256]^T @ B[L,256], split-K atomics, f32x2 --------
__global__ void __launch_bounds__(256) atb_kernel(
    const float* __restrict__ A, const float* __restrict__ B,
    float* __restrict__ C, int L, int rows_per_z)
{
    __shared__ __align__(16) float As[32][128];   // duplicated A-cols
    __shared__ __align__(16) float Bs[32][64];

    const int tid = threadIdx.x;
    const int tx = tid & 15;
    const int ty = tid >> 4;
    const int ar0 = blockIdx.y * 64;
    const int bc0 = blockIdx.x * 64;
    const int lstart = blockIdx.z * rows_per_z;
    const int lend = min(L, lstart + rows_per_z);

    ull acc[4][2];
#pragma unroll
    for (int i = 0; i < 4; i++) { acc[i][0] = 0ull; acc[i][1] = 0ull; }

    for (int l0 = lstart; l0 < lend; l0 += 32) {
#pragma unroll
        for (int p = 0; p < 2; p++) {
            int id = tid + p * 256;
            int lr = id >> 4;
            int c4 = (id & 15) * 4;
            int l = l0 + lr;
            float4 avv, bvv;
            if (l < lend) {
                avv = *reinterpret_cast<const float4*>(&A[(size_t)l * HID + ar0 + c4]);
                bvv = *reinterpret_cast<const float4*>(&B[(size_t)l * HID + bc0 + c4]);
            } else { avv = make_float4(0,0,0,0); bvv = avv; }
            float am[4] = {avv.x, avv.y, avv.z, avv.w};
#pragma unroll
            for (int m = 0; m < 4; m++)
                *reinterpret_cast<ull*>(&As[lr][2 * (c4 + m)]) = pack2(am[m], am[m]);
            *reinterpret_cast<float4*>(&Bs[lr][c4]) = bvv;
        }
        __syncthreads();

#pragma unroll
        for (int l = 0; l < 32; l++) {
            ulonglong2 a01 = *reinterpret_cast<const ulonglong2*>(&As[l][ty * 8]);
            ulonglong2 a23 = *reinterpret_cast<const ulonglong2*>(&As[l][ty * 8 + 4]);
            ulonglong2 bp  = *reinterpret_cast<const ulonglong2*>(&Bs[l][tx * 4]);
            ull ap[4] = {a01.x, a01.y, a23.x, a23.y};
#pragma unroll
            for (int i = 0; i < 4; i++) {
                ffma2(acc[i][0], ap[i], bp.x);
                ffma2(acc[i][1], ap[i], bp.y);
            }
        }
        __syncthreads();
    }

#pragma unroll
    for (int i = 0; i < 4; i++) {
        float c0, c1, c2, c3;
        unpack2(c0, c1, acc[i][0]); unpack2(c2, c3, acc[i][1]);
        float* base = &C[(size_t)(ar0 + ty * 4 + i) * HID + bc0 + tx * 4];
        atomicAdd(base + 0, c0); atomicAdd(base + 1, c1);
        atomicAdd(base + 2, c2); atomicAdd(base + 3, c3);
    }
}

// ---------------- LN + relu ----------------
__global__ void __launch_bounds__(256) ln_relu_kernel(
    const float* __restrict__ t, const float* __restrict__ g,
    const float* __restrict__ b, float* __restrict__ out)
{
    __shared__ float sh[16];
    int row = blockIdx.x, c = threadIdx.x;
    float v = t[(size_t)row * HID + c];
    float s  = block_sum_256(v, sh);
    float s2 = block_sum_256(v * v, sh);
    float mean = s * (1.f / HID);
    float var  = s2 * (1.f / HID) - mean * mean;
    float y = (v - mean) * rsqrtf(var + 1e-5f) * g[c] + b[c];
    out[(size_t)row * HID + c] = fmaxf(y, 0.f);
}

// ---------------- sum of squares ----------------
__global__ void __launch_bounds__(256) sumsq_kernel(
    const float4* __restrict__ p, int n4, float* __restrict__ out)
{
    __shared__ float sh[16];
    float s = 0.f;
    for (int i = blockIdx.x * blockDim.x + threadIdx.x; i < n4;
         i += gridDim.x * blockDim.x) {
        float4 v = p[i];
        s += v.x * v.x + v.y * v.y + v.z * v.z + v.w * v.w;
    }
    float tot = block_sum_256(s, sh);
    if (threadIdx.x == 0) atomicAdd(out, tot);
}

// ---------------- column sum + sumsq of k (wide grid) ----------------
__global__ void __launch_bounds__(256) colsum_sq_kernel(
    const float* __restrict__ k, float* __restrict__ colsum, float* __restrict__ ss)
{
    __shared__ float sh[16];
    int c = threadIdx.x;
    float acc = 0.f, s2 = 0.f;
    for (int r = blockIdx.x; r < N_NODES; r += gridDim.x) {
        float v = k[(size_t)r * HID + c];
        acc += v;
        s2 += v * v;
    }
    atomicAdd(&colsum[c], acc);
    float tot = block_sum_256(s2, sh);
    if (c == 0) atomicAdd(ss, tot);
}

// ---------------- scale kvs / kssum by 1/||k|| ----------------
__global__ void scale_kvs_kernel(float* __restrict__ kvs, float* __restrict__ kssum,
                                 const float* __restrict__ scal)
{
    float sk = rsqrtf(scal[1]);
    int i = blockIdx.x * blockDim.x + threadIdx.x;
    if (i < HID * HID) kvs[i] *= sk;
    if (i < HID) kssum[i] *= sk;
}

// ---------------- TransConv epilogue ----------------
__global__ void __launch_bounds__(256) trans_epi_kernel(
    const float* __restrict__ q, const float* __restrict__ t2,
    const float* __restrict__ v, const float* __restrict__ h,
    const float* __restrict__ kssum, const float* __restrict__ scal,
    const float* __restrict__ g1, const float* __restrict__ b1,
    float* __restrict__ out_xt)
{
    __shared__ float sh[16];
    int row = blockIdx.x, c = threadIdx.x;
    size_t o = (size_t)row * HID + c;
    float rq = rsqrtf(scal[0]);
    float qv = q[o];
    float dot = block_sum_256(qv * kssum[c], sh);
    float denom = rq * dot + (float)N_NODES;
    float attn = (rq * t2[o] + (float)N_NODES * v[o]) / denom;
    float h1 = 0.5f * attn + 0.5f * h[o];
    float s  = block_sum_256(h1, sh);
    float s2 = block_sum_256(h1 * h1, sh);
    float mean = s * (1.f / HID);
    float var  = s2 * (1.f / HID) - mean * mean;
    float y = (h1 - mean) * rsqrtf(var + 1e-5f) * g1[c] + b1[c];
    y = fmaxf(y, 0.f);
    float ss = block_sum_256(y * y, sh);
    out_xt[o] = y / fmaxf(sqrtf(ss), 1e-12f);
}

// ---------------- BN affine coefficients ----------------
__global__ void bn_coef_kernel(const float* __restrict__ gcn_b0, const float* __restrict__ gcn_b,
                               const float* __restrict__ bn_g, const float* __restrict__ bn_b,
                               const float* __restrict__ bn_mean, const float* __restrict__ bn_var,
                               float* __restrict__ coef_s, float* __restrict__ coef_t)
{
    int idx = blockIdx.x * blockDim.x + threadIdx.x;
    if (idx >= NUM_GC * HID) return;
    int layer = idx >> 8, c = idx & 255;
    float b = (layer == 0) ? gcn_b0[c] : gcn_b[(size_t)(layer - 1) * HID + c];
    float rs = rsqrtf(bn_var[idx] + 1e-5f);
    float sv = bn_g[idx] * rs;
    coef_s[idx] = sv;
    coef_t[idx] = (b - bn_mean[idx]) * sv + bn_b[idx];
}

// ---------------- CSR build ----------------
__global__ void count_kernel(const int* __restrict__ dst, int* __restrict__ cnt) {
    int e = blockIdx.x * blockDim.x + threadIdx.x;
    if (e < E_EDGES) atomicAdd(&cnt[dst[e]], 1);
}

// single block of 1024: exclusive scan over cnt -> off & cur; dinv from cnt.
__global__ void __launch_bounds__(1024) scan_kernel(
    const int* __restrict__ cnt, int* __restrict__ off, int* __restrict__ cur,
    float* __restrict__ dinv)
{
    __shared__ int part[1024];
    const int T = 1024;
    const int CHUNK = (N_NODES + T - 1) / T;   // 49
    int t = threadIdx.x;
    int lo = t * CHUNK, hi = min(N_NODES, lo + CHUNK);
    int s = 0;
    for (int i = lo; i < hi; i++) s += cnt[i];
    part[t] = s;
    __syncthreads();
    for (int d = 1; d < T; d <<= 1) {
        int v = (t >= d) ? part[t - d] : 0;
        __syncthreads();
        part[t] += v;
        __syncthreads();
    }
    int run = (t == 0) ? 0 : part[t - 1];
    for (int i = lo; i < hi; i++) {
        off[i] = run;
        cur[i] = run;
        int c = cnt[i];
        run += c;
        dinv[i] = rsqrtf((float)(c + 1));
    }
    if (t == T - 1) off[N_NODES] = run;
}

__global__ void fill_kernel(const int* __restrict__ src, const int* __restrict__ dst,
                            const float* __restrict__ dinv,
                            int* __restrict__ cur, int* __restrict__ csrc,
                            float* __restrict__ cw)
{
    int e = blockIdx.x * blockDim.x + threadIdx.x;
    if (e >= E_EDGES) return;
    int d = dst[e];
    int s = src[e];
    int pos = atomicAdd(&cur[d], 1);
    csrc[pos] = s;
    cw[pos] = dinv[s];
}

// ------- CSR aggregation + self loop + (affine+relu for next layer) --------
// grid = N/4 blocks, 256 threads; 4 rows per block, float4 per thread.
__global__ void __launch_bounds__(256) csr_agg_kernel(
    const float4* __restrict__ gw, const int* __restrict__ off,
    const int* __restrict__ csrc, const float* __restrict__ cw,
    const float* __restrict__ dinv,
    const float* __restrict__ aff_s, const float* __restrict__ aff_t,
    float4* __restrict__ outy)
{
    int row = blockIdx.x * 4 + (threadIdx.x >> 6);
    int c4 = threadIdx.x & 63;
    float di = dinv[row];
    float4 g = gw[(size_t)row * 64 + c4];
    float4 acc = make_float4(g.x * di, g.y * di, g.z * di, g.w * di);
    int e0 = off[row], e1 = off[row + 1];
    for (int j = e0; j < e1; j++) {
        int s = __ldg(&csrc[j]);
        float w = __ldg(&cw[j]);
        float4 gv = gw[(size_t)s * 64 + c4];
        acc.x = fmaf(w, gv.x, acc.x);
        acc.y = fmaf(w, gv.y, acc.y);
        acc.z = fmaf(w, gv.z, acc.z);
        acc.w = fmaf(w, gv.w, acc.w);
    }
    acc.x *= di; acc.y *= di; acc.z *= di; acc.w *= di;
    if (aff_s) {
        float4 s4 = *reinterpret_cast<const float4*>(&aff_s[c4 * 4]);
        float4 t4 = *reinterpret_cast<const float4*>(&aff_t[c4 * 4]);
        acc.x = fmaxf(fmaf(acc.x, s4.x, t4.x), 0.f);
        acc.y = fmaxf(fmaf(acc.y, s4.y, t4.y), 0.f);
        acc.z = fmaxf(fmaf(acc.z, s4.z, t4.z), 0.f);
        acc.w = fmaxf(fmaf(acc.w, s4.w, t4.w), 0.f);
    }
    outy[(size_t)row * 64 + c4] = acc;
}

// ---------------- final: affine(layer4) -> l2 norm -> out_g + pool ---------
__global__ void __launch_bounds__(256) final_kernel(
    const float* __restrict__ agg, const float* __restrict__ s4, const float* __restrict__ t4,
    const int* __restrict__ batch,
    float* __restrict__ out_g, float* __restrict__ out_pool)
{
    __shared__ float sh[16];
    int row = blockIdx.x, c = threadIdx.x;
    float v = agg[(size_t)row * HID + c] * s4[c] + t4[c];
    float ss = block_sum_256(v * v, sh);
    float y = v / fmaxf(sqrtf(ss), 1e-12f);
    out_g[(size_t)row * HID + c] = y;
    atomicAdd(&out_pool[(size_t)batch[row] * HID + c], y);
}

// ---------------- launcher ----------------
extern "C" void kernel_launch(void* const* d_in, const int* in_sizes, int n_in,
                              void* d_out, int out_size)
{
    const float* x       = (const float*)d_in[0];
    const int*   edge    = (const int*)  d_in[1];
    const int*   batch   = (const int*)  d_in[2];
    // d_in[3] = beta (unused)
    const float* fc_W    = (const float*)d_in[4];
    const float* fc_b    = (const float*)d_in[5];
    const float* ln0_g   = (const float*)d_in[6];
    const float* ln0_b   = (const float*)d_in[7];
    const float* Wq      = (const float*)d_in[8];
    const float* bq      = (const float*)d_in[9];
    const float* Wk      = (const float*)d_in[10];
    const float* bk      = (const float*)d_in[11];
    const float* Wv      = (const float*)d_in[12];
    const float* bv      = (const float*)d_in[13];
    const float* ln1_g   = (const float*)d_in[14];
    const float* ln1_b   = (const float*)d_in[15];
    const float* gcn_W0  = (const float*)d_in[16];
    const float* gcn_b0  = (const float*)d_in[17];
    const float* gcn_W   = (const float*)d_in[18];
    const float* gcn_b   = (const float*)d_in[19];
    const float* bn_g    = (const float*)d_in[20];
    const float* bn_b    = (const float*)d_in[21];
    const float* bn_mean = (const float*)d_in[22];
    const float* bn_var  = (const float*)d_in[23];

    const int* src = edge;
    const int* dst = edge + E_EDGES;

    float* out      = (float*)d_out;
    float* out_pool = out;                               // [G, HID]
    float* out_g    = out + (size_t)G_GRP * HID;         // [N, HID]
    float* out_xt   = out_g + (size_t)N_NODES * HID;     // [N, HID]

    float* fbase = nullptr;
    int* ibase = nullptr;
    cudaGetSymbolAddress((void**)&fbase, d_scratch);
    cudaGetSymbolAddress((void**)&ibase, d_iscratch);

    float* p_h     = fbase;
    float* p_q     = fbase + (size_t)1 * NH;
    float* p_k     = fbase + (size_t)2 * NH;
    float* p_v     = fbase + (size_t)3 * NH;
    float* p_t     = fbase + (size_t)4 * NH;            // gw / gemm scratch
    float* p_y     = fbase + (size_t)5 * NH;            // agg output / next input
    float* p_kvs   = fbase + (size_t)6 * NH;
    float* p_kssum = p_kvs + HID * HID;
    float* p_scal  = p_kssum + HID;
    float* p_dinv  = p_scal + 16;
    float* p_cs    = p_dinv + N_NODES;
    float* p_ct    = p_cs + NUM_GC * HID;
    float* p_cw    = p_ct + NUM_GC * HID;                // [E]

    int* p_cnt  = ibase;                                 // [N]
    int* p_off  = p_cnt + N_NODES;                       // [N+1]
    int* p_cur  = p_off + N_NODES + 1;                   // [N]
    int* p_csrc = p_cur + N_NODES;                       // [E]

    const dim3 gg(HID / 128, (N_NODES + 127) / 128);     // (2, 391)
    const int THR = 256;

    // ===== TransConv branch =====
    sgemm128<<<gg, THR>>>(x, fc_W, fc_b, p_t, N_NODES, HID, F_IN);
    ln_relu_kernel<<<N_NODES, THR>>>(p_t, ln0_g, ln0_b, p_h);

    sgemm128<<<gg, THR>>>(p_h, Wq, bq, p_q, N_NODES, HID, HID);
    sgemm128<<<gg, THR>>>(p_h, Wk, bk, p_k, N_NODES, HID, HID);
    sgemm128<<<gg, THR>>>(p_h, Wv, bv, p_v, N_NODES, HID, HID);

    zero_kernel<<<(HID * HID + HID + 16 + THR - 1) / THR, THR>>>(p_kvs, HID * HID + HID + 16);
    sumsq_kernel<<<1024, THR>>>((const float4*)p_q, NH / 4, &p_scal[0]);
    colsum_sq_kernel<<<2048, THR>>>(p_k, p_kssum, &p_scal[1]);

    {
        const int SPLITS = 64;
        const int rows_per_z = (N_NODES + SPLITS - 1) / SPLITS;
        atb_kernel<<<dim3(HID / 64, HID / 64, SPLITS), THR>>>(p_k, p_v, p_kvs, N_NODES, rows_per_z);
    }
    scale_kvs_kernel<<<(HID * HID + THR - 1) / THR, THR>>>(p_kvs, p_kssum, p_scal);

    sgemm128<<<gg, THR>>>(p_q, p_kvs, nullptr, p_t, N_NODES, HID, HID);
    trans_epi_kernel<<<N_NODES, THR>>>(p_q, p_t, p_v, p_h, p_kssum, p_scal,
                                       ln1_g, ln1_b, out_xt);

    // ===== GCN branch: CSR build =====
    bn_coef_kernel<<<(NUM_GC * HID + THR - 1) / THR, THR>>>(
        gcn_b0, gcn_b, bn_g, bn_b, bn_mean, bn_var, p_cs, p_ct);
    zero_int_kernel<<<(N_NODES + THR - 1) / THR, THR>>>(p_cnt, N_NODES);
    count_kernel<<<(E_EDGES + THR - 1) / THR, THR>>>(dst, p_cnt);
    scan_kernel<<<1, 1024>>>(p_cnt, p_off, p_cur, p_dinv);
    fill_kernel<<<(E_EDGES + THR - 1) / THR, THR>>>(src, dst, p_dinv, p_cur, p_csrc, p_cw);

    // ===== GCN layers =====
    for (int i = 0; i < NUM_GC; i++) {
        const float* W = (i == 0) ? gcn_W0 : gcn_W + (size_t)(i - 1) * HID * HID;
        const float* Ain = (i == 0) ? x : p_y;
        int K = (i == 0) ? F_IN : HID;
        const float* bb = (i == 0) ? nullptr : nullptr;  // bias folded into affine

        sgemm128<<<gg, THR>>>(Ain, W, bb, p_t, N_NODES, HID, K);

        // layers 0..3: apply this layer's affine(+relu) producing next input;
        // layer 4: raw aggregate (final_kernel applies affine 4).
        const float* as = (i < NUM_GC - 1) ? p_cs + (size_t)i * HID : nullptr;
        const float* at = (i < NUM_GC - 1) ? p_ct + (size_t)i * HID : nullptr;
        csr_agg_kernel<<<N_NODES / 4, THR>>>(
            (const float4*)p_t, p_off, p_csrc, p_cw, p_dinv, as, at, (float4*)p_y);
    }

    // ===== outputs =====
    zero_kernel<<<(G_GRP * HID + THR - 1) / THR, THR>>>(out_pool, G_GRP * HID);
    final_kernel<<<N_NODES, THR>>>(p_y, p_cs + (size_t)(NUM_GC - 1) * HID,
                                   p_ct + (size_t)(NUM_GC - 1) * HID,
                                   batch, out_g, out_pool);
}

// round 8
// speedup vs baseline: 1.1326x; 1.1326x over previous
#include <cuda_runtime.h>
#include <cuda_bf16.h>
#include <math.h>

// ---------------- problem constants ----------------
#define N_NODES 50000
#define E_EDGES 300000
#define F_IN    128
#define HID     256
#define G_GRP   1000
#define NUM_GC  5
#define NH      (N_NODES * HID)          // 12,800,000

typedef unsigned long long ull;

// ---------------- scratch ----------------
// floats: h, q, v, t, gw, y (6*NH) then smalls:
//   S(64K) U(64K) P(64K) kvs0(64K) hs(256) scal(16)   <- zeroed region (262416)
//   kvsF(64K) kssum(256) kk(256) wvhs(256)
//   dinv(N) cs(5*256) ct(5*256) cw(E)
__device__ float d_scratch[6 * (size_t)NH + 700000];
// ints: cnt(N), off(N+1), cur(N), csrc(E)
__device__ int d_iscratch[3 * N_NODES + 1 + E_EDGES];

// ---------------- f32x2 helpers ----------------
__device__ __forceinline__ void ffma2(ull& d, ull a, ull b) {
    asm("fma.rn.f32x2 %0, %1, %2, %0;" : "+l"(d) : "l"(a), "l"(b));
}
__device__ __forceinline__ ull pack2(float x, float y) {
    ull r;
    asm("mov.b64 %0, {%1, %2};" : "=l"(r) : "f"(x), "f"(y));
    return r;
}
__device__ __forceinline__ void unpack2(float& lo, float& hi, ull v) {
    asm("mov.b64 {%0, %1}, %2;" : "=f"(lo), "=f"(hi) : "l"(v));
}

// ---------------- misc helpers ----------------
__device__ __forceinline__ float warp_sum(float v) {
#pragma unroll
    for (int o = 16; o; o >>= 1) v += __shfl_xor_sync(0xffffffffu, v, o);
    return v;
}
__device__ __forceinline__ float block_sum_256(float v, float* sh) {
    v = warp_sum(v);
    if ((threadIdx.x & 31) == 0) sh[threadIdx.x >> 5] = v;
    __syncthreads();
    if (threadIdx.x < 32) {
        float t = (threadIdx.x < 8) ? sh[threadIdx.x] : 0.f;
        t = warp_sum(t);
        if (threadIdx.x == 0) sh[8] = t;
    }
    __syncthreads();
    float r = sh[8];
    __syncthreads();
    return r;
}

__global__ void zero_kernel(float* __restrict__ p, int n) {
    int i = blockIdx.x * blockDim.x + threadIdx.x;
    if (i < n) p[i] = 0.f;
}
__global__ void zero_int_kernel(int* __restrict__ p, int n) {
    int i = blockIdx.x * blockDim.x + threadIdx.x;
    if (i < n) p[i] = 0;
}

// ============ 128x128x8 SGEMM body (R6-proven, f32x2 FFMA2) ============
// C[M,Nn] = A[M,K] @ B[K,Nn] (+bias). 256 threads, 8x8/thread, double buffered.
// Requires Nn % 128 == 0, K % 8 == 0.
__device__ __forceinline__ void sgemm_body(
    const float* __restrict__ A, const float* __restrict__ B,
    const float* __restrict__ bias, float* __restrict__ C,
    int M, int Nn, int K)
{
    __shared__ __align__(16) float As[2][8][128];
    __shared__ __align__(16) float Bs[2][8][128];

    const int tid = threadIdx.x;
    const int tx = tid & 15;
    const int ty = tid >> 4;
    const int row0 = blockIdx.y * 128;
    const int col0 = blockIdx.x * 128;

    const int arow = tid >> 1, ak4 = (tid & 1) * 4;
    const int brow = tid >> 5, bc4 = (tid & 31) * 4;

    const int KT = K >> 3;

    ull acc[8][4];
#pragma unroll
    for (int i = 0; i < 8; i++)
#pragma unroll
        for (int j = 0; j < 4; j++) acc[i][j] = 0ull;

    float4 av, bv;

    {
        int r = row0 + arow;
        if (r < M) av = *reinterpret_cast<const float4*>(&A[(size_t)r * K + ak4]);
        else       av = make_float4(0.f, 0.f, 0.f, 0.f);
        bv = *reinterpret_cast<const float4*>(&B[(size_t)brow * Nn + col0 + bc4]);
        As[0][ak4 + 0][arow] = av.x; As[0][ak4 + 1][arow] = av.y;
        As[0][ak4 + 2][arow] = av.z; As[0][ak4 + 3][arow] = av.w;
        *reinterpret_cast<float4*>(&Bs[0][brow][bc4]) = bv;
    }
    __syncthreads();

    for (int kt = 0; kt < KT; kt++) {
        const int buf = kt & 1;
        if (kt + 1 < KT) {
            const int k0 = (kt + 1) << 3;
            int r = row0 + arow;
            if (r < M) av = *reinterpret_cast<const float4*>(&A[(size_t)r * K + k0 + ak4]);
            else       av = make_float4(0.f, 0.f, 0.f, 0.f);
            bv = *reinterpret_cast<const float4*>(&B[(size_t)(k0 + brow) * Nn + col0 + bc4]);
        }

#pragma unroll
        for (int k = 0; k < 8; k++) {
            float4 a0 = *reinterpret_cast<const float4*>(&As[buf][k][ty * 4]);
            float4 a1 = *reinterpret_cast<const float4*>(&As[buf][k][64 + ty * 4]);
            ulonglong2 b0 = *reinterpret_cast<const ulonglong2*>(&Bs[buf][k][tx * 4]);
            ulonglong2 b1 = *reinterpret_cast<const ulonglong2*>(&Bs[buf][k][64 + tx * 4]);
            ull bp0 = b0.x, bp1 = b0.y, bp2 = b1.x, bp3 = b1.y;
            float aa[8] = {a0.x, a0.y, a0.z, a0.w, a1.x, a1.y, a1.z, a1.w};
#pragma unroll
            for (int i = 0; i < 8; i++) {
                ull ap = pack2(aa[i], aa[i]);
                ffma2(acc[i][0], ap, bp0);
                ffma2(acc[i][1], ap, bp1);
                ffma2(acc[i][2], ap, bp2);
                ffma2(acc[i][3], ap, bp3);
            }
        }

        if (kt + 1 < KT) {
            const int nb = buf ^ 1;
            As[nb][ak4 + 0][arow] = av.x; As[nb][ak4 + 1][arow] = av.y;
            As[nb][ak4 + 2][arow] = av.z; As[nb][ak4 + 3][arow] = av.w;
            *reinterpret_cast<float4*>(&Bs[nb][brow][bc4]) = bv;
        }
        __syncthreads();
    }

    float4 b_lo = make_float4(0.f, 0.f, 0.f, 0.f), b_hi = b_lo;
    if (bias) {
        b_lo = *reinterpret_cast<const float4*>(&bias[col0 + tx * 4]);
        b_hi = *reinterpret_cast<const float4*>(&bias[col0 + 64 + tx * 4]);
    }
#pragma unroll
    for (int i = 0; i < 8; i++) {
        int row = row0 + ((i < 4) ? (ty * 4 + i) : (64 + ty * 4 + (i - 4)));
        if (row >= M) continue;
        float o0, o1, o2, o3, o4, o5, o6, o7;
        unpack2(o0, o1, acc[i][0]); unpack2(o2, o3, acc[i][1]);
        unpack2(o4, o5, acc[i][2]); unpack2(o6, o7, acc[i][3]);
        float4 lo = make_float4(o0 + b_lo.x, o1 + b_lo.y, o2 + b_lo.z, o3 + b_lo.w);
        float4 hi = make_float4(o4 + b_hi.x, o5 + b_hi.y, o6 + b_hi.z, o7 + b_hi.w);
        *reinterpret_cast<float4*>(&C[(size_t)row * Nn + col0 + tx * 4]) = lo;
        *reinterpret_cast<float4*>(&C[(size_t)row * Nn + col0 + 64 + tx * 4]) = hi;
    }
}

__global__ void __launch_bounds__(256, 2) sgemm128(
    const float* __restrict__ A, const float* __restrict__ B,
    const float* __restrict__ bias, float* __restrict__ C,
    int M, int Nn, int K)
{
    sgemm_body(A, B, bias, C, M, Nn, K);
}

// batched variant: blockIdx.z picks (B, bias, C) pair; A shared.
__global__ void __launch_bounds__(256, 2) sgemm128_b2(
    const float* __restrict__ A,
    const float* __restrict__ B0, const float* __restrict__ B1,
    const float* __restrict__ bias0, const float* __restrict__ bias1,
    float* __restrict__ C0, float* __restrict__ C1,
    int M, int Nn, int K)
{
    if (blockIdx.z == 0) sgemm_body(A, B0, bias0, C0, M, Nn, K);
    else                 sgemm_body(A, B1, bias1, C1, M, Nn, K);
}

// ------ C[256,256] += A[L,256]^T @ B[L,256], split-K atomics, f32x2 --------
__global__ void __launch_bounds__(256) atb_kernel(
    const float* __restrict__ A, const float* __restrict__ B,
    float* __restrict__ C, int L, int rows_per_z)
{
    __shared__ __align__(16) float As[32][128];   // duplicated A-cols
    __shared__ __align__(16) float Bs[32][64];

    const int tid = threadIdx.x;
    const int tx = tid & 15;
    const int ty = tid >> 4;
    const int ar0 = blockIdx.y * 64;
    const int bc0 = blockIdx.x * 64;
    const int lstart = blockIdx.z * rows_per_z;
    const int lend = min(L, lstart + rows_per_z);

    ull acc[4][2];
#pragma unroll
    for (int i = 0; i < 4; i++) { acc[i][0] = 0ull; acc[i][1] = 0ull; }

    for (int l0 = lstart; l0 < lend; l0 += 32) {
#pragma unroll
        for (int p = 0; p < 2; p++) {
            int id = tid + p * 256;
            int lr = id >> 4;
            int c4 = (id & 15) * 4;
            int l = l0 + lr;
            float4 avv, bvv;
            if (l < lend) {
                avv = *reinterpret_cast<const float4*>(&A[(size_t)l * HID + ar0 + c4]);
                bvv = *reinterpret_cast<const float4*>(&B[(size_t)l * HID + bc0 + c4]);
            } else { avv = make_float4(0,0,0,0); bvv = avv; }
            float am[4] = {avv.x, avv.y, avv.z, avv.w};
#pragma unroll
            for (int m = 0; m < 4; m++)
                *reinterpret_cast<ull*>(&As[lr][2 * (c4 + m)]) = pack2(am[m], am[m]);
            *reinterpret_cast<float4*>(&Bs[lr][c4]) = bvv;
        }
        __syncthreads();

#pragma unroll
        for (int l = 0; l < 32; l++) {
            ulonglong2 a01 = *reinterpret_cast<const ulonglong2*>(&As[l][ty * 8]);
            ulonglong2 a23 = *reinterpret_cast<const ulonglong2*>(&As[l][ty * 8 + 4]);
            ulonglong2 bp  = *reinterpret_cast<const ulonglong2*>(&Bs[l][tx * 4]);
            ull ap[4] = {a01.x, a01.y, a23.x, a23.y};
#pragma unroll
            for (int i = 0; i < 4; i++) {
                ffma2(acc[i][0], ap[i], bp.x);
                ffma2(acc[i][1], ap[i], bp.y);
            }
        }
        __syncthreads();
    }

#pragma unroll
    for (int i = 0; i < 4; i++) {
        float c0, c1, c2, c3;
        unpack2(c0, c1, acc[i][0]); unpack2(c2, c3, acc[i][1]);
        float* base = &C[(size_t)(ar0 + ty * 4 + i) * HID + bc0 + tx * 4];
        atomicAdd(base + 0, c0); atomicAdd(base + 1, c1);
        atomicAdd(base + 2, c2); atomicAdd(base + 3, c3);
    }
}

// ---------------- LN + relu ----------------
__global__ void __launch_bounds__(256) ln_relu_kernel(
    const float* __restrict__ t, const float* __restrict__ g,
    const float* __restrict__ b, float* __restrict__ out)
{
    __shared__ float sh[16];
    int row = blockIdx.x, c = threadIdx.x;
    float v = t[(size_t)row * HID + c];
    float s  = block_sum_256(v, sh);
    float s2 = block_sum_256(v * v, sh);
    float mean = s * (1.f / HID);
    float var  = s2 * (1.f / HID) - mean * mean;
    float y = (v - mean) * rsqrtf(var + 1e-5f) * g[c] + b[c];
    out[(size_t)row * HID + c] = fmaxf(y, 0.f);
}

// ---------------- sum of squares ----------------
__global__ void __launch_bounds__(256) sumsq_kernel(
    const float4* __restrict__ p, int n4, float* __restrict__ out)
{
    __shared__ float sh[16];
    float s = 0.f;
    for (int i = blockIdx.x * blockDim.x + threadIdx.x; i < n4;
         i += gridDim.x * blockDim.x) {
        float4 v = p[i];
        s += v.x * v.x + v.y * v.y + v.z * v.z + v.w * v.w;
    }
    float tot = block_sum_256(s, sh);
    if (threadIdx.x == 0) atomicAdd(out, tot);
}

// ---------------- column sum (+ sumsq dump) ----------------
__global__ void __launch_bounds__(256) colsum_sq_kernel(
    const float* __restrict__ k, float* __restrict__ colsum, float* __restrict__ ss)
{
    __shared__ float sh[16];
    int c = threadIdx.x;
    float acc = 0.f, s2 = 0.f;
    for (int r = blockIdx.x; r < N_NODES; r += gridDim.x) {
        float v = k[(size_t)r * HID + c];
        acc += v;
        s2 += v * v;
    }
    atomicAdd(&colsum[c], acc);
    float tot = block_sum_256(s2, sh);
    if (c == 0) atomicAdd(ss, tot);
}

// ---------------- matvec: kk = Wk^T hs ; wvhs = Wv^T hs ----------------
__global__ void matvec_kernel(const float* __restrict__ Wk, const float* __restrict__ Wv,
                              const float* __restrict__ hs,
                              float* __restrict__ kk, float* __restrict__ wvhs)
{
    const float* W = blockIdx.x ? Wv : Wk;
    float* o = blockIdx.x ? wvhs : kk;
    int c = threadIdx.x;
    float a = 0.f;
    for (int l = 0; l < HID; l++) a = fmaf(W[(size_t)l * HID + c], hs[l], a);
    o[c] = a;
}

// ---------------- kss = tr(Wk^T S Wk) + 2 bk.kk + n ||bk||^2 ----------------
__global__ void __launch_bounds__(256) kss_kernel(
    const float* __restrict__ P, const float* __restrict__ Wk,
    const float* __restrict__ bk, const float* __restrict__ kk,
    float* __restrict__ scal)
{
    __shared__ float sh[16];
    float s = 0.f;
    for (int i = threadIdx.x; i < HID * HID; i += 256) s = fmaf(P[i], Wk[i], s);
    float bkc = bk[threadIdx.x];
    s += 2.f * bkc * kk[threadIdx.x] + (float)N_NODES * bkc * bkc;
    float tot = block_sum_256(s, sh);
    if (threadIdx.x == 0) scal[1] = tot;
}

// ---------------- kvs finalize (+ kssum) ----------------
__global__ void kvs_final_kernel(const float* __restrict__ kvs0,
                                 const float* __restrict__ kk, const float* __restrict__ wvhs,
                                 const float* __restrict__ bk, const float* __restrict__ bv,
                                 const float* __restrict__ scal,
                                 float* __restrict__ kvsF, float* __restrict__ kssum)
{
    int i = blockIdx.x, j = threadIdx.x;
    float sk = rsqrtf(scal[1]);
    float bki = bk[i];
    float val = kvs0[(size_t)i * HID + j] + kk[i] * bv[j] + bki * wvhs[j]
              + (float)N_NODES * bki * bv[j];
    kvsF[(size_t)i * HID + j] = val * sk;
    if (j == 0) kssum[i] = (kk[i] + (float)N_NODES * bki) * sk;
}

// ---------------- TransConv epilogue ----------------
__global__ void __launch_bounds__(256) trans_epi_kernel(
    const float* __restrict__ q, const float* __restrict__ t2,
    const float* __restrict__ v, const float* __restrict__ h,
    const float* __restrict__ kssum, const float* __restrict__ scal,
    const float* __restrict__ g1, const float* __restrict__ b1,
    float* __restrict__ out_xt)
{
    __shared__ float sh[16];
    int row = blockIdx.x, c = threadIdx.x;
    size_t o = (size_t)row * HID + c;
    float rq = rsqrtf(scal[0]);
    float qv = q[o];
    float dot = block_sum_256(qv * kssum[c], sh);
    float denom = rq * dot + (float)N_NODES;
    float attn = (rq * t2[o] + (float)N_NODES * v[o]) / denom;
    float h1 = 0.5f * attn + 0.5f * h[o];
    float s  = block_sum_256(h1, sh);
    float s2 = block_sum_256(h1 * h1, sh);
    float mean = s * (1.f / HID);
    float var  = s2 * (1.f / HID) - mean * mean;
    float y = (h1 - mean) * rsqrtf(var + 1e-5f) * g1[c] + b1[c];
    y = fmaxf(y, 0.f);
    float ss = block_sum_256(y * y, sh);
    out_xt[o] = y / fmaxf(sqrtf(ss), 1e-12f);
}

// ---------------- BN affine coefficients ----------------
__global__ void bn_coef_kernel(const float* __restrict__ gcn_b0, const float* __restrict__ gcn_b,
                               const float* __restrict__ bn_g, const float* __restrict__ bn_b,
                               const float* __restrict__ bn_mean, const float* __restrict__ bn_var,
                               float* __restrict__ coef_s, float* __restrict__ coef_t)
{
    int idx = blockIdx.x * blockDim.x + threadIdx.x;
    if (idx >= NUM_GC * HID) return;
    int layer = idx >> 8, c = idx & 255;
    float b = (layer == 0) ? gcn_b0[c] : gcn_b[(size_t)(layer - 1) * HID + c];
    float rs = rsqrtf(bn_var[idx] + 1e-5f);
    float sv = bn_g[idx] * rs;
    coef_s[idx] = sv;
    coef_t[idx] = (b - bn_mean[idx]) * sv + bn_b[idx];
}

// ---------------- CSR build ----------------
__global__ void count_kernel(const int* __restrict__ dst, int* __restrict__ cnt) {
    int e = blockIdx.x * blockDim.x + threadIdx.x;
    if (e < E_EDGES) atomicAdd(&cnt[dst[e]], 1);
}

__global__ void __launch_bounds__(1024) scan_kernel(
    const int* __restrict__ cnt, int* __restrict__ off, int* __restrict__ cur,
    float* __restrict__ dinv)
{
    __shared__ int part[1024];
    const int T = 1024;
    const int CHUNK = (N_NODES + T - 1) / T;
    int t = threadIdx.x;
    int lo = t * CHUNK, hi = min(N_NODES, lo + CHUNK);
    int s = 0;
    for (int i = lo; i < hi; i++) s += cnt[i];
    part[t] = s;
    __syncthreads();
    for (int d = 1; d < T; d <<= 1) {
        int v = (t >= d) ? part[t - d] : 0;
        __syncthreads();
        part[t] += v;
        __syncthreads();
    }
    int run = (t == 0) ? 0 : part[t - 1];
    for (int i = lo; i < hi; i++) {
        off[i] = run;
        cur[i] = run;
        int c = cnt[i];
        run += c;
        dinv[i] = rsqrtf((float)(c + 1));
    }
    if (t == T - 1) off[N_NODES] = run;
}

__global__ void fill_kernel(const int* __restrict__ src, const int* __restrict__ dst,
                            const float* __restrict__ dinv,
                            int* __restrict__ cur, int* __restrict__ csrc,
                            float* __restrict__ cw)
{
    int e = blockIdx.x * blockDim.x + threadIdx.x;
    if (e >= E_EDGES) return;
    int d = dst[e];
    int s = src[e];
    int pos = atomicAdd(&cur[d], 1);
    csrc[pos] = s;
    cw[pos] = dinv[s];
}

// ------- CSR aggregation + self loop + (affine+relu for next layer) --------
__global__ void __launch_bounds__(256) csr_agg_kernel(
    const float4* __restrict__ gw, const int* __restrict__ off,
    const int* __restrict__ csrc, const float* __restrict__ cw,
    const float* __restrict__ dinv,
    const float* __restrict__ aff_s, const float* __restrict__ aff_t,
    float4* __restrict__ outy)
{
    int row = blockIdx.x * 4 + (threadIdx.x >> 6);
    int c4 = threadIdx.x & 63;
    float di = dinv[row];
    float4 g = gw[(size_t)row * 64 + c4];
    float4 acc = make_float4(g.x * di, g.y * di, g.z * di, g.w * di);
    int e0 = off[row], e1 = off[row + 1];
    int j = e0;
    for (; j + 4 <= e1; j += 4) {
        int s0 = __ldg(&csrc[j]),     s1 = __ldg(&csrc[j + 1]);
        int s2 = __ldg(&csrc[j + 2]), s3 = __ldg(&csrc[j + 3]);
        float w0 = __ldg(&cw[j]),     w1 = __ldg(&cw[j + 1]);
        float w2 = __ldg(&cw[j + 2]), w3 = __ldg(&cw[j + 3]);
        float4 g0 = gw[(size_t)s0 * 64 + c4];
        float4 g1 = gw[(size_t)s1 * 64 + c4];
        float4 g2 = gw[(size_t)s2 * 64 + c4];
        float4 g3 = gw[(size_t)s3 * 64 + c4];
        acc.x = fmaf(w0, g0.x, fmaf(w1, g1.x, fmaf(w2, g2.x, fmaf(w3, g3.x, acc.x))));
        acc.y = fmaf(w0, g0.y, fmaf(w1, g1.y, fmaf(w2, g2.y, fmaf(w3, g3.y, acc.y))));
        acc.z = fmaf(w0, g0.z, fmaf(w1, g1.z, fmaf(w2, g2.z, fmaf(w3, g3.z, acc.z))));
        acc.w = fmaf(w0, g0.w, fmaf(w1, g1.w, fmaf(w2, g2.w, fmaf(w3, g3.w, acc.w))));
    }
    for (; j < e1; j++) {
        int s = __ldg(&csrc[j]);
        float w = __ldg(&cw[j]);
        float4 gv = gw[(size_t)s * 64 + c4];
        acc.x = fmaf(w, gv.x, acc.x);
        acc.y = fmaf(w, gv.y, acc.y);
        acc.z = fmaf(w, gv.z, acc.z);
        acc.w = fmaf(w, gv.w, acc.w);
    }
    acc.x *= di; acc.y *= di; acc.z *= di; acc.w *= di;
    if (aff_s) {
        float4 s4 = *reinterpret_cast<const float4*>(&aff_s[c4 * 4]);
        float4 t4 = *reinterpret_cast<const float4*>(&aff_t[c4 * 4]);
        acc.x = fmaxf(fmaf(acc.x, s4.x, t4.x), 0.f);
        acc.y = fmaxf(fmaf(acc.y, s4.y, t4.y), 0.f);
        acc.z = fmaxf(fmaf(acc.z, s4.z, t4.z), 0.f);
        acc.w = fmaxf(fmaf(acc.w, s4.w, t4.w), 0.f);
    }
    outy[(size_t)row * 64 + c4] = acc;
}

// ---------------- final: affine(layer4) -> l2 norm -> out_g + pool ---------
__global__ void __launch_bounds__(256) final_kernel(
    const float* __restrict__ agg, const float* __restrict__ s4, const float* __restrict__ t4,
    const int* __restrict__ batch,
    float* __restrict__ out_g, float* __restrict__ out_pool)
{
    __shared__ float sh[16];
    int row = blockIdx.x, c = threadIdx.x;
    float v = agg[(size_t)row * HID + c] * s4[c] + t4[c];
    float ss = block_sum_256(v * v, sh);
    float y = v / fmaxf(sqrtf(ss), 1e-12f);
    out_g[(size_t)row * HID + c] = y;
    atomicAdd(&out_pool[(size_t)batch[row] * HID + c], y);
}

// ---------------- launcher ----------------
extern "C" void kernel_launch(void* const* d_in, const int* in_sizes, int n_in,
                              void* d_out, int out_size)
{
    const float* x       = (const float*)d_in[0];
    const int*   edge    = (const int*)  d_in[1];
    const int*   batch   = (const int*)  d_in[2];
    // d_in[3] = beta (unused)
    const float* fc_W    = (const float*)d_in[4];
    const float* fc_b    = (const float*)d_in[5];
    const float* ln0_g   = (const float*)d_in[6];
    const float* ln0_b   = (const float*)d_in[7];
    const float* Wq      = (const float*)d_in[8];
    const float* bq      = (const float*)d_in[9];
    const float* Wk      = (const float*)d_in[10];
    const float* bk      = (const float*)d_in[11];
    const float* Wv      = (const float*)d_in[12];
    const float* bv      = (const float*)d_in[13];
    const float* ln1_g   = (const float*)d_in[14];
    const float* ln1_b   = (const float*)d_in[15];
    const float* gcn_W0  = (const float*)d_in[16];
    const float* gcn_b0  = (const float*)d_in[17];
    const float* gcn_W   = (const float*)d_in[18];
    const float* gcn_b   = (const float*)d_in[19];
    const float* bn_g    = (const float*)d_in[20];
    const float* bn_b    = (const float*)d_in[21];
    const float* bn_mean = (const float*)d_in[22];
    const float* bn_var  = (const float*)d_in[23];

    const int* src = edge;
    const int* dst = edge + E_EDGES;

    float* out      = (float*)d_out;
    float* out_pool = out;                               // [G, HID]
    float* out_g    = out + (size_t)G_GRP * HID;         // [N, HID]
    float* out_xt   = out_g + (size_t)N_NODES * HID;     // [N, HID]

    float* fbase = nullptr;
    int* ibase = nullptr;
    cudaGetSymbolAddress((void**)&fbase, d_scratch);
    cudaGetSymbolAddress((void**)&ibase, d_iscratch);

    float* p_h   = fbase;
    float* p_q   = fbase + (size_t)1 * NH;
    float* p_v   = fbase + (size_t)2 * NH;
    float* p_t   = fbase + (size_t)3 * NH;   // fc out, then Q@kvs out
    float* p_gw  = fbase + (size_t)4 * NH;   // GCN gemm outputs
    float* p_y   = fbase + (size_t)5 * NH;   // agg outputs

    float* p_sm   = fbase + (size_t)6 * NH;  // zeroed small region start
    float* p_S    = p_sm;                    // 65536
    float* p_U    = p_S + HID * HID;         // 65536
    float* p_P    = p_U + HID * HID;         // 65536
    float* p_kvs0 = p_P + HID * HID;         // 65536
    float* p_hs   = p_kvs0 + HID * HID;      // 256
    float* p_scal = p_hs + HID;              // 16
    const int ZSM = 4 * HID * HID + HID + 16;

    float* p_kvsF  = p_scal + 16;            // 65536 (fresh write)
    float* p_kssum = p_kvsF + HID * HID;     // 256
    float* p_kk    = p_kssum + HID;          // 256
    float* p_wvhs  = p_kk + HID;             // 256
    float* p_dinv  = p_wvhs + HID;           // N
    float* p_cs    = p_dinv + N_NODES;       // 5*256
    float* p_ct    = p_cs + NUM_GC * HID;    // 5*256
    float* p_cw    = p_ct + NUM_GC * HID;    // E

    int* p_cnt  = ibase;
    int* p_off  = p_cnt + N_NODES;
    int* p_cur  = p_off + N_NODES + 1;
    int* p_csrc = p_cur + N_NODES;

    const dim3 gg(HID / 128, (N_NODES + 127) / 128);     // (2, 391)
    const dim3 gg2(HID / 128, (N_NODES + 127) / 128, 2);
    const int THR = 256;

    // ===== CSR build + coefficients (independent prefix) =====
    bn_coef_kernel<<<(NUM_GC * HID + THR - 1) / THR, THR>>>(
        gcn_b0, gcn_b, bn_g, bn_b, bn_mean, bn_var, p_cs, p_ct);
    zero_int_kernel<<<(N_NODES + THR - 1) / THR, THR>>>(p_cnt, N_NODES);
    count_kernel<<<(E_EDGES + THR - 1) / THR, THR>>>(dst, p_cnt);
    scan_kernel<<<1, 1024>>>(p_cnt, p_off, p_cur, p_dinv);
    fill_kernel<<<(E_EDGES + THR - 1) / THR, THR>>>(src, dst, p_dinv, p_cur, p_csrc, p_cw);

    // ===== shared K=128 GEMMs: fc and gcn layer-0 (both A = x) =====
    sgemm128_b2<<<gg2, THR>>>(x, fc_W, gcn_W0, fc_b, nullptr,
                              p_t, p_gw, N_NODES, HID, F_IN);
    ln_relu_kernel<<<N_NODES, THR>>>(p_t, ln0_g, ln0_b, p_h);

    // ===== Q and V GEMMs (shared A = h) =====
    sgemm128_b2<<<gg2, THR>>>(p_h, Wq, Wv, bq, bv,
                              p_q, p_v, N_NODES, HID, HID);

    // ===== small-matrix attention algebra =====
    zero_kernel<<<(ZSM + THR - 1) / THR, THR>>>(p_sm, ZSM);
    sumsq_kernel<<<1024, THR>>>((const float4*)p_q, NH / 4, &p_scal[0]);
    colsum_sq_kernel<<<2048, THR>>>(p_h, p_hs, &p_scal[3]);   // hs; ss unused

    {   // S = H^T H
        const int SPLITS = 64;
        const int rows_per_z = (N_NODES + SPLITS - 1) / SPLITS;
        atb_kernel<<<dim3(HID / 64, HID / 64, SPLITS), THR>>>(p_h, p_h, p_S, N_NODES, rows_per_z);
    }
    // U = S^T Wv = S Wv (S symmetric); P = S Wk; kvs0 = Wk^T U
    atb_kernel<<<dim3(HID / 64, HID / 64, 1), THR>>>(p_S, Wv, p_U, HID, HID);
    atb_kernel<<<dim3(HID / 64, HID / 64, 1), THR>>>(p_S, Wk, p_P, HID, HID);
    atb_kernel<<<dim3(HID / 64, HID / 64, 1), THR>>>(Wk, p_U, p_kvs0, HID, HID);
    matvec_kernel<<<2, THR>>>(Wk, Wv, p_hs, p_kk, p_wvhs);
    kss_kernel<<<1, THR>>>(p_P, Wk, bk, p_kk, p_scal);
    kvs_final_kernel<<<HID, THR>>>(p_kvs0, p_kk, p_wvhs, bk, bv, p_scal, p_kvsF, p_kssum);

    // t2 = Q @ kvsF ; epilogue
    sgemm128<<<gg, THR>>>(p_q, p_kvsF, nullptr, p_t, N_NODES, HID, HID);
    trans_epi_kernel<<<N_NODES, THR>>>(p_q, p_t, p_v, p_h, p_kssum, p_scal,
                                       ln1_g, ln1_b, out_xt);

    // ===== GCN layers =====
    // layer 0 aggregation (gemm already done in merged launch)
    csr_agg_kernel<<<N_NODES / 4, THR>>>(
        (const float4*)p_gw, p_off, p_csrc, p_cw, p_dinv,
        p_cs, p_ct, (float4*)p_y);

    for (int i = 1; i < NUM_GC; i++) {
        const float* W = gcn_W + (size_t)(i - 1) * HID * HID;
        sgemm128<<<gg, THR>>>(p_y, W, nullptr, p_gw, N_NODES, HID, HID);
        const float* as = (i < NUM_GC - 1) ? p_cs + (size_t)i * HID : nullptr;
        const float* at = (i < NUM_GC - 1) ? p_ct + (size_t)i * HID : nullptr;
        csr_agg_kernel<<<N_NODES / 4, THR>>>(
            (const float4*)p_gw, p_off, p_csrc, p_cw, p_dinv, as, at, (float4*)p_y);
    }

    // ===== outputs =====
    zero_kernel<<<(G_GRP * HID + THR - 1) / THR, THR>>>(out_pool, G_GRP * HID);
    final_kernel<<<N_NODES, THR>>>(p_y, p_cs + (size_t)(NUM_GC - 1) * HID,
                                   p_ct + (size_t)(NUM_GC - 1) * HID,
                                   batch, out_g, out_pool);
}

// round 9
// speedup vs baseline: 1.3209x; 1.1663x over previous
#include <cuda_runtime.h>
#include <cuda_bf16.h>
#include <math.h>

// ---------------- problem constants ----------------
#define N_NODES 50000
#define E_EDGES 300000
#define F_IN    128
#define HID     256
#define G_GRP   1000
#define NUM_GC  5
#define NH      (N_NODES * HID)          // 12,800,000
#define NROWBLK ((N_NODES + 7) / 8)      // warp-per-row grids
#define SCANBLK ((N_NODES + 255) / 256)  // 196

typedef unsigned long long ull;

// ---------------- scratch ----------------
__device__ float d_scratch[6 * (size_t)NH + 700000];
// ints: cnt(N), off(N+1), cur(N), csrc(E), partial(256), pbase(256)
__device__ int d_iscratch[3 * N_NODES + 1 + E_EDGES + 512];

// ---------------- f32x2 helpers ----------------
__device__ __forceinline__ void ffma2(ull& d, ull a, ull b) {
    asm("fma.rn.f32x2 %0, %1, %2, %0;" : "+l"(d) : "l"(a), "l"(b));
}
__device__ __forceinline__ ull pack2(float x, float y) {
    ull r;
    asm("mov.b64 %0, {%1, %2};" : "=l"(r) : "f"(x), "f"(y));
    return r;
}
__device__ __forceinline__ void unpack2(float& lo, float& hi, ull v) {
    asm("mov.b64 {%0, %1}, %2;" : "=f"(lo), "=f"(hi) : "l"(v));
}

// ---------------- misc helpers ----------------
__device__ __forceinline__ float warp_sum(float v) {
#pragma unroll
    for (int o = 16; o; o >>= 1) v += __shfl_xor_sync(0xffffffffu, v, o);
    return v;
}
__device__ __forceinline__ float block_sum_256(float v, float* sh) {
    v = warp_sum(v);
    if ((threadIdx.x & 31) == 0) sh[threadIdx.x >> 5] = v;
    __syncthreads();
    if (threadIdx.x < 32) {
        float t = (threadIdx.x < 8) ? sh[threadIdx.x] : 0.f;
        t = warp_sum(t);
        if (threadIdx.x == 0) sh[8] = t;
    }
    __syncthreads();
    float r = sh[8];
    __syncthreads();
    return r;
}
__device__ __forceinline__ float sum8(float4 a, float4 b) {
    return a.x + a.y + a.z + a.w + b.x + b.y + b.z + b.w;
}
__device__ __forceinline__ float sumsq8(float4 a, float4 b) {
    return a.x*a.x + a.y*a.y + a.z*a.z + a.w*a.w
         + b.x*b.x + b.y*b.y + b.z*b.z + b.w*b.w;
}

__global__ void zero_kernel(float* __restrict__ p, int n) {
    int i = blockIdx.x * blockDim.x + threadIdx.x;
    if (i < n) p[i] = 0.f;
}
__global__ void zero_int_kernel(int* __restrict__ p, int n) {
    int i = blockIdx.x * blockDim.x + threadIdx.x;
    if (i < n) p[i] = 0;
}

// ============ 128x128x8 SGEMM body (R6-proven, f32x2 FFMA2) ============
// Optional ssq: accumulate sum of squares of outputs (after bias) there.
__device__ __forceinline__ void sgemm_body(
    const float* __restrict__ A, const float* __restrict__ B,
    const float* __restrict__ bias, float* __restrict__ C,
    int M, int Nn, int K, float* __restrict__ ssq)
{
    __shared__ __align__(16) float As[2][8][128];
    __shared__ __align__(16) float Bs[2][8][128];
    __shared__ float red[16];

    const int tid = threadIdx.x;
    const int tx = tid & 15;
    const int ty = tid >> 4;
    const int row0 = blockIdx.y * 128;
    const int col0 = blockIdx.x * 128;

    const int arow = tid >> 1, ak4 = (tid & 1) * 4;
    const int brow = tid >> 5, bc4 = (tid & 31) * 4;

    const int KT = K >> 3;

    ull acc[8][4];
#pragma unroll
    for (int i = 0; i < 8; i++)
#pragma unroll
        for (int j = 0; j < 4; j++) acc[i][j] = 0ull;

    float4 av, bv;

    {
        int r = row0 + arow;
        if (r < M) av = *reinterpret_cast<const float4*>(&A[(size_t)r * K + ak4]);
        else       av = make_float4(0.f, 0.f, 0.f, 0.f);
        bv = *reinterpret_cast<const float4*>(&B[(size_t)brow * Nn + col0 + bc4]);
        As[0][ak4 + 0][arow] = av.x; As[0][ak4 + 1][arow] = av.y;
        As[0][ak4 + 2][arow] = av.z; As[0][ak4 + 3][arow] = av.w;
        *reinterpret_cast<float4*>(&Bs[0][brow][bc4]) = bv;
    }
    __syncthreads();

    for (int kt = 0; kt < KT; kt++) {
        const int buf = kt & 1;
        if (kt + 1 < KT) {
            const int k0 = (kt + 1) << 3;
            int r = row0 + arow;
            if (r < M) av = *reinterpret_cast<const float4*>(&A[(size_t)r * K + k0 + ak4]);
            else       av = make_float4(0.f, 0.f, 0.f, 0.f);
            bv = *reinterpret_cast<const float4*>(&B[(size_t)(k0 + brow) * Nn + col0 + bc4]);
        }

#pragma unroll
        for (int k = 0; k < 8; k++) {
            float4 a0 = *reinterpret_cast<const float4*>(&As[buf][k][ty * 4]);
            float4 a1 = *reinterpret_cast<const float4*>(&As[buf][k][64 + ty * 4]);
            ulonglong2 b0 = *reinterpret_cast<const ulonglong2*>(&Bs[buf][k][tx * 4]);
            ulonglong2 b1 = *reinterpret_cast<const ulonglong2*>(&Bs[buf][k][64 + tx * 4]);
            ull bp0 = b0.x, bp1 = b0.y, bp2 = b1.x, bp3 = b1.y;
            float aa[8] = {a0.x, a0.y, a0.z, a0.w, a1.x, a1.y, a1.z, a1.w};
#pragma unroll
            for (int i = 0; i < 8; i++) {
                ull ap = pack2(aa[i], aa[i]);
                ffma2(acc[i][0], ap, bp0);
                ffma2(acc[i][1], ap, bp1);
                ffma2(acc[i][2], ap, bp2);
                ffma2(acc[i][3], ap, bp3);
            }
        }

        if (kt + 1 < KT) {
            const int nb = buf ^ 1;
            As[nb][ak4 + 0][arow] = av.x; As[nb][ak4 + 1][arow] = av.y;
            As[nb][ak4 + 2][arow] = av.z; As[nb][ak4 + 3][arow] = av.w;
            *reinterpret_cast<float4*>(&Bs[nb][brow][bc4]) = bv;
        }
        __syncthreads();
    }

    float4 b_lo = make_float4(0.f, 0.f, 0.f, 0.f), b_hi = b_lo;
    if (bias) {
        b_lo = *reinterpret_cast<const float4*>(&bias[col0 + tx * 4]);
        b_hi = *reinterpret_cast<const float4*>(&bias[col0 + 64 + tx * 4]);
    }
    float myss = 0.f;
#pragma unroll
    for (int i = 0; i < 8; i++) {
        int row = row0 + ((i < 4) ? (ty * 4 + i) : (64 + ty * 4 + (i - 4)));
        if (row >= M) continue;
        float o0, o1, o2, o3, o4, o5, o6, o7;
        unpack2(o0, o1, acc[i][0]); unpack2(o2, o3, acc[i][1]);
        unpack2(o4, o5, acc[i][2]); unpack2(o6, o7, acc[i][3]);
        float4 lo = make_float4(o0 + b_lo.x, o1 + b_lo.y, o2 + b_lo.z, o3 + b_lo.w);
        float4 hi = make_float4(o4 + b_hi.x, o5 + b_hi.y, o6 + b_hi.z, o7 + b_hi.w);
        *reinterpret_cast<float4*>(&C[(size_t)row * Nn + col0 + tx * 4]) = lo;
        *reinterpret_cast<float4*>(&C[(size_t)row * Nn + col0 + 64 + tx * 4]) = hi;
        if (ssq) myss += sumsq8(lo, hi);
    }
    if (ssq) {
        float tot = block_sum_256(myss, red);
        if (tid == 0) atomicAdd(ssq, tot);
    }
}

__global__ void __launch_bounds__(256, 2) sgemm128(
    const float* __restrict__ A, const float* __restrict__ B,
    const float* __restrict__ bias, float* __restrict__ C,
    int M, int Nn, int K)
{
    sgemm_body(A, B, bias, C, M, Nn, K, nullptr);
}

__global__ void __launch_bounds__(256, 2) sgemm128_b2(
    const float* __restrict__ A,
    const float* __restrict__ B0, const float* __restrict__ B1,
    const float* __restrict__ bias0, const float* __restrict__ bias1,
    float* __restrict__ C0, float* __restrict__ C1,
    int M, int Nn, int K, float* __restrict__ ssq0)
{
    if (blockIdx.z == 0) sgemm_body(A, B0, bias0, C0, M, Nn, K, ssq0);
    else                 sgemm_body(A, B1, bias1, C1, M, Nn, K, nullptr);
}

// ------ C[256,256] += A[L,256]^T @ B[L,256], split-K atomics, f32x2 --------
__global__ void __launch_bounds__(256) atb_kernel(
    const float* __restrict__ A, const float* __restrict__ B,
    float* __restrict__ C, int L, int rows_per_z)
{
    __shared__ __align__(16) float As[32][128];
    __shared__ __align__(16) float Bs[32][64];

    const int tid = threadIdx.x;
    const int tx = tid & 15;
    const int ty = tid >> 4;
    const int ar0 = blockIdx.y * 64;
    const int bc0 = blockIdx.x * 64;
    const int lstart = blockIdx.z * rows_per_z;
    const int lend = min(L, lstart + rows_per_z);

    ull acc[4][2];
#pragma unroll
    for (int i = 0; i < 4; i++) { acc[i][0] = 0ull; acc[i][1] = 0ull; }

    for (int l0 = lstart; l0 < lend; l0 += 32) {
#pragma unroll
        for (int p = 0; p < 2; p++) {
            int id = tid + p * 256;
            int lr = id >> 4;
            int c4 = (id & 15) * 4;
            int l = l0 + lr;
            float4 avv, bvv;
            if (l < lend) {
                avv = *reinterpret_cast<const float4*>(&A[(size_t)l * HID + ar0 + c4]);
                bvv = *reinterpret_cast<const float4*>(&B[(size_t)l * HID + bc0 + c4]);
            } else { avv = make_float4(0,0,0,0); bvv = avv; }
            float am[4] = {avv.x, avv.y, avv.z, avv.w};
#pragma unroll
            for (int m = 0; m < 4; m++)
                *reinterpret_cast<ull*>(&As[lr][2 * (c4 + m)]) = pack2(am[m], am[m]);
            *reinterpret_cast<float4*>(&Bs[lr][c4]) = bvv;
        }
        __syncthreads();

#pragma unroll
        for (int l = 0; l < 32; l++) {
            ulonglong2 a01 = *reinterpret_cast<const ulonglong2*>(&As[l][ty * 8]);
            ulonglong2 a23 = *reinterpret_cast<const ulonglong2*>(&As[l][ty * 8 + 4]);
            ulonglong2 bp  = *reinterpret_cast<const ulonglong2*>(&Bs[l][tx * 4]);
            ull ap[4] = {a01.x, a01.y, a23.x, a23.y};
#pragma unroll
            for (int i = 0; i < 4; i++) {
                ffma2(acc[i][0], ap[i], bp.x);
                ffma2(acc[i][1], ap[i], bp.y);
            }
        }
        __syncthreads();
    }

#pragma unroll
    for (int i = 0; i < 4; i++) {
        float c0, c1, c2, c3;
        unpack2(c0, c1, acc[i][0]); unpack2(c2, c3, acc[i][1]);
        float* base = &C[(size_t)(ar0 + ty * 4 + i) * HID + bc0 + tx * 4];
        atomicAdd(base + 0, c0); atomicAdd(base + 1, c1);
        atomicAdd(base + 2, c2); atomicAdd(base + 3, c3);
    }
}

// ---------------- warp-per-row LN + relu ----------------
__global__ void __launch_bounds__(256) ln_relu_w(
    const float4* __restrict__ t, const float4* __restrict__ g,
    const float4* __restrict__ b, float4* __restrict__ out)
{
    int row = blockIdx.x * 8 + (threadIdx.x >> 5);
    if (row >= N_NODES) return;
    int lane = threadIdx.x & 31;
    const float4* tr = t + (size_t)row * 64;
    float4 v0 = tr[lane], v1 = tr[lane + 32];
    float s  = warp_sum(sum8(v0, v1));
    float s2 = warp_sum(sumsq8(v0, v1));
    float mean = s * (1.f / HID);
    float var  = s2 * (1.f / HID) - mean * mean;
    float r = rsqrtf(var + 1e-5f);
    float4 g0 = g[lane], g1 = g[lane + 32], b0 = b[lane], b1 = b[lane + 32];
    float4 o0, o1;
    o0.x = fmaxf((v0.x - mean) * r * g0.x + b0.x, 0.f);
    o0.y = fmaxf((v0.y - mean) * r * g0.y + b0.y, 0.f);
    o0.z = fmaxf((v0.z - mean) * r * g0.z + b0.z, 0.f);
    o0.w = fmaxf((v0.w - mean) * r * g0.w + b0.w, 0.f);
    o1.x = fmaxf((v1.x - mean) * r * g1.x + b1.x, 0.f);
    o1.y = fmaxf((v1.y - mean) * r * g1.y + b1.y, 0.f);
    o1.z = fmaxf((v1.z - mean) * r * g1.z + b1.z, 0.f);
    o1.w = fmaxf((v1.w - mean) * r * g1.w + b1.w, 0.f);
    float4* orow = out + (size_t)row * 64;
    orow[lane] = o0; orow[lane + 32] = o1;
}

// ---------------- column sum of h ----------------
__global__ void __launch_bounds__(256) colsum_kernel(
    const float* __restrict__ k, float* __restrict__ colsum)
{
    int c = threadIdx.x;
    float acc = 0.f;
    for (int r = blockIdx.x; r < N_NODES; r += gridDim.x)
        acc += k[(size_t)r * HID + c];
    atomicAdd(&colsum[c], acc);
}

// ---------------- matvec: kk = Wk^T hs ; wvhs = Wv^T hs ----------------
__global__ void matvec_kernel(const float* __restrict__ Wk, const float* __restrict__ Wv,
                              const float* __restrict__ hs,
                              float* __restrict__ kk, float* __restrict__ wvhs)
{
    const float* W = blockIdx.x ? Wv : Wk;
    float* o = blockIdx.x ? wvhs : kk;
    int c = threadIdx.x;
    float a = 0.f;
    for (int l = 0; l < HID; l++) a = fmaf(W[(size_t)l * HID + c], hs[l], a);
    o[c] = a;
}

// ---------------- kss = tr(Wk^T S Wk) + 2 bk.kk + n ||bk||^2 ----------------
__global__ void __launch_bounds__(256) kss_kernel(
    const float* __restrict__ P, const float* __restrict__ Wk,
    const float* __restrict__ bk, const float* __restrict__ kk,
    float* __restrict__ scal)
{
    __shared__ float sh[16];
    float s = 0.f;
    for (int i = threadIdx.x; i < HID * HID; i += 256) s = fmaf(P[i], Wk[i], s);
    float bkc = bk[threadIdx.x];
    s += 2.f * bkc * kk[threadIdx.x] + (float)N_NODES * bkc * bkc;
    float tot = block_sum_256(s, sh);
    if (threadIdx.x == 0) scal[1] = tot;
}

// ---------------- kvs finalize (+ kssum) ----------------
__global__ void kvs_final_kernel(const float* __restrict__ kvs0,
                                 const float* __restrict__ kk, const float* __restrict__ wvhs,
                                 const float* __restrict__ bk, const float* __restrict__ bv,
                                 const float* __restrict__ scal,
                                 float* __restrict__ kvsF, float* __restrict__ kssum)
{
    int i = blockIdx.x, j = threadIdx.x;
    float sk = rsqrtf(scal[1]);
    float bki = bk[i];
    float val = kvs0[(size_t)i * HID + j] + kk[i] * bv[j] + bki * wvhs[j]
              + (float)N_NODES * bki * bv[j];
    kvsF[(size_t)i * HID + j] = val * sk;
    if (j == 0) kssum[i] = (kk[i] + (float)N_NODES * bki) * sk;
}

// ---------------- warp-per-row TransConv epilogue ----------------
__global__ void __launch_bounds__(256) trans_epi_w(
    const float4* __restrict__ q, const float4* __restrict__ t2,
    const float4* __restrict__ v, const float4* __restrict__ h,
    const float4* __restrict__ kssum, const float* __restrict__ scal,
    const float4* __restrict__ g1, const float4* __restrict__ b1,
    float4* __restrict__ out_xt)
{
    int row = blockIdx.x * 8 + (threadIdx.x >> 5);
    if (row >= N_NODES) return;
    int lane = threadIdx.x & 31;
    size_t ro = (size_t)row * 64;
    float4 q0 = q[ro + lane], q1 = q[ro + lane + 32];
    float4 ks0 = kssum[lane], ks1 = kssum[lane + 32];
    float rq = rsqrtf(scal[0]);
    float dotl = q0.x*ks0.x + q0.y*ks0.y + q0.z*ks0.z + q0.w*ks0.w
               + q1.x*ks1.x + q1.y*ks1.y + q1.z*ks1.z + q1.w*ks1.w;
    float denom = rq * warp_sum(dotl) + (float)N_NODES;
    float inv_d = 1.f / denom;
    float4 t20 = t2[ro + lane], t21 = t2[ro + lane + 32];
    float4 v0 = v[ro + lane], v1 = v[ro + lane + 32];
    float4 h0 = h[ro + lane], h1v = h[ro + lane + 32];
    float4 a0, a1;
    a0.x = 0.5f * (rq * t20.x + (float)N_NODES * v0.x) * inv_d + 0.5f * h0.x;
    a0.y = 0.5f * (rq * t20.y + (float)N_NODES * v0.y) * inv_d + 0.5f * h0.y;
    a0.z = 0.5f * (rq * t20.z + (float)N_NODES * v0.z) * inv_d + 0.5f * h0.z;
    a0.w = 0.5f * (rq * t20.w + (float)N_NODES * v0.w) * inv_d + 0.5f * h0.w;
    a1.x = 0.5f * (rq * t21.x + (float)N_NODES * v1.x) * inv_d + 0.5f * h1v.x;
    a1.y = 0.5f * (rq * t21.y + (float)N_NODES * v1.y) * inv_d + 0.5f * h1v.y;
    a1.z = 0.5f * (rq * t21.z + (float)N_NODES * v1.z) * inv_d + 0.5f * h1v.z;
    a1.w = 0.5f * (rq * t21.w + (float)N_NODES * v1.w) * inv_d + 0.5f * h1v.w;
    float s  = warp_sum(sum8(a0, a1));
    float s2 = warp_sum(sumsq8(a0, a1));
    float mean = s * (1.f / HID);
    float var  = s2 * (1.f / HID) - mean * mean;
    float r = rsqrtf(var + 1e-5f);
    float4 gg0 = g1[lane], gg1 = g1[lane + 32], bb0 = b1[lane], bb1 = b1[lane + 32];
    float4 y0, y1;
    y0.x = fmaxf((a0.x - mean) * r * gg0.x + bb0.x, 0.f);
    y0.y = fmaxf((a0.y - mean) * r * gg0.y + bb0.y, 0.f);
    y0.z = fmaxf((a0.z - mean) * r * gg0.z + bb0.z, 0.f);
    y0.w = fmaxf((a0.w - mean) * r * gg0.w + bb0.w, 0.f);
    y1.x = fmaxf((a1.x - mean) * r * gg1.x + bb1.x, 0.f);
    y1.y = fmaxf((a1.y - mean) * r * gg1.y + bb1.y, 0.f);
    y1.z = fmaxf((a1.z - mean) * r * gg1.z + bb1.z, 0.f);
    y1.w = fmaxf((a1.w - mean) * r * gg1.w + bb1.w, 0.f);
    float ssn = warp_sum(sumsq8(y0, y1));
    float inv_n = 1.f / fmaxf(sqrtf(ssn), 1e-12f);
    y0.x *= inv_n; y0.y *= inv_n; y0.z *= inv_n; y0.w *= inv_n;
    y1.x *= inv_n; y1.y *= inv_n; y1.z *= inv_n; y1.w *= inv_n;
    out_xt[ro + lane] = y0; out_xt[ro + lane + 32] = y1;
}

// ---------------- BN affine coefficients ----------------
__global__ void bn_coef_kernel(const float* __restrict__ gcn_b0, const float* __restrict__ gcn_b,
                               const float* __restrict__ bn_g, const float* __restrict__ bn_b,
                               const float* __restrict__ bn_mean, const float* __restrict__ bn_var,
                               float* __restrict__ coef_s, float* __restrict__ coef_t)
{
    int idx = blockIdx.x * blockDim.x + threadIdx.x;
    if (idx >= NUM_GC * HID) return;
    int layer = idx >> 8, c = idx & 255;
    float b = (layer == 0) ? gcn_b0[c] : gcn_b[(size_t)(layer - 1) * HID + c];
    float rs = rsqrtf(bn_var[idx] + 1e-5f);
    float sv = bn_g[idx] * rs;
    coef_s[idx] = sv;
    coef_t[idx] = (b - bn_mean[idx]) * sv + bn_b[idx];
}

// ---------------- CSR build (parallel scan) ----------------
__global__ void count_kernel(const int* __restrict__ dst, int* __restrict__ cnt) {
    int e = blockIdx.x * blockDim.x + threadIdx.x;
    if (e < E_EDGES) atomicAdd(&cnt[dst[e]], 1);
}

// phase 1: per-block sums of cnt (grid = SCANBLK, block 256)
__global__ void __launch_bounds__(256) scan_partial_kernel(
    const int* __restrict__ cnt, int* __restrict__ partial)
{
    __shared__ int sh[8];
    int i = blockIdx.x * 256 + threadIdx.x;
    int v = (i < N_NODES) ? cnt[i] : 0;
#pragma unroll
    for (int o = 16; o; o >>= 1) v += __shfl_xor_sync(0xffffffffu, v, o);
    if ((threadIdx.x & 31) == 0) sh[threadIdx.x >> 5] = v;
    __syncthreads();
    if (threadIdx.x < 8) {
        int t = sh[threadIdx.x];
#pragma unroll
        for (int o = 4; o; o >>= 1) t += __shfl_xor_sync(0xffu, t, o);
        if (threadIdx.x == 0) partial[blockIdx.x] = t;
    }
}

// phase 2: exclusive scan of SCANBLK partials (1 block, 256 threads)
__global__ void __launch_bounds__(256) scan_base_kernel(
    const int* __restrict__ partial, int* __restrict__ pbase)
{
    __shared__ int sh[256];
    int t = threadIdx.x;
    int v = (t < SCANBLK) ? partial[t] : 0;
    sh[t] = v;
    __syncthreads();
#pragma unroll
    for (int d = 1; d < 256; d <<= 1) {
        int u = (t >= d) ? sh[t - d] : 0;
        __syncthreads();
        sh[t] += u;
        __syncthreads();
    }
    pbase[t] = sh[t] - v;   // exclusive
}

// phase 3: per-block exclusive scan + fill off/cur/dinv
__global__ void __launch_bounds__(256) scan_fill_kernel(
    const int* __restrict__ cnt, const int* __restrict__ pbase,
    int* __restrict__ off, int* __restrict__ cur, float* __restrict__ dinv)
{
    __shared__ int wsum[8];
    int i = blockIdx.x * 256 + threadIdx.x;
    int lane = threadIdx.x & 31, wid = threadIdx.x >> 5;
    int c = (i < N_NODES) ? cnt[i] : 0;
    int v = c;
#pragma unroll
    for (int o = 1; o < 32; o <<= 1) {
        int u = __shfl_up_sync(0xffffffffu, v, o);
        if (lane >= o) v += u;
    }
    if (lane == 31) wsum[wid] = v;
    __syncthreads();
    int wpre = 0;
    if (threadIdx.x < 8) {
        int w = wsum[threadIdx.x];
#pragma unroll
        for (int o = 1; o < 8; o <<= 1) {
            int u = __shfl_up_sync(0xffu, w, o);
            if (threadIdx.x >= o) w += u;
        }
        wsum[threadIdx.x] = w;   // inclusive warp prefix
    }
    __syncthreads();
    wpre = (wid == 0) ? 0 : wsum[wid - 1];
    int excl = v - c + wpre + pbase[blockIdx.x];
    if (i < N_NODES) {
        off[i] = excl;
        cur[i] = excl;
        dinv[i] = rsqrtf((float)(c + 1));
    }
    if (i == N_NODES - 1) off[N_NODES] = E_EDGES;
}

__global__ void fill_kernel(const int* __restrict__ src, const int* __restrict__ dst,
                            const float* __restrict__ dinv,
                            int* __restrict__ cur, int* __restrict__ csrc,
                            float* __restrict__ cw)
{
    int e = blockIdx.x * blockDim.x + threadIdx.x;
    if (e >= E_EDGES) return;
    int d = dst[e];
    int s = src[e];
    int pos = atomicAdd(&cur[d], 1);
    csrc[pos] = s;
    cw[pos] = dinv[s];
}

// ------- CSR aggregation + self loop + (affine+relu for next layer) --------
__global__ void __launch_bounds__(256) csr_agg_kernel(
    const float4* __restrict__ gw, const int* __restrict__ off,
    const int* __restrict__ csrc, const float* __restrict__ cw,
    const float* __restrict__ dinv,
    const float* __restrict__ aff_s, const float* __restrict__ aff_t,
    float4* __restrict__ outy)
{
    int row = blockIdx.x * 4 + (threadIdx.x >> 6);
    int c4 = threadIdx.x & 63;
    float di = dinv[row];
    float4 g = gw[(size_t)row * 64 + c4];
    float4 acc = make_float4(g.x * di, g.y * di, g.z * di, g.w * di);
    int e0 = off[row], e1 = off[row + 1];
    int j = e0;
    for (; j + 4 <= e1; j += 4) {
        int s0 = __ldg(&csrc[j]),     s1 = __ldg(&csrc[j + 1]);
        int s2 = __ldg(&csrc[j + 2]), s3 = __ldg(&csrc[j + 3]);
        float w0 = __ldg(&cw[j]),     w1 = __ldg(&cw[j + 1]);
        float w2 = __ldg(&cw[j + 2]), w3 = __ldg(&cw[j + 3]);
        float4 g0 = gw[(size_t)s0 * 64 + c4];
        float4 g1 = gw[(size_t)s1 * 64 + c4];
        float4 g2 = gw[(size_t)s2 * 64 + c4];
        float4 g3 = gw[(size_t)s3 * 64 + c4];
        acc.x = fmaf(w0, g0.x, fmaf(w1, g1.x, fmaf(w2, g2.x, fmaf(w3, g3.x, acc.x))));
        acc.y = fmaf(w0, g0.y, fmaf(w1, g1.y, fmaf(w2, g2.y, fmaf(w3, g3.y, acc.y))));
        acc.z = fmaf(w0, g0.z, fmaf(w1, g1.z, fmaf(w2, g2.z, fmaf(w3, g3.z, acc.z))));
        acc.w = fmaf(w0, g0.w, fmaf(w1, g1.w, fmaf(w2, g2.w, fmaf(w3, g3.w, acc.w))));
    }
    for (; j < e1; j++) {
        int s = __ldg(&csrc[j]);
        float w = __ldg(&cw[j]);
        float4 gv = gw[(size_t)s * 64 + c4];
        acc.x = fmaf(w, gv.x, acc.x);
        acc.y = fmaf(w, gv.y, acc.y);
        acc.z = fmaf(w, gv.z, acc.z);
        acc.w = fmaf(w, gv.w, acc.w);
    }
    acc.x *= di; acc.y *= di; acc.z *= di; acc.w *= di;
    if (aff_s) {
        float4 s4 = *reinterpret_cast<const float4*>(&aff_s[c4 * 4]);
        float4 t4 = *reinterpret_cast<const float4*>(&aff_t[c4 * 4]);
        acc.x = fmaxf(fmaf(acc.x, s4.x, t4.x), 0.f);
        acc.y = fmaxf(fmaf(acc.y, s4.y, t4.y), 0.f);
        acc.z = fmaxf(fmaf(acc.z, s4.z, t4.z), 0.f);
        acc.w = fmaxf(fmaf(acc.w, s4.w, t4.w), 0.f);
    }
    outy[(size_t)row * 64 + c4] = acc;
}

// ------- warp-per-row final: affine4 -> l2 -> out_g + pool (red.v4) --------
__global__ void __launch_bounds__(256) final_w(
    const float4* __restrict__ agg, const float4* __restrict__ s4,
    const float4* __restrict__ t4, const int* __restrict__ batch,
    float4* __restrict__ out_g, float* __restrict__ out_pool)
{
    int row = blockIdx.x * 8 + (threadIdx.x >> 5);
    if (row >= N_NODES) return;
    int lane = threadIdx.x & 31;
    size_t ro = (size_t)row * 64;
    float4 a0 = agg[ro + lane], a1 = agg[ro + lane + 32];
    float4 ss0 = s4[lane], ss1 = s4[lane + 32], tt0 = t4[lane], tt1 = t4[lane + 32];
    float4 v0, v1;
    v0.x = a0.x * ss0.x + tt0.x; v0.y = a0.y * ss0.y + tt0.y;
    v0.z = a0.z * ss0.z + tt0.z; v0.w = a0.w * ss0.w + tt0.w;
    v1.x = a1.x * ss1.x + tt1.x; v1.y = a1.y * ss1.y + tt1.y;
    v1.z = a1.z * ss1.z + tt1.z; v1.w = a1.w * ss1.w + tt1.w;
    float ssn = warp_sum(sumsq8(v0, v1));
    float inv_n = 1.f / fmaxf(sqrtf(ssn), 1e-12f);
    v0.x *= inv_n; v0.y *= inv_n; v0.z *= inv_n; v0.w *= inv_n;
    v1.x *= inv_n; v1.y *= inv_n; v1.z *= inv_n; v1.w *= inv_n;
    out_g[ro + lane] = v0; out_g[ro + lane + 32] = v1;
    int grp = batch[row];
    float* p0 = &out_pool[(size_t)grp * HID + lane * 4];
    float* p1 = p0 + 128;
    asm volatile("red.global.add.v4.f32 [%0], {%1, %2, %3, %4};"
                 :: "l"(p0), "f"(v0.x), "f"(v0.y), "f"(v0.z), "f"(v0.w) : "memory");
    asm volatile("red.global.add.v4.f32 [%0], {%1, %2, %3, %4};"
                 :: "l"(p1), "f"(v1.x), "f"(v1.y), "f"(v1.z), "f"(v1.w) : "memory");
}

// ---------------- launcher ----------------
extern "C" void kernel_launch(void* const* d_in, const int* in_sizes, int n_in,
                              void* d_out, int out_size)
{
    const float* x       = (const float*)d_in[0];
    const int*   edge    = (const int*)  d_in[1];
    const int*   batch   = (const int*)  d_in[2];
    // d_in[3] = beta (unused)
    const float* fc_W    = (const float*)d_in[4];
    const float* fc_b    = (const float*)d_in[5];
    const float* ln0_g   = (const float*)d_in[6];
    const float* ln0_b   = (const float*)d_in[7];
    const float* Wq      = (const float*)d_in[8];
    const float* bq      = (const float*)d_in[9];
    const float* Wk      = (const float*)d_in[10];
    const float* bk      = (const float*)d_in[11];
    const float* Wv      = (const float*)d_in[12];
    const float* bv      = (const float*)d_in[13];
    const float* ln1_g   = (const float*)d_in[14];
    const float* ln1_b   = (const float*)d_in[15];
    const float* gcn_W0  = (const float*)d_in[16];
    const float* gcn_b0  = (const float*)d_in[17];
    const float* gcn_W   = (const float*)d_in[18];
    const float* gcn_b   = (const float*)d_in[19];
    const float* bn_g    = (const float*)d_in[20];
    const float* bn_b    = (const float*)d_in[21];
    const float* bn_mean = (const float*)d_in[22];
    const float* bn_var  = (const float*)d_in[23];

    const int* src = edge;
    const int* dst = edge + E_EDGES;

    float* out      = (float*)d_out;
    float* out_pool = out;
    float* out_g    = out + (size_t)G_GRP * HID;
    float* out_xt   = out_g + (size_t)N_NODES * HID;

    float* fbase = nullptr;
    int* ibase = nullptr;
    cudaGetSymbolAddress((void**)&fbase, d_scratch);
    cudaGetSymbolAddress((void**)&ibase, d_iscratch);

    float* p_h   = fbase;
    float* p_q   = fbase + (size_t)1 * NH;
    float* p_v   = fbase + (size_t)2 * NH;
    float* p_t   = fbase + (size_t)3 * NH;
    float* p_gw  = fbase + (size_t)4 * NH;
    float* p_y   = fbase + (size_t)5 * NH;

    float* p_sm   = fbase + (size_t)6 * NH;
    float* p_S    = p_sm;
    float* p_U    = p_S + HID * HID;
    float* p_P    = p_U + HID * HID;
    float* p_kvs0 = p_P + HID * HID;
    float* p_hs   = p_kvs0 + HID * HID;
    float* p_scal = p_hs + HID;
    const int ZSM = 4 * HID * HID + HID + 16;

    float* p_kvsF  = p_scal + 16;
    float* p_kssum = p_kvsF + HID * HID;
    float* p_kk    = p_kssum + HID;
    float* p_wvhs  = p_kk + HID;
    float* p_dinv  = p_wvhs + HID;
    float* p_cs    = p_dinv + N_NODES;
    float* p_ct    = p_cs + NUM_GC * HID;
    float* p_cw    = p_ct + NUM_GC * HID;

    int* p_cnt     = ibase;
    int* p_off     = p_cnt + N_NODES;
    int* p_cur     = p_off + N_NODES + 1;
    int* p_csrc    = p_cur + N_NODES;
    int* p_partial = p_csrc + E_EDGES;
    int* p_pbase   = p_partial + 256;

    const dim3 gg(HID / 128, (N_NODES + 127) / 128);
    const dim3 gg2(HID / 128, (N_NODES + 127) / 128, 2);
    const int THR = 256;

    // ===== CSR build + coefficients + zero small region =====
    bn_coef_kernel<<<(NUM_GC * HID + THR - 1) / THR, THR>>>(
        gcn_b0, gcn_b, bn_g, bn_b, bn_mean, bn_var, p_cs, p_ct);
    zero_int_kernel<<<(N_NODES + THR - 1) / THR, THR>>>(p_cnt, N_NODES);
    zero_kernel<<<(ZSM + THR - 1) / THR, THR>>>(p_sm, ZSM);
    count_kernel<<<(E_EDGES + THR - 1) / THR, THR>>>(dst, p_cnt);
    scan_partial_kernel<<<SCANBLK, THR>>>(p_cnt, p_partial);
    scan_base_kernel<<<1, THR>>>(p_partial, p_pbase);
    scan_fill_kernel<<<SCANBLK, THR>>>(p_cnt, p_pbase, p_off, p_cur, p_dinv);
    fill_kernel<<<(E_EDGES + THR - 1) / THR, THR>>>(src, dst, p_dinv, p_cur, p_csrc, p_cw);

    // ===== shared K=128 GEMMs: fc and gcn layer-0 (A = x) =====
    sgemm128_b2<<<gg2, THR>>>(x, fc_W, gcn_W0, fc_b, nullptr,
                              p_t, p_gw, N_NODES, HID, F_IN, nullptr);
    ln_relu_w<<<NROWBLK, THR>>>((const float4*)p_t, (const float4*)ln0_g,
                                (const float4*)ln0_b, (float4*)p_h);

    // ===== Q and V GEMMs (A = h); Q sumsq fused into epilogue =====
    sgemm128_b2<<<gg2, THR>>>(p_h, Wq, Wv, bq, bv,
                              p_q, p_v, N_NODES, HID, HID, &p_scal[0]);

    // ===== small-matrix attention algebra =====
    colsum_kernel<<<2048, THR>>>(p_h, p_hs);
    {
        const int SPLITS = 64;
        const int rows_per_z = (N_NODES + SPLITS - 1) / SPLITS;
        atb_kernel<<<dim3(HID / 64, HID / 64, SPLITS), THR>>>(p_h, p_h, p_S, N_NODES, rows_per_z);
    }
    atb_kernel<<<dim3(HID / 64, HID / 64, 1), THR>>>(p_S, Wv, p_U, HID, HID);
    atb_kernel<<<dim3(HID / 64, HID / 64, 1), THR>>>(p_S, Wk, p_P, HID, HID);
    atb_kernel<<<dim3(HID / 64, HID / 64, 1), THR>>>(Wk, p_U, p_kvs0, HID, HID);
    matvec_kernel<<<2, THR>>>(Wk, Wv, p_hs, p_kk, p_wvhs);
    kss_kernel<<<1, THR>>>(p_P, Wk, bk, p_kk, p_scal);
    kvs_final_kernel<<<HID, THR>>>(p_kvs0, p_kk, p_wvhs, bk, bv, p_scal, p_kvsF, p_kssum);

    // t2 = Q @ kvsF ; epilogue
    sgemm128<<<gg, THR>>>(p_q, p_kvsF, nullptr, p_t, N_NODES, HID, HID);
    trans_epi_w<<<NROWBLK, THR>>>((const float4*)p_q, (const float4*)p_t,
                                  (const float4*)p_v, (const float4*)p_h,
                                  (const float4*)p_kssum, p_scal,
                                  (const float4*)ln1_g, (const float4*)ln1_b,
                                  (float4*)out_xt);

    // ===== GCN layers =====
    csr_agg_kernel<<<N_NODES / 4, THR>>>(
        (const float4*)p_gw, p_off, p_csrc, p_cw, p_dinv,
        p_cs, p_ct, (float4*)p_y);

    for (int i = 1; i < NUM_GC; i++) {
        const float* W = gcn_W + (size_t)(i - 1) * HID * HID;
        sgemm128<<<gg, THR>>>(p_y, W, nullptr, p_gw, N_NODES, HID, HID);
        const float* as = (i < NUM_GC - 1) ? p_cs + (size_t)i * HID : nullptr;
        const float* at = (i < NUM_GC - 1) ? p_ct + (size_t)i * HID : nullptr;
        csr_agg_kernel<<<N_NODES / 4, THR>>>(
            (const float4*)p_gw, p_off, p_csrc, p_cw, p_dinv, as, at, (float4*)p_y);
    }

    // ===== outputs =====
    zero_kernel<<<(G_GRP * HID + THR - 1) / THR, THR>>>(out_pool, G_GRP * HID);
    final_w<<<NROWBLK, THR>>>((const float4*)p_y,
                              (const float4*)(p_cs + (size_t)(NUM_GC - 1) * HID),
                              (const float4*)(p_ct + (size_t)(NUM_GC - 1) * HID),
                              batch, (float4*)out_g, out_pool);
}

// round 12
// speedup vs baseline: 1.5961x; 1.2084x over previous
#include <cuda_runtime.h>
#include <cuda_bf16.h>
#include <cstdint>
#include <math.h>

// ---------------- problem constants ----------------
#define N_NODES 50000
#define E_EDGES 300000
#define F_IN    128
#define HID     256
#define G_GRP   1000
#define NUM_GC  5
#define NH      (N_NODES * HID)
#define NROWBLK ((N_NODES + 7) / 8)
#define SCANBLK ((N_NODES + 255) / 256)

typedef unsigned long long ull;

// ---------------- scratch ----------------
// floats: h, t, gw, y (4*NH) then smalls (see launcher)
__device__ float d_scratch[4 * (size_t)NH + 1000000];
__device__ int d_iscratch[3 * N_NODES + 1 + E_EDGES + 512];

// ---------------- f32x2 helpers ----------------
__device__ __forceinline__ void ffma2(ull& d, ull a, ull b) {
    asm("fma.rn.f32x2 %0, %1, %2, %0;" : "+l"(d) : "l"(a), "l"(b));
}
__device__ __forceinline__ ull pack2(float x, float y) {
    ull r;
    asm("mov.b64 %0, {%1, %2};" : "=l"(r) : "f"(x), "f"(y));
    return r;
}
__device__ __forceinline__ void unpack2(float& lo, float& hi, ull v) {
    asm("mov.b64 {%0, %1}, %2;" : "=f"(lo), "=f"(hi) : "l"(v));
}

// ---------------- misc helpers ----------------
__device__ __forceinline__ float warp_sum(float v) {
#pragma unroll
    for (int o = 16; o; o >>= 1) v += __shfl_xor_sync(0xffffffffu, v, o);
    return v;
}
__device__ __forceinline__ float block_sum_256(float v, float* sh) {
    v = warp_sum(v);
    if ((threadIdx.x & 31) == 0) sh[threadIdx.x >> 5] = v;
    __syncthreads();
    if (threadIdx.x < 32) {
        float t = (threadIdx.x < 8) ? sh[threadIdx.x] : 0.f;
        t = warp_sum(t);
        if (threadIdx.x == 0) sh[8] = t;
    }
    __syncthreads();
    float r = sh[8];
    __syncthreads();
    return r;
}
__device__ __forceinline__ float sum8(float4 a, float4 b) {
    return a.x + a.y + a.z + a.w + b.x + b.y + b.z + b.w;
}
__device__ __forceinline__ float sumsq8(float4 a, float4 b) {
    return a.x*a.x + a.y*a.y + a.z*a.z + a.w*a.w
         + b.x*b.x + b.y*b.y + b.z*b.z + b.w*b.w;
}

__global__ void zero_kernel(float* __restrict__ p, int n) {
    int i = blockIdx.x * blockDim.x + threadIdx.x;
    if (i < n) p[i] = 0.f;
}
__global__ void zero_int_kernel(int* __restrict__ p, int n) {
    int i = blockIdx.x * blockDim.x + threadIdx.x;
    if (i < n) p[i] = 0;
}

// ============ 128x128x8 SGEMM (R6-proven, f32x2 FFMA2) ============
__device__ __forceinline__ void sgemm_body(
    const float* __restrict__ A, const float* __restrict__ B,
    const float* __restrict__ bias, float* __restrict__ C,
    int M, int Nn, int K)
{
    __shared__ __align__(16) float As[2][8][128];
    __shared__ __align__(16) float Bs[2][8][128];

    const int tid = threadIdx.x;
    const int tx = tid & 15;
    const int ty = tid >> 4;
    const int row0 = blockIdx.y * 128;
    const int col0 = blockIdx.x * 128;

    const int arow = tid >> 1, ak4 = (tid & 1) * 4;
    const int brow = tid >> 5, bc4 = (tid & 31) * 4;

    const int KT = K >> 3;

    ull acc[8][4];
#pragma unroll
    for (int i = 0; i < 8; i++)
#pragma unroll
        for (int j = 0; j < 4; j++) acc[i][j] = 0ull;

    float4 av, bv;

    {
        int r = row0 + arow;
        if (r < M) av = *reinterpret_cast<const float4*>(&A[(size_t)r * K + ak4]);
        else       av = make_float4(0.f, 0.f, 0.f, 0.f);
        bv = *reinterpret_cast<const float4*>(&B[(size_t)brow * Nn + col0 + bc4]);
        As[0][ak4 + 0][arow] = av.x; As[0][ak4 + 1][arow] = av.y;
        As[0][ak4 + 2][arow] = av.z; As[0][ak4 + 3][arow] = av.w;
        *reinterpret_cast<float4*>(&Bs[0][brow][bc4]) = bv;
    }
    __syncthreads();

    for (int kt = 0; kt < KT; kt++) {
        const int buf = kt & 1;
        if (kt + 1 < KT) {
            const int k0 = (kt + 1) << 3;
            int r = row0 + arow;
            if (r < M) av = *reinterpret_cast<const float4*>(&A[(size_t)r * K + k0 + ak4]);
            else       av = make_float4(0.f, 0.f, 0.f, 0.f);
            bv = *reinterpret_cast<const float4*>(&B[(size_t)(k0 + brow) * Nn + col0 + bc4]);
        }

#pragma unroll
        for (int k = 0; k < 8; k++) {
            float4 a0 = *reinterpret_cast<const float4*>(&As[buf][k][ty * 4]);
            float4 a1 = *reinterpret_cast<const float4*>(&As[buf][k][64 + ty * 4]);
            ulonglong2 b0 = *reinterpret_cast<const ulonglong2*>(&Bs[buf][k][tx * 4]);
            ulonglong2 b1 = *reinterpret_cast<const ulonglong2*>(&Bs[buf][k][64 + tx * 4]);
            ull bp0 = b0.x, bp1 = b0.y, bp2 = b1.x, bp3 = b1.y;
            float aa[8] = {a0.x, a0.y, a0.z, a0.w, a1.x, a1.y, a1.z, a1.w};
#pragma unroll
            for (int i = 0; i < 8; i++) {
                ull ap = pack2(aa[i], aa[i]);
                ffma2(acc[i][0], ap, bp0);
                ffma2(acc[i][1], ap, bp1);
                ffma2(acc[i][2], ap, bp2);
                ffma2(acc[i][3], ap, bp3);
            }
        }

        if (kt + 1 < KT) {
            const int nb = buf ^ 1;
            As[nb][ak4 + 0][arow] = av.x; As[nb][ak4 + 1][arow] = av.y;
            As[nb][ak4 + 2][arow] = av.z; As[nb][ak4 + 3][arow] = av.w;
            *reinterpret_cast<float4*>(&Bs[nb][brow][bc4]) = bv;
        }
        __syncthreads();
    }

    float4 b_lo = make_float4(0.f, 0.f, 0.f, 0.f), b_hi = b_lo;
    if (bias) {
        b_lo = *reinterpret_cast<const float4*>(&bias[col0 + tx * 4]);
        b_hi = *reinterpret_cast<const float4*>(&bias[col0 + 64 + tx * 4]);
    }
#pragma unroll
    for (int i = 0; i < 8; i++) {
        int row = row0 + ((i < 4) ? (ty * 4 + i) : (64 + ty * 4 + (i - 4)));
        if (row >= M) continue;
        float o0, o1, o2, o3, o4, o5, o6, o7;
        unpack2(o0, o1, acc[i][0]); unpack2(o2, o3, acc[i][1]);
        unpack2(o4, o5, acc[i][2]); unpack2(o6, o7, acc[i][3]);
        float4 lo = make_float4(o0 + b_lo.x, o1 + b_lo.y, o2 + b_lo.z, o3 + b_lo.w);
        float4 hi = make_float4(o4 + b_hi.x, o5 + b_hi.y, o6 + b_hi.z, o7 + b_hi.w);
        *reinterpret_cast<float4*>(&C[(size_t)row * Nn + col0 + tx * 4]) = lo;
        *reinterpret_cast<float4*>(&C[(size_t)row * Nn + col0 + 64 + tx * 4]) = hi;
    }
}

__global__ void __launch_bounds__(256, 2) sgemm128(
    const float* __restrict__ A, const float* __restrict__ B,
    const float* __restrict__ bias, float* __restrict__ C,
    int M, int Nn, int K)
{
    sgemm_body(A, B, bias, C, M, Nn, K);
}

__global__ void __launch_bounds__(256, 2) sgemm128_b2(
    const float* __restrict__ A,
    const float* __restrict__ B0, const float* __restrict__ B1,
    const float* __restrict__ bias0, const float* __restrict__ bias1,
    float* __restrict__ C0, float* __restrict__ C1,
    int M, int Nn, int K)
{
    if (blockIdx.z == 0) sgemm_body(A, B0, bias0, C0, M, Nn, K);
    else                 sgemm_body(A, B1, bias1, C1, M, Nn, K);
}

// ------ C[256,256] += A[L,256]^T @ B[L,256], split-K atomics, f32x2 --------
// sym!=0: skip tiles with tile_row > tile_col (use symfill after).
__global__ void __launch_bounds__(256) atb_kernel(
    const float* __restrict__ A, const float* __restrict__ B,
    float* __restrict__ C, int L, int rows_per_z, int sym)
{
    if (sym && blockIdx.y > blockIdx.x) return;

    __shared__ __align__(16) float As[32][128];
    __shared__ __align__(16) float Bs[32][64];

    const int tid = threadIdx.x;
    const int tx = tid & 15;
    const int ty = tid >> 4;
    const int ar0 = blockIdx.y * 64;
    const int bc0 = blockIdx.x * 64;
    const int lstart = blockIdx.z * rows_per_z;
    const int lend = min(L, lstart + rows_per_z);

    ull acc[4][2];
#pragma unroll
    for (int i = 0; i < 4; i++) { acc[i][0] = 0ull; acc[i][1] = 0ull; }

    for (int l0 = lstart; l0 < lend; l0 += 32) {
#pragma unroll
        for (int p = 0; p < 2; p++) {
            int id = tid + p * 256;
            int lr = id >> 4;
            int c4 = (id & 15) * 4;
            int l = l0 + lr;
            float4 avv, bvv;
            if (l < lend) {
                avv = *reinterpret_cast<const float4*>(&A[(size_t)l * HID + ar0 + c4]);
                bvv = *reinterpret_cast<const float4*>(&B[(size_t)l * HID + bc0 + c4]);
            } else { avv = make_float4(0,0,0,0); bvv = avv; }
            float am[4] = {avv.x, avv.y, avv.z, avv.w};
#pragma unroll
            for (int m = 0; m < 4; m++)
                *reinterpret_cast<ull*>(&As[lr][2 * (c4 + m)]) = pack2(am[m], am[m]);
            *reinterpret_cast<float4*>(&Bs[lr][c4]) = bvv;
        }
        __syncthreads();

#pragma unroll
        for (int l = 0; l < 32; l++) {
            ulonglong2 a01 = *reinterpret_cast<const ulonglong2*>(&As[l][ty * 8]);
            ulonglong2 a23 = *reinterpret_cast<const ulonglong2*>(&As[l][ty * 8 + 4]);
            ulonglong2 bp  = *reinterpret_cast<const ulonglong2*>(&Bs[l][tx * 4]);
            ull ap[4] = {a01.x, a01.y, a23.x, a23.y};
#pragma unroll
            for (int i = 0; i < 4; i++) {
                ffma2(acc[i][0], ap[i], bp.x);
                ffma2(acc[i][1], ap[i], bp.y);
            }
        }
        __syncthreads();
    }

#pragma unroll
    for (int i = 0; i < 4; i++) {
        float c0, c1, c2, c3;
        unpack2(c0, c1, acc[i][0]); unpack2(c2, c3, acc[i][1]);
        float* base = &C[(size_t)(ar0 + ty * 4 + i) * HID + bc0 + tx * 4];
        atomicAdd(base + 0, c0); atomicAdd(base + 1, c1);
        atomicAdd(base + 2, c2); atomicAdd(base + 3, c3);
    }
}

// mirror lower triangle tiles from upper: C[i][j] = C[j][i] for tile_row>tile_col
__global__ void symfill_kernel(float* __restrict__ C) {
    int i = blockIdx.x, j = threadIdx.x;
    if ((i >> 6) > (j >> 6))
        C[(size_t)i * HID + j] = C[(size_t)j * HID + i];
}

// ---------------- C[256,256] = A[256,256] @ B[256,256] ----------------
__global__ void __launch_bounds__(256) ab256_kernel(
    const float* __restrict__ A, const float* __restrict__ B, float* __restrict__ C)
{
    __shared__ float Ar[256];
    int i = blockIdx.x, j = threadIdx.x;
    Ar[j] = A[(size_t)i * HID + j];
    __syncthreads();
    float acc = 0.f;
    for (int l = 0; l < HID; l++) acc = fmaf(Ar[l], B[(size_t)l * HID + j], acc);
    C[(size_t)i * HID + j] = acc;
}

// ---------------- warp-per-row LN + relu ----------------
__global__ void __launch_bounds__(256) ln_relu_w(
    const float4* __restrict__ t, const float4* __restrict__ g,
    const float4* __restrict__ b, float4* __restrict__ out)
{
    int row = blockIdx.x * 8 + (threadIdx.x >> 5);
    if (row >= N_NODES) return;
    int lane = threadIdx.x & 31;
    const float4* tr = t + (size_t)row * 64;
    float4 v0 = tr[lane], v1 = tr[lane + 32];
    float s  = warp_sum(sum8(v0, v1));
    float s2 = warp_sum(sumsq8(v0, v1));
    float mean = s * (1.f / HID);
    float var  = s2 * (1.f / HID) - mean * mean;
    float r = rsqrtf(var + 1e-5f);
    float4 g0 = g[lane], g1 = g[lane + 32], b0 = b[lane], b1 = b[lane + 32];
    float4 o0, o1;
    o0.x = fmaxf((v0.x - mean) * r * g0.x + b0.x, 0.f);
    o0.y = fmaxf((v0.y - mean) * r * g0.y + b0.y, 0.f);
    o0.z = fmaxf((v0.z - mean) * r * g0.z + b0.z, 0.f);
    o0.w = fmaxf((v0.w - mean) * r * g0.w + b0.w, 0.f);
    o1.x = fmaxf((v1.x - mean) * r * g1.x + b1.x, 0.f);
    o1.y = fmaxf((v1.y - mean) * r * g1.y + b1.y, 0.f);
    o1.z = fmaxf((v1.z - mean) * r * g1.z + b1.z, 0.f);
    o1.w = fmaxf((v1.w - mean) * r * g1.w + b1.w, 0.f);
    float4* orow = out + (size_t)row * 64;
    orow[lane] = o0; orow[lane + 32] = o1;
}

// ---------------- column sum of h ----------------
__global__ void __launch_bounds__(256) colsum_kernel(
    const float* __restrict__ k, float* __restrict__ colsum)
{
    int c = threadIdx.x;
    float acc = 0.f;
    for (int r = blockIdx.x; r < N_NODES; r += gridDim.x)
        acc += k[(size_t)r * HID + c];
    atomicAdd(&colsum[c], acc);
}

// ---------------- 3-way column matvec: o = W^T hs for (Wk,Wv,Wq) ----------
__global__ void matvec3_kernel(const float* __restrict__ Wk, const float* __restrict__ Wv,
                               const float* __restrict__ Wq, const float* __restrict__ hs,
                               float* __restrict__ kk, float* __restrict__ wvhs,
                               float* __restrict__ kq)
{
    const float* W = (blockIdx.x == 0) ? Wk : (blockIdx.x == 1) ? Wv : Wq;
    float* o = (blockIdx.x == 0) ? kk : (blockIdx.x == 1) ? wvhs : kq;
    int c = threadIdx.x;
    float a = 0.f;
    for (int l = 0; l < HID; l++) a = fmaf(W[(size_t)l * HID + c], hs[l], a);
    o[c] = a;
}

// -------- trace: *out = sum(P.*W) + 2 b.wv + n||b||^2 --------
__global__ void __launch_bounds__(256) trace_kernel(
    const float* __restrict__ P, const float* __restrict__ W,
    const float* __restrict__ b, const float* __restrict__ wv,
    float* __restrict__ out)
{
    __shared__ float sh[16];
    float s = 0.f;
    for (int i = threadIdx.x; i < HID * HID; i += 256) s = fmaf(P[i], W[i], s);
    float bc_ = b[threadIdx.x];
    s += 2.f * bc_ * wv[threadIdx.x] + (float)N_NODES * bc_ * bc_;
    float tot = block_sum_256(s, sh);
    if (threadIdx.x == 0) *out = tot;
}

// ---------------- kvs finalize (+ kssum) ----------------
__global__ void kvs_final_kernel(const float* __restrict__ kvs0,
                                 const float* __restrict__ kk, const float* __restrict__ wvhs,
                                 const float* __restrict__ bk, const float* __restrict__ bv,
                                 const float* __restrict__ scal,
                                 float* __restrict__ kvsF, float* __restrict__ kssum)
{
    int i = blockIdx.x, j = threadIdx.x;
    float sk = rsqrtf(scal[1]);
    float bki = bk[i];
    float val = kvs0[(size_t)i * HID + j] + kk[i] * bv[j] + bki * wvhs[j]
              + (float)N_NODES * bki * bv[j];
    kvsF[(size_t)i * HID + j] = val * sk;
    if (j == 0) kssum[i] = (kk[i] + (float)N_NODES * bki) * sk;
}

// -------- w1 = Wq @ kssum (row-form matvec), warp per row --------
__global__ void __launch_bounds__(256) rowmv_kernel(
    const float* __restrict__ Wq, const float* __restrict__ kssum,
    float* __restrict__ w1)
{
    int row = blockIdx.x * 8 + (threadIdx.x >> 5);
    int lane = threadIdx.x & 31;
    const float4* wr = reinterpret_cast<const float4*>(&Wq[(size_t)row * HID]);
    const float4* ks = reinterpret_cast<const float4*>(kssum);
    float4 a0 = wr[lane], a1 = wr[lane + 32];
    float4 k0 = __ldg(&ks[lane]), k1 = __ldg(&ks[lane + 32]);
    float d = a0.x*k0.x + a0.y*k0.y + a0.z*k0.z + a0.w*k0.w
            + a1.x*k1.x + a1.y*k1.y + a1.z*k1.z + a1.w*k1.w;
    d = warp_sum(d);
    if (lane == 0) w1[row] = d;
}

// -------- bq' = kvsF^T bq (column matvec) --------
__global__ void __launch_bounds__(256) colmv_kernel(
    const float* __restrict__ kvsF, const float* __restrict__ bq,
    float* __restrict__ bqp)
{
    __shared__ float bs[256];
    int j = threadIdx.x;
    bs[j] = bq[j];
    __syncthreads();
    float a = 0.f;
    for (int l = 0; l < HID; l++) a = fmaf(kvsF[(size_t)l * HID + j], bs[l], a);
    bqp[j] = a;
}

// -------- Wc = rq*Wq' + n*Wv ; bc = rq*bq' + n*bv ; scal[2] = bq.kssum -----
__global__ void __launch_bounds__(256) combine_kernel(
    const float* __restrict__ wqp, const float* __restrict__ Wv,
    const float* __restrict__ bqp, const float* __restrict__ bv,
    const float* __restrict__ bq, const float* __restrict__ kssum,
    float* __restrict__ scal, float* __restrict__ Wc, float* __restrict__ bc)
{
    __shared__ float sh[16];
    float rq = rsqrtf(scal[0]);
    int b = blockIdx.x, j = threadIdx.x;
    if (b < 256) {
        size_t o = (size_t)b * HID + j;
        Wc[o] = rq * wqp[o] + (float)N_NODES * Wv[o];
    } else {
        bc[j] = rq * bqp[j] + (float)N_NODES * bv[j];
        float s = block_sum_256(bq[j] * kssum[j], sh);
        if (j == 0) scal[2] = s;
    }
}

// ---------------- warp-per-row TransConv epilogue ----------------
// h1 = 0.5*t3/denom + 0.5*h, denom = rq*(h.w1 + c1) + n; then LN+relu+l2.
__global__ void __launch_bounds__(256) trans_epi_w(
    const float4* __restrict__ t3, const float4* __restrict__ h,
    const float4* __restrict__ w1, const float* __restrict__ scal,
    const float4* __restrict__ g1, const float4* __restrict__ b1,
    float4* __restrict__ out_xt)
{
    int row = blockIdx.x * 8 + (threadIdx.x >> 5);
    if (row >= N_NODES) return;
    int lane = threadIdx.x & 31;
    size_t ro = (size_t)row * 64;
    float4 h0 = h[ro + lane], h1v = h[ro + lane + 32];
    float4 wa = w1[lane], wb = w1[lane + 32];
    float dotl = h0.x*wa.x + h0.y*wa.y + h0.z*wa.z + h0.w*wa.w
               + h1v.x*wb.x + h1v.y*wb.y + h1v.z*wb.z + h1v.w*wb.w;
    float dot = warp_sum(dotl);
    float rq = rsqrtf(scal[0]);
    float denom = rq * (dot + scal[2]) + (float)N_NODES;
    float hi = 0.5f / denom;
    float4 t0 = t3[ro + lane], t1 = t3[ro + lane + 32];
    float4 a0, a1;
    a0.x = t0.x * hi + 0.5f * h0.x;  a0.y = t0.y * hi + 0.5f * h0.y;
    a0.z = t0.z * hi + 0.5f * h0.z;  a0.w = t0.w * hi + 0.5f * h0.w;
    a1.x = t1.x * hi + 0.5f * h1v.x; a1.y = t1.y * hi + 0.5f * h1v.y;
    a1.z = t1.z * hi + 0.5f * h1v.z; a1.w = t1.w * hi + 0.5f * h1v.w;
    float s  = warp_sum(sum8(a0, a1));
    float s2 = warp_sum(sumsq8(a0, a1));
    float mean = s * (1.f / HID);
    float var  = s2 * (1.f / HID) - mean * mean;
    float r = rsqrtf(var + 1e-5f);
    float4 gg0 = g1[lane], gg1 = g1[lane + 32], bb0 = b1[lane], bb1 = b1[lane + 32];
    float4 y0, y1;
    y0.x = fmaxf((a0.x - mean) * r * gg0.x + bb0.x, 0.f);
    y0.y = fmaxf((a0.y - mean) * r * gg0.y + bb0.y, 0.f);
    y0.z = fmaxf((a0.z - mean) * r * gg0.z + bb0.z, 0.f);
    y0.w = fmaxf((a0.w - mean) * r * gg0.w + bb0.w, 0.f);
    y1.x = fmaxf((a1.x - mean) * r * gg1.x + bb1.x, 0.f);
    y1.y = fmaxf((a1.y - mean) * r * gg1.y + bb1.y, 0.f);
    y1.z = fmaxf((a1.z - mean) * r * gg1.z + bb1.z, 0.f);
    y1.w = fmaxf((a1.w - mean) * r * gg1.w + bb1.w, 0.f);
    float ssn = warp_sum(sumsq8(y0, y1));
    float inv_n = 1.f / fmaxf(sqrtf(ssn), 1e-12f);
    y0.x *= inv_n; y0.y *= inv_n; y0.z *= inv_n; y0.w *= inv_n;
    y1.x *= inv_n; y1.y *= inv_n; y1.z *= inv_n; y1.w *= inv_n;
    out_xt[ro + lane] = y0; out_xt[ro + lane + 32] = y1;
}

// ---------------- BN affine coefficients ----------------
__global__ void bn_coef_kernel(const float* __restrict__ gcn_b0, const float* __restrict__ gcn_b,
                               const float* __restrict__ bn_g, const float* __restrict__ bn_b,
                               const float* __restrict__ bn_mean, const float* __restrict__ bn_var,
                               float* __restrict__ coef_s, float* __restrict__ coef_t)
{
    int idx = blockIdx.x * blockDim.x + threadIdx.x;
    if (idx >= NUM_GC * HID) return;
    int layer = idx >> 8, c = idx & 255;
    float b = (layer == 0) ? gcn_b0[c] : gcn_b[(size_t)(layer - 1) * HID + c];
    float rs = rsqrtf(bn_var[idx] + 1e-5f);
    float sv = bn_g[idx] * rs;
    coef_s[idx] = sv;
    coef_t[idx] = (b - bn_mean[idx]) * sv + bn_b[idx];
}

// ---------------- CSR build (parallel scan) ----------------
__global__ void count_kernel(const int* __restrict__ dst, int* __restrict__ cnt) {
    int e = blockIdx.x * blockDim.x + threadIdx.x;
    if (e < E_EDGES) atomicAdd(&cnt[dst[e]], 1);
}

__global__ void __launch_bounds__(256) scan_partial_kernel(
    const int* __restrict__ cnt, int* __restrict__ partial)
{
    __shared__ int sh[8];
    int i = blockIdx.x * 256 + threadIdx.x;
    int v = (i < N_NODES) ? cnt[i] : 0;
#pragma unroll
    for (int o = 16; o; o >>= 1) v += __shfl_xor_sync(0xffffffffu, v, o);
    if ((threadIdx.x & 31) == 0) sh[threadIdx.x >> 5] = v;
    __syncthreads();
    if (threadIdx.x < 8) {
        int t = sh[threadIdx.x];
#pragma unroll
        for (int o = 4; o; o >>= 1) t += __shfl_xor_sync(0xffu, t, o);
        if (threadIdx.x == 0) partial[blockIdx.x] = t;
    }
}

__global__ void __launch_bounds__(256) scan_base_kernel(
    const int* __restrict__ partial, int* __restrict__ pbase)
{
    __shared__ int sh[256];
    int t = threadIdx.x;
    int v = (t < SCANBLK) ? partial[t] : 0;
    sh[t] = v;
    __syncthreads();
#pragma unroll
    for (int d = 1; d < 256; d <<= 1) {
        int u = (t >= d) ? sh[t - d] : 0;
        __syncthreads();
        sh[t] += u;
        __syncthreads();
    }
    pbase[t] = sh[t] - v;
}

__global__ void __launch_bounds__(256) scan_fill_kernel(
    const int* __restrict__ cnt, const int* __restrict__ pbase,
    int* __restrict__ off, int* __restrict__ cur, float* __restrict__ dinv)
{
    __shared__ int wsum[8];
    int i = blockIdx.x * 256 + threadIdx.x;
    int lane = threadIdx.x & 31, wid = threadIdx.x >> 5;
    int c = (i < N_NODES) ? cnt[i] : 0;
    int v = c;
#pragma unroll
    for (int o = 1; o < 32; o <<= 1) {
        int u = __shfl_up_sync(0xffffffffu, v, o);
        if (lane >= o) v += u;
    }
    if (lane == 31) wsum[wid] = v;
    __syncthreads();
    if (threadIdx.x < 8) {
        int w = wsum[threadIdx.x];
#pragma unroll
        for (int o = 1; o < 8; o <<= 1) {
            int u = __shfl_up_sync(0xffu, w, o);
            if (threadIdx.x >= o) w += u;
        }
        wsum[threadIdx.x] = w;
    }
    __syncthreads();
    int wpre = (wid == 0) ? 0 : wsum[wid - 1];
    int excl = v - c + wpre + pbase[blockIdx.x];
    if (i < N_NODES) {
        off[i] = excl;
        cur[i] = excl;
        dinv[i] = rsqrtf((float)(c + 1));
    }
    if (i == N_NODES - 1) off[N_NODES] = E_EDGES;
}

__global__ void fill_kernel(const int* __restrict__ src, const int* __restrict__ dst,
                            const float* __restrict__ dinv,
                            int* __restrict__ cur, int* __restrict__ csrc,
                            float* __restrict__ cw)
{
    int e = blockIdx.x * blockDim.x + threadIdx.x;
    if (e >= E_EDGES) return;
    int d = dst[e];
    int s = src[e];
    int pos = atomicAdd(&cur[d], 1);
    csrc[pos] = s;
    cw[pos] = dinv[s];
}

// ------- CSR aggregation + self loop + (affine+relu) --------
__global__ void __launch_bounds__(256) csr_agg_kernel(
    const float4* __restrict__ gw, const int* __restrict__ off,
    const int* __restrict__ csrc, const float* __restrict__ cw,
    const float* __restrict__ dinv,
    const float* __restrict__ aff_s, const float* __restrict__ aff_t,
    float4* __restrict__ outy)
{
    int row = blockIdx.x * 4 + (threadIdx.x >> 6);
    int c4 = threadIdx.x & 63;
    float di = dinv[row];
    float4 g = gw[(size_t)row * 64 + c4];
    float4 acc = make_float4(g.x * di, g.y * di, g.z * di, g.w * di);
    int e0 = off[row], e1 = off[row + 1];
    int j = e0;
    for (; j + 4 <= e1; j += 4) {
        int s0 = __ldg(&csrc[j]),     s1 = __ldg(&csrc[j + 1]);
        int s2 = __ldg(&csrc[j + 2]), s3 = __ldg(&csrc[j + 3]);
        float w0 = __ldg(&cw[j]),     w1 = __ldg(&cw[j + 1]);
        float w2 = __ldg(&cw[j + 2]), w3 = __ldg(&cw[j + 3]);
        float4 g0 = gw[(size_t)s0 * 64 + c4];
        float4 g1 = gw[(size_t)s1 * 64 + c4];
        float4 g2 = gw[(size_t)s2 * 64 + c4];
        float4 g3 = gw[(size_t)s3 * 64 + c4];
        acc.x = fmaf(w0, g0.x, fmaf(w1, g1.x, fmaf(w2, g2.x, fmaf(w3, g3.x, acc.x))));
        acc.y = fmaf(w0, g0.y, fmaf(w1, g1.y, fmaf(w2, g2.y, fmaf(w3, g3.y, acc.y))));
        acc.z = fmaf(w0, g0.z, fmaf(w1, g1.z, fmaf(w2, g2.z, fmaf(w3, g3.z, acc.z))));
        acc.w = fmaf(w0, g0.w, fmaf(w1, g1.w, fmaf(w2, g2.w, fmaf(w3, g3.w, acc.w))));
    }
    for (; j < e1; j++) {
        int s = __ldg(&csrc[j]);
        float w = __ldg(&cw[j]);
        float4 gv = gw[(size_t)s * 64 + c4];
        acc.x = fmaf(w, gv.x, acc.x);
        acc.y = fmaf(w, gv.y, acc.y);
        acc.z = fmaf(w, gv.z, acc.z);
        acc.w = fmaf(w, gv.w, acc.w);
    }
    acc.x *= di; acc.y *= di; acc.z *= di; acc.w *= di;
    if (aff_s) {
        float4 s4 = *reinterpret_cast<const float4*>(&aff_s[c4 * 4]);
        float4 t4 = *reinterpret_cast<const float4*>(&aff_t[c4 * 4]);
        acc.x = fmaxf(fmaf(acc.x, s4.x, t4.x), 0.f);
        acc.y = fmaxf(fmaf(acc.y, s4.y, t4.y), 0.f);
        acc.z = fmaxf(fmaf(acc.z, s4.z, t4.z), 0.f);
        acc.w = fmaxf(fmaf(acc.w, s4.w, t4.w), 0.f);
    }
    outy[(size_t)row * 64 + c4] = acc;
}

// ------- warp-per-row final ----------
__global__ void __launch_bounds__(256) final_w(
    const float4* __restrict__ agg, const float4* __restrict__ s4,
    const float4* __restrict__ t4, const int* __restrict__ batch,
    float4* __restrict__ out_g, float* __restrict__ out_pool)
{
    int row = blockIdx.x * 8 + (threadIdx.x >> 5);
    if (row >= N_NODES) return;
    int lane = threadIdx.x & 31;
    size_t ro = (size_t)row * 64;
    float4 a0 = agg[ro + lane], a1 = agg[ro + lane + 32];
    float4 ss0 = s4[lane], ss1 = s4[lane + 32], tt0 = t4[lane], tt1 = t4[lane + 32];
    float4 v0, v1;
    v0.x = a0.x * ss0.x + tt0.x; v0.y = a0.y * ss0.y + tt0.y;
    v0.z = a0.z * ss0.z + tt0.z; v0.w = a0.w * ss0.w + tt0.w;
    v1.x = a1.x * ss1.x + tt1.x; v1.y = a1.y * ss1.y + tt1.y;
    v1.z = a1.z * ss1.z + tt1.z; v1.w = a1.w * ss1.w + tt1.w;
    float ssn = warp_sum(sumsq8(v0, v1));
    float inv_n = 1.f / fmaxf(sqrtf(ssn), 1e-12f);
    v0.x *= inv_n; v0.y *= inv_n; v0.z *= inv_n; v0.w *= inv_n;
    v1.x *= inv_n; v1.y *= inv_n; v1.z *= inv_n; v1.w *= inv_n;
    out_g[ro + lane] = v0; out_g[ro + lane + 32] = v1;
    int grp = batch[row];
    float* p0 = &out_pool[(size_t)grp * HID + lane * 4];
    float* p1 = p0 + 128;
    asm volatile("red.global.add.v4.f32 [%0], {%1, %2, %3, %4};"
                 :: "l"(p0), "f"(v0.x), "f"(v0.y), "f"(v0.z), "f"(v0.w) : "memory");
    asm volatile("red.global.add.v4.f32 [%0], {%1, %2, %3, %4};"
                 :: "l"(p1), "f"(v1.x), "f"(v1.y), "f"(v1.z), "f"(v1.w) : "memory");
}

// ---------------- launcher ----------------
extern "C" void kernel_launch(void* const* d_in, const int* in_sizes, int n_in,
                              void* d_out, int out_size)
{
    const float* x       = (const float*)d_in[0];
    const int*   edge    = (const int*)  d_in[1];
    const int*   batch   = (const int*)  d_in[2];
    // d_in[3] = beta (unused)
    const float* fc_W    = (const float*)d_in[4];
    const float* fc_b    = (const float*)d_in[5];
    const float* ln0_g   = (const float*)d_in[6];
    const float* ln0_b   = (const float*)d_in[7];
    const float* Wq      = (const float*)d_in[8];
    const float* bq      = (const float*)d_in[9];
    const float* Wk      = (const float*)d_in[10];
    const float* bk      = (const float*)d_in[11];
    const float* Wv      = (const float*)d_in[12];
    const float* bv      = (const float*)d_in[13];
    const float* ln1_g   = (const float*)d_in[14];
    const float* ln1_b   = (const float*)d_in[15];
    const float* gcn_W0  = (const float*)d_in[16];
    const float* gcn_b0  = (const float*)d_in[17];
    const float* gcn_W   = (const float*)d_in[18];
    const float* gcn_b   = (const float*)d_in[19];
    const float* bn_g    = (const float*)d_in[20];
    const float* bn_b    = (const float*)d_in[21];
    const float* bn_mean = (const float*)d_in[22];
    const float* bn_var  = (const float*)d_in[23];

    const int* src = edge;
    const int* dst = edge + E_EDGES;

    float* out      = (float*)d_out;
    float* out_pool = out;
    float* out_g    = out + (size_t)G_GRP * HID;
    float* out_xt   = out_g + (size_t)N_NODES * HID;

    float* fbase = nullptr;
    int* ibase = nullptr;
    cudaGetSymbolAddress((void**)&fbase, d_scratch);
    cudaGetSymbolAddress((void**)&ibase, d_iscratch);

    float* p_h   = fbase;                    // [N,256]
    float* p_t   = fbase + (size_t)1 * NH;   // fc out / t3
    float* p_gw  = fbase + (size_t)2 * NH;   // GCN gemm outputs
    float* p_y   = fbase + (size_t)3 * NH;   // agg outputs

    float* p_sm   = fbase + (size_t)4 * NH;  // zeroed region start
    float* p_S    = p_sm;                    // 65536
    float* p_U    = p_S + HID * HID;         // 65536 (S@Wv)
    float* p_Pk   = p_U + HID * HID;         // 65536 (S@Wk)
    float* p_Pq   = p_Pk + HID * HID;        // 65536 (S@Wq)
    float* p_kvs0 = p_Pq + HID * HID;        // 65536
    float* p_hs   = p_kvs0 + HID * HID;      // 256
    float* p_scal = p_hs + HID;              // 16 [0]=qss [1]=kss [2]=c1
    const int ZSM = 5 * HID * HID + HID + 16;

    float* p_kvsF  = p_scal + 16;            // 65536
    float* p_wqp   = p_kvsF + HID * HID;     // 65536 (Wq@kvsF)
    float* p_Wc    = p_wqp + HID * HID;      // 65536
    float* p_kssum = p_Wc + HID * HID;       // 256
    float* p_kk    = p_kssum + HID;          // 256
    float* p_wvhs  = p_kk + HID;             // 256
    float* p_kq    = p_wvhs + HID;           // 256
    float* p_bqp   = p_kq + HID;             // 256
    float* p_bc    = p_bqp + HID;            // 256
    float* p_w1    = p_bc + HID;             // 256
    float* p_dinv  = p_w1 + HID;             // N
    float* p_cs    = p_dinv + N_NODES;       // 5*256
    float* p_ct    = p_cs + NUM_GC * HID;    // 5*256
    float* p_cw    = p_ct + NUM_GC * HID;    // E

    int* p_cnt     = ibase;
    int* p_off     = p_cnt + N_NODES;
    int* p_cur     = p_off + N_NODES + 1;
    int* p_csrc    = p_cur + N_NODES;
    int* p_partial = p_csrc + E_EDGES;
    int* p_pbase   = p_partial + 256;

    const dim3 gg(HID / 128, (N_NODES + 127) / 128);
    const dim3 gg2(HID / 128, (N_NODES + 127) / 128, 2);
    const int THR = 256;

    // ===== CSR build + coefficients + zeroing =====
    bn_coef_kernel<<<(NUM_GC * HID + THR - 1) / THR, THR>>>(
        gcn_b0, gcn_b, bn_g, bn_b, bn_mean, bn_var, p_cs, p_ct);
    zero_int_kernel<<<(N_NODES + THR - 1) / THR, THR>>>(p_cnt, N_NODES);
    zero_kernel<<<(ZSM + THR - 1) / THR, THR>>>(p_sm, ZSM);
    count_kernel<<<(E_EDGES + THR - 1) / THR, THR>>>(dst, p_cnt);
    scan_partial_kernel<<<SCANBLK, THR>>>(p_cnt, p_partial);
    scan_base_kernel<<<1, THR>>>(p_partial, p_pbase);
    scan_fill_kernel<<<SCANBLK, THR>>>(p_cnt, p_pbase, p_off, p_cur, p_dinv);
    fill_kernel<<<(E_EDGES + THR - 1) / THR, THR>>>(src, dst, p_dinv, p_cur, p_csrc, p_cw);

    // ===== batched K=128 GEMMs: fc and gcn layer-0 (both A = x) =====
    sgemm128_b2<<<gg2, THR>>>(x, fc_W, gcn_W0, fc_b, nullptr,
                              p_t, p_gw, N_NODES, HID, F_IN);
    ln_relu_w<<<NROWBLK, THR>>>((const float4*)p_t, (const float4*)ln0_g,
                                (const float4*)ln0_b, (float4*)p_h);

    // ===== attention small-matrix algebra (no Q/V GEMMs!) =====
    colsum_kernel<<<2048, THR>>>(p_h, p_hs);
    {   // S = H^T H (symmetric: upper tiles only + mirror)
        const int SPLITS = 64;
        const int rows_per_z = (N_NODES + SPLITS - 1) / SPLITS;
        atb_kernel<<<dim3(HID / 64, HID / 64, SPLITS), THR>>>(
            p_h, p_h, p_S, N_NODES, rows_per_z, 1);
    }
    symfill_kernel<<<HID, THR>>>(p_S);
    atb_kernel<<<dim3(4, 4, 1), THR>>>(p_S, Wv, p_U, HID, HID, 0);    // U = S@Wv
    atb_kernel<<<dim3(4, 4, 1), THR>>>(p_S, Wk, p_Pk, HID, HID, 0);   // Pk = S@Wk
    atb_kernel<<<dim3(4, 4, 1), THR>>>(p_S, Wq, p_Pq, HID, HID, 0);   // Pq = S@Wq
    atb_kernel<<<dim3(4, 4, 1), THR>>>(Wk, p_U, p_kvs0, HID, HID, 0); // kvs0 = Wk^T U
    matvec3_kernel<<<3, THR>>>(Wk, Wv, Wq, p_hs, p_kk, p_wvhs, p_kq);
    trace_kernel<<<1, THR>>>(p_Pk, Wk, bk, p_kk, &p_scal[1]);         // kss
    trace_kernel<<<1, THR>>>(p_Pq, Wq, bq, p_kq, &p_scal[0]);         // qss
    kvs_final_kernel<<<HID, THR>>>(p_kvs0, p_kk, p_wvhs, bk, bv, p_scal, p_kvsF, p_kssum);
    ab256_kernel<<<HID, THR>>>(Wq, p_kvsF, p_wqp);                    // Wq' = Wq@kvsF
    rowmv_kernel<<<HID / 8, THR>>>(Wq, p_kssum, p_w1);                // w1 = Wq@kssum
    colmv_kernel<<<1, THR>>>(p_kvsF, bq, p_bqp);                      // bq' = kvsF^T bq
    combine_kernel<<<HID + 1, THR>>>(p_wqp, Wv, p_bqp, bv, bq, p_kssum,
                                     p_scal, p_Wc, p_bc);

    // ===== t3 = H @ Wc + bc (the ONLY attention N-GEMM) =====
    sgemm128<<<gg, THR>>>(p_h, p_Wc, p_bc, p_t, N_NODES, HID, HID);
    trans_epi_w<<<NROWBLK, THR>>>((const float4*)p_t, (const float4*)p_h,
                                  (const float4*)p_w1, p_scal,
                                  (const float4*)ln1_g, (const float4*)ln1_b,
                                  (float4*)out_xt);

    // ===== GCN layers =====
    csr_agg_kernel<<<N_NODES / 4, THR>>>(
        (const float4*)p_gw, p_off, p_csrc, p_cw, p_dinv,
        p_cs, p_ct, (float4*)p_y);

    for (int i = 1; i < NUM_GC; i++) {
        const float* W = gcn_W + (size_t)(i - 1) * HID * HID;
        sgemm128<<<gg, THR>>>(p_y, W, nullptr, p_gw, N_NODES, HID, HID);
        const float* as = (i < NUM_GC - 1) ? p_cs + (size_t)i * HID : nullptr;
        const float* at = (i < NUM_GC - 1) ? p_ct + (size_t)i * HID : nullptr;
        csr_agg_kernel<<<N_NODES / 4, THR>>>(
            (const float4*)p_gw, p_off, p_csrc, p_cw, p_dinv, as, at, (float4*)p_y);
    }

    // ===== outputs =====
    zero_kernel<<<(G_GRP * HID + THR - 1) / THR, THR>>>(out_pool, G_GRP * HID);
    final_w<<<NROWBLK, THR>>>((const float4*)p_y,
                              (const float4*)(p_cs + (size_t)(NUM_GC - 1) * HID),
                              (const float4*)(p_ct + (size_t)(NUM_GC - 1) * HID),
                              batch, (float4*)out_g, out_pool);
}

// round 13
// speedup vs baseline: 1.6886x; 1.0579x over previous
#include <cuda_runtime.h>
#include <cuda_bf16.h>
#include <cstdint>
#include <math.h>

// ---------------- problem constants ----------------
#define N_NODES 50000
#define E_EDGES 300000
#define F_IN    128
#define HID     256
#define G_GRP   1000
#define NUM_GC  5
#define NH      (N_NODES * HID)
#define NROWBLK ((N_NODES + 7) / 8)
#define SCANBLK ((N_NODES + 255) / 256)

typedef unsigned long long ull;

// ---------------- scratch ----------------
__device__ float d_scratch[4 * (size_t)NH + 1000000];
__device__ int d_iscratch[3 * N_NODES + 1 + E_EDGES + 512];

// ---------------- f32x2 helpers ----------------
__device__ __forceinline__ void ffma2(ull& d, ull a, ull b) {
    asm("fma.rn.f32x2 %0, %1, %2, %0;" : "+l"(d) : "l"(a), "l"(b));
}
__device__ __forceinline__ ull pack2(float x, float y) {
    ull r;
    asm("mov.b64 %0, {%1, %2};" : "=l"(r) : "f"(x), "f"(y));
    return r;
}
__device__ __forceinline__ void unpack2(float& lo, float& hi, ull v) {
    asm("mov.b64 {%0, %1}, %2;" : "=f"(lo), "=f"(hi) : "l"(v));
}

// ---------------- misc helpers ----------------
__device__ __forceinline__ float warp_sum(float v) {
#pragma unroll
    for (int o = 16; o; o >>= 1) v += __shfl_xor_sync(0xffffffffu, v, o);
    return v;
}
__device__ __forceinline__ float block_sum_256(float v, float* sh) {
    v = warp_sum(v);
    if ((threadIdx.x & 31) == 0) sh[threadIdx.x >> 5] = v;
    __syncthreads();
    if (threadIdx.x < 32) {
        float t = (threadIdx.x < 8) ? sh[threadIdx.x] : 0.f;
        t = warp_sum(t);
        if (threadIdx.x == 0) sh[8] = t;
    }
    __syncthreads();
    float r = sh[8];
    __syncthreads();
    return r;
}
__device__ __forceinline__ float sum8(float4 a, float4 b) {
    return a.x + a.y + a.z + a.w + b.x + b.y + b.z + b.w;
}
__device__ __forceinline__ float sumsq8(float4 a, float4 b) {
    return a.x*a.x + a.y*a.y + a.z*a.z + a.w*a.w
         + b.x*b.x + b.y*b.y + b.z*b.z + b.w*b.w;
}

__global__ void zero_kernel(float* __restrict__ p, int n) {
    int i = blockIdx.x * blockDim.x + threadIdx.x;
    if (i < n) p[i] = 0.f;
}
__global__ void zero_int_kernel(int* __restrict__ p, int n) {
    int i = blockIdx.x * blockDim.x + threadIdx.x;
    if (i < n) p[i] = 0;
}

// ============ 128x128x16 SGEMM (f32x2 FFMA2, plain-A layout) ============
// BK=16 halves __syncthreads count vs BK=8; per-k LDS bytes unchanged
// (4x LDS.128/thread/k) so the crossbar/FFMA2 balance is preserved.
__device__ __forceinline__ void sgemm_body(
    const float* __restrict__ A, const float* __restrict__ B,
    const float* __restrict__ bias, float* __restrict__ C,
    int M, int Nn, int K)
{
    __shared__ __align__(16) float As[2][16][128];
    __shared__ __align__(16) float Bs[2][16][128];

    const int tid = threadIdx.x;
    const int tx = tid & 15;
    const int ty = tid >> 4;
    const int row0 = blockIdx.y * 128;
    const int col0 = blockIdx.x * 128;

    const int KT = K >> 4;

    ull acc[8][4];
#pragma unroll
    for (int i = 0; i < 8; i++)
#pragma unroll
        for (int j = 0; j < 4; j++) acc[i][j] = 0ull;

    float4 av[2], bv[2];

    // prologue (stage 0)
#pragma unroll
    for (int p = 0; p < 2; p++) {
        int f4 = tid + p * 256;
        int arow = f4 >> 2, ak4 = (f4 & 3) * 4;
        int r = row0 + arow;
        float4 a;
        if (r < M) a = *reinterpret_cast<const float4*>(&A[(size_t)r * K + ak4]);
        else       a = make_float4(0.f, 0.f, 0.f, 0.f);
        As[0][ak4 + 0][arow] = a.x; As[0][ak4 + 1][arow] = a.y;
        As[0][ak4 + 2][arow] = a.z; As[0][ak4 + 3][arow] = a.w;
        int brow = f4 >> 5, bc4 = (f4 & 31) * 4;
        *reinterpret_cast<float4*>(&Bs[0][brow][bc4]) =
            *reinterpret_cast<const float4*>(&B[(size_t)brow * Nn + col0 + bc4]);
    }
    __syncthreads();

    for (int kt = 0; kt < KT; kt++) {
        const int buf = kt & 1;
        if (kt + 1 < KT) {
            const int k0 = (kt + 1) << 4;
#pragma unroll
            for (int p = 0; p < 2; p++) {
                int f4 = tid + p * 256;
                int arow = f4 >> 2, ak4 = (f4 & 3) * 4;
                int r = row0 + arow;
                if (r < M) av[p] = *reinterpret_cast<const float4*>(&A[(size_t)r * K + k0 + ak4]);
                else       av[p] = make_float4(0.f, 0.f, 0.f, 0.f);
                int brow = f4 >> 5, bc4 = (f4 & 31) * 4;
                bv[p] = *reinterpret_cast<const float4*>(&B[(size_t)(k0 + brow) * Nn + col0 + bc4]);
            }
        }

#pragma unroll
        for (int k = 0; k < 16; k++) {
            float4 a0 = *reinterpret_cast<const float4*>(&As[buf][k][ty * 4]);
            float4 a1 = *reinterpret_cast<const float4*>(&As[buf][k][64 + ty * 4]);
            ulonglong2 b0 = *reinterpret_cast<const ulonglong2*>(&Bs[buf][k][tx * 4]);
            ulonglong2 b1 = *reinterpret_cast<const ulonglong2*>(&Bs[buf][k][64 + tx * 4]);
            ull bp0 = b0.x, bp1 = b0.y, bp2 = b1.x, bp3 = b1.y;
            float aa[8] = {a0.x, a0.y, a0.z, a0.w, a1.x, a1.y, a1.z, a1.w};
#pragma unroll
            for (int i = 0; i < 8; i++) {
                ull ap = pack2(aa[i], aa[i]);
                ffma2(acc[i][0], ap, bp0);
                ffma2(acc[i][1], ap, bp1);
                ffma2(acc[i][2], ap, bp2);
                ffma2(acc[i][3], ap, bp3);
            }
        }

        if (kt + 1 < KT) {
            const int nb = buf ^ 1;
#pragma unroll
            for (int p = 0; p < 2; p++) {
                int f4 = tid + p * 256;
                int arow = f4 >> 2, ak4 = (f4 & 3) * 4;
                As[nb][ak4 + 0][arow] = av[p].x; As[nb][ak4 + 1][arow] = av[p].y;
                As[nb][ak4 + 2][arow] = av[p].z; As[nb][ak4 + 3][arow] = av[p].w;
                int brow = f4 >> 5, bc4 = (f4 & 31) * 4;
                *reinterpret_cast<float4*>(&Bs[nb][brow][bc4]) = bv[p];
            }
        }
        __syncthreads();
    }

    float4 b_lo = make_float4(0.f, 0.f, 0.f, 0.f), b_hi = b_lo;
    if (bias) {
        b_lo = *reinterpret_cast<const float4*>(&bias[col0 + tx * 4]);
        b_hi = *reinterpret_cast<const float4*>(&bias[col0 + 64 + tx * 4]);
    }
#pragma unroll
    for (int i = 0; i < 8; i++) {
        int row = row0 + ((i < 4) ? (ty * 4 + i) : (64 + ty * 4 + (i - 4)));
        if (row >= M) continue;
        float o0, o1, o2, o3, o4, o5, o6, o7;
        unpack2(o0, o1, acc[i][0]); unpack2(o2, o3, acc[i][1]);
        unpack2(o4, o5, acc[i][2]); unpack2(o6, o7, acc[i][3]);
        float4 lo = make_float4(o0 + b_lo.x, o1 + b_lo.y, o2 + b_lo.z, o3 + b_lo.w);
        float4 hi = make_float4(o4 + b_hi.x, o5 + b_hi.y, o6 + b_hi.z, o7 + b_hi.w);
        *reinterpret_cast<float4*>(&C[(size_t)row * Nn + col0 + tx * 4]) = lo;
        *reinterpret_cast<float4*>(&C[(size_t)row * Nn + col0 + 64 + tx * 4]) = hi;
    }
}

__global__ void __launch_bounds__(256, 2) sgemm128(
    const float* __restrict__ A, const float* __restrict__ B,
    const float* __restrict__ bias, float* __restrict__ C,
    int M, int Nn, int K)
{
    sgemm_body(A, B, bias, C, M, Nn, K);
}

__global__ void __launch_bounds__(256, 2) sgemm128_b2(
    const float* __restrict__ A,
    const float* __restrict__ B0, const float* __restrict__ B1,
    const float* __restrict__ bias0, const float* __restrict__ bias1,
    float* __restrict__ C0, float* __restrict__ C1,
    int M, int Nn, int K)
{
    if (blockIdx.z == 0) sgemm_body(A, B0, bias0, C0, M, Nn, K);
    else                 sgemm_body(A, B1, bias1, C1, M, Nn, K);
}

// ------ C[256,256] += A[L,256]^T @ B[L,256], split-K atomics, f32x2 --------
__global__ void __launch_bounds__(256) atb_kernel(
    const float* __restrict__ A, const float* __restrict__ B,
    float* __restrict__ C, int L, int rows_per_z, int sym)
{
    if (sym && blockIdx.y > blockIdx.x) return;

    __shared__ __align__(16) float As[32][128];
    __shared__ __align__(16) float Bs[32][64];

    const int tid = threadIdx.x;
    const int tx = tid & 15;
    const int ty = tid >> 4;
    const int ar0 = blockIdx.y * 64;
    const int bc0 = blockIdx.x * 64;
    const int lstart = blockIdx.z * rows_per_z;
    const int lend = min(L, lstart + rows_per_z);

    ull acc[4][2];
#pragma unroll
    for (int i = 0; i < 4; i++) { acc[i][0] = 0ull; acc[i][1] = 0ull; }

    for (int l0 = lstart; l0 < lend; l0 += 32) {
#pragma unroll
        for (int p = 0; p < 2; p++) {
            int id = tid + p * 256;
            int lr = id >> 4;
            int c4 = (id & 15) * 4;
            int l = l0 + lr;
            float4 avv, bvv;
            if (l < lend) {
                avv = *reinterpret_cast<const float4*>(&A[(size_t)l * HID + ar0 + c4]);
                bvv = *reinterpret_cast<const float4*>(&B[(size_t)l * HID + bc0 + c4]);
            } else { avv = make_float4(0,0,0,0); bvv = avv; }
            float am[4] = {avv.x, avv.y, avv.z, avv.w};
#pragma unroll
            for (int m = 0; m < 4; m++)
                *reinterpret_cast<ull*>(&As[lr][2 * (c4 + m)]) = pack2(am[m], am[m]);
            *reinterpret_cast<float4*>(&Bs[lr][c4]) = bvv;
        }
        __syncthreads();

#pragma unroll
        for (int l = 0; l < 32; l++) {
            ulonglong2 a01 = *reinterpret_cast<const ulonglong2*>(&As[l][ty * 8]);
            ulonglong2 a23 = *reinterpret_cast<const ulonglong2*>(&As[l][ty * 8 + 4]);
            ulonglong2 bp  = *reinterpret_cast<const ulonglong2*>(&Bs[l][tx * 4]);
            ull ap[4] = {a01.x, a01.y, a23.x, a23.y};
#pragma unroll
            for (int i = 0; i < 4; i++) {
                ffma2(acc[i][0], ap[i], bp.x);
                ffma2(acc[i][1], ap[i], bp.y);
            }
        }
        __syncthreads();
    }

#pragma unroll
    for (int i = 0; i < 4; i++) {
        float c0, c1, c2, c3;
        unpack2(c0, c1, acc[i][0]); unpack2(c2, c3, acc[i][1]);
        float* base = &C[(size_t)(ar0 + ty * 4 + i) * HID + bc0 + tx * 4];
        atomicAdd(base + 0, c0); atomicAdd(base + 1, c1);
        atomicAdd(base + 2, c2); atomicAdd(base + 3, c3);
    }
}

__global__ void symfill_kernel(float* __restrict__ C) {
    int i = blockIdx.x, j = threadIdx.x;
    if ((i >> 6) > (j >> 6))
        C[(size_t)i * HID + j] = C[(size_t)j * HID + i];
}

// ---------------- C[256,256] = A[256,256] @ B[256,256] ----------------
__global__ void __launch_bounds__(256) ab256_kernel(
    const float* __restrict__ A, const float* __restrict__ B, float* __restrict__ C)
{
    __shared__ float Ar[256];
    int i = blockIdx.x, j = threadIdx.x;
    Ar[j] = A[(size_t)i * HID + j];
    __syncthreads();
    float acc = 0.f;
    for (int l = 0; l < HID; l++) acc = fmaf(Ar[l], B[(size_t)l * HID + j], acc);
    C[(size_t)i * HID + j] = acc;
}

// ---------------- warp-per-row LN + relu ----------------
__global__ void __launch_bounds__(256) ln_relu_w(
    const float4* __restrict__ t, const float4* __restrict__ g,
    const float4* __restrict__ b, float4* __restrict__ out)
{
    int row = blockIdx.x * 8 + (threadIdx.x >> 5);
    if (row >= N_NODES) return;
    int lane = threadIdx.x & 31;
    const float4* tr = t + (size_t)row * 64;
    float4 v0 = tr[lane], v1 = tr[lane + 32];
    float s  = warp_sum(sum8(v0, v1));
    float s2 = warp_sum(sumsq8(v0, v1));
    float mean = s * (1.f / HID);
    float var  = s2 * (1.f / HID) - mean * mean;
    float r = rsqrtf(var + 1e-5f);
    float4 g0 = g[lane], g1 = g[lane + 32], b0 = b[lane], b1 = b[lane + 32];
    float4 o0, o1;
    o0.x = fmaxf((v0.x - mean) * r * g0.x + b0.x, 0.f);
    o0.y = fmaxf((v0.y - mean) * r * g0.y + b0.y, 0.f);
    o0.z = fmaxf((v0.z - mean) * r * g0.z + b0.z, 0.f);
    o0.w = fmaxf((v0.w - mean) * r * g0.w + b0.w, 0.f);
    o1.x = fmaxf((v1.x - mean) * r * g1.x + b1.x, 0.f);
    o1.y = fmaxf((v1.y - mean) * r * g1.y + b1.y, 0.f);
    o1.z = fmaxf((v1.z - mean) * r * g1.z + b1.z, 0.f);
    o1.w = fmaxf((v1.w - mean) * r * g1.w + b1.w, 0.f);
    float4* orow = out + (size_t)row * 64;
    orow[lane] = o0; orow[lane + 32] = o1;
}

// ---------------- column sum of h ----------------
__global__ void __launch_bounds__(256) colsum_kernel(
    const float* __restrict__ k, float* __restrict__ colsum)
{
    int c = threadIdx.x;
    float acc = 0.f;
    for (int r = blockIdx.x; r < N_NODES; r += gridDim.x)
        acc += k[(size_t)r * HID + c];
    atomicAdd(&colsum[c], acc);
}

// ---------------- 3-way column matvec ----------------
__global__ void matvec3_kernel(const float* __restrict__ Wk, const float* __restrict__ Wv,
                               const float* __restrict__ Wq, const float* __restrict__ hs,
                               float* __restrict__ kk, float* __restrict__ wvhs,
                               float* __restrict__ kq)
{
    const float* W = (blockIdx.x == 0) ? Wk : (blockIdx.x == 1) ? Wv : Wq;
    float* o = (blockIdx.x == 0) ? kk : (blockIdx.x == 1) ? wvhs : kq;
    int c = threadIdx.x;
    float a = 0.f;
    for (int l = 0; l < HID; l++) a = fmaf(W[(size_t)l * HID + c], hs[l], a);
    o[c] = a;
}

// -------- trace: *out = sum(P.*W) + 2 b.wv + n||b||^2 --------
__global__ void __launch_bounds__(256) trace_kernel(
    const float* __restrict__ P, const float* __restrict__ W,
    const float* __restrict__ b, const float* __restrict__ wv,
    float* __restrict__ out)
{
    __shared__ float sh[16];
    float s = 0.f;
    for (int i = threadIdx.x; i < HID * HID; i += 256) s = fmaf(P[i], W[i], s);
    float bc_ = b[threadIdx.x];
    s += 2.f * bc_ * wv[threadIdx.x] + (float)N_NODES * bc_ * bc_;
    float tot = block_sum_256(s, sh);
    if (threadIdx.x == 0) *out = tot;
}

// ---------------- kvs finalize (+ kssum) ----------------
__global__ void kvs_final_kernel(const float* __restrict__ kvs0,
                                 const float* __restrict__ kk, const float* __restrict__ wvhs,
                                 const float* __restrict__ bk, const float* __restrict__ bv,
                                 const float* __restrict__ scal,
                                 float* __restrict__ kvsF, float* __restrict__ kssum)
{
    int i = blockIdx.x, j = threadIdx.x;
    float sk = rsqrtf(scal[1]);
    float bki = bk[i];
    float val = kvs0[(size_t)i * HID + j] + kk[i] * bv[j] + bki * wvhs[j]
              + (float)N_NODES * bki * bv[j];
    kvsF[(size_t)i * HID + j] = val * sk;
    if (j == 0) kssum[i] = (kk[i] + (float)N_NODES * bki) * sk;
}

// -------- w1 = Wq @ kssum, warp per row --------
__global__ void __launch_bounds__(256) rowmv_kernel(
    const float* __restrict__ Wq, const float* __restrict__ kssum,
    float* __restrict__ w1)
{
    int row = blockIdx.x * 8 + (threadIdx.x >> 5);
    int lane = threadIdx.x & 31;
    const float4* wr = reinterpret_cast<const float4*>(&Wq[(size_t)row * HID]);
    const float4* ks = reinterpret_cast<const float4*>(kssum);
    float4 a0 = wr[lane], a1 = wr[lane + 32];
    float4 k0 = __ldg(&ks[lane]), k1 = __ldg(&ks[lane + 32]);
    float d = a0.x*k0.x + a0.y*k0.y + a0.z*k0.z + a0.w*k0.w
            + a1.x*k1.x + a1.y*k1.y + a1.z*k1.z + a1.w*k1.w;
    d = warp_sum(d);
    if (lane == 0) w1[row] = d;
}

// -------- bq' = kvsF^T bq --------
__global__ void __launch_bounds__(256) colmv_kernel(
    const float* __restrict__ kvsF, const float* __restrict__ bq,
    float* __restrict__ bqp)
{
    __shared__ float bs[256];
    int j = threadIdx.x;
    bs[j] = bq[j];
    __syncthreads();
    float a = 0.f;
    for (int l = 0; l < HID; l++) a = fmaf(kvsF[(size_t)l * HID + j], bs[l], a);
    bqp[j] = a;
}

// -------- Wc = rq*Wq' + n*Wv ; bc = rq*bq' + n*bv ; scal[2] = bq.kssum -----
__global__ void __launch_bounds__(256) combine_kernel(
    const float* __restrict__ wqp, const float* __restrict__ Wv,
    const float* __restrict__ bqp, const float* __restrict__ bv,
    const float* __restrict__ bq, const float* __restrict__ kssum,
    float* __restrict__ scal, float* __restrict__ Wc, float* __restrict__ bc)
{
    __shared__ float sh[16];
    float rq = rsqrtf(scal[0]);
    int b = blockIdx.x, j = threadIdx.x;
    if (b < 256) {
        size_t o = (size_t)b * HID + j;
        Wc[o] = rq * wqp[o] + (float)N_NODES * Wv[o];
    } else {
        bc[j] = rq * bqp[j] + (float)N_NODES * bv[j];
        float s = block_sum_256(bq[j] * kssum[j], sh);
        if (j == 0) scal[2] = s;
    }
}

// ---------------- warp-per-row TransConv epilogue ----------------
__global__ void __launch_bounds__(256) trans_epi_w(
    const float4* __restrict__ t3, const float4* __restrict__ h,
    const float4* __restrict__ w1, const float* __restrict__ scal,
    const float4* __restrict__ g1, const float4* __restrict__ b1,
    float4* __restrict__ out_xt)
{
    int row = blockIdx.x * 8 + (threadIdx.x >> 5);
    if (row >= N_NODES) return;
    int lane = threadIdx.x & 31;
    size_t ro = (size_t)row * 64;
    float4 h0 = h[ro + lane], h1v = h[ro + lane + 32];
    float4 wa = w1[lane], wb = w1[lane + 32];
    float dotl = h0.x*wa.x + h0.y*wa.y + h0.z*wa.z + h0.w*wa.w
               + h1v.x*wb.x + h1v.y*wb.y + h1v.z*wb.z + h1v.w*wb.w;
    float dot = warp_sum(dotl);
    float rq = rsqrtf(scal[0]);
    float denom = rq * (dot + scal[2]) + (float)N_NODES;
    float hi = 0.5f / denom;
    float4 t0 = t3[ro + lane], t1 = t3[ro + lane + 32];
    float4 a0, a1;
    a0.x = t0.x * hi + 0.5f * h0.x;  a0.y = t0.y * hi + 0.5f * h0.y;
    a0.z = t0.z * hi + 0.5f * h0.z;  a0.w = t0.w * hi + 0.5f * h0.w;
    a1.x = t1.x * hi + 0.5f * h1v.x; a1.y = t1.y * hi + 0.5f * h1v.y;
    a1.z = t1.z * hi + 0.5f * h1v.z; a1.w = t1.w * hi + 0.5f * h1v.w;
    float s  = warp_sum(sum8(a0, a1));
    float s2 = warp_sum(sumsq8(a0, a1));
    float mean = s * (1.f / HID);
    float var  = s2 * (1.f / HID) - mean * mean;
    float r = rsqrtf(var + 1e-5f);
    float4 gg0 = g1[lane], gg1 = g1[lane + 32], bb0 = b1[lane], bb1 = b1[lane + 32];
    float4 y0, y1;
    y0.x = fmaxf((a0.x - mean) * r * gg0.x + bb0.x, 0.f);
    y0.y = fmaxf((a0.y - mean) * r * gg0.y + bb0.y, 0.f);
    y0.z = fmaxf((a0.z - mean) * r * gg0.z + bb0.z, 0.f);
    y0.w = fmaxf((a0.w - mean) * r * gg0.w + bb0.w, 0.f);
    y1.x = fmaxf((a1.x - mean) * r * gg1.x + bb1.x, 0.f);
    y1.y = fmaxf((a1.y - mean) * r * gg1.y + bb1.y, 0.f);
    y1.z = fmaxf((a1.z - mean) * r * gg1.z + bb1.z, 0.f);
    y1.w = fmaxf((a1.w - mean) * r * gg1.w + bb1.w, 0.f);
    float ssn = warp_sum(sumsq8(y0, y1));
    float inv_n = 1.f / fmaxf(sqrtf(ssn), 1e-12f);
    y0.x *= inv_n; y0.y *= inv_n; y0.z *= inv_n; y0.w *= inv_n;
    y1.x *= inv_n; y1.y *= inv_n; y1.z *= inv_n; y1.w *= inv_n;
    out_xt[ro + lane] = y0; out_xt[ro + lane + 32] = y1;
}

// ---------------- BN affine coefficients ----------------
__global__ void bn_coef_kernel(const float* __restrict__ gcn_b0, const float* __restrict__ gcn_b,
                               const float* __restrict__ bn_g, const float* __restrict__ bn_b,
                               const float* __restrict__ bn_mean, const float* __restrict__ bn_var,
                               float* __restrict__ coef_s, float* __restrict__ coef_t)
{
    int idx = blockIdx.x * blockDim.x + threadIdx.x;
    if (idx >= NUM_GC * HID) return;
    int layer = idx >> 8, c = idx & 255;
    float b = (layer == 0) ? gcn_b0[c] : gcn_b[(size_t)(layer - 1) * HID + c];
    float rs = rsqrtf(bn_var[idx] + 1e-5f);
    float sv = bn_g[idx] * rs;
    coef_s[idx] = sv;
    coef_t[idx] = (b - bn_mean[idx]) * sv + bn_b[idx];
}

// ---------------- CSR build (parallel scan) ----------------
__global__ void count_kernel(const int* __restrict__ dst, int* __restrict__ cnt) {
    int e = blockIdx.x * blockDim.x + threadIdx.x;
    if (e < E_EDGES) atomicAdd(&cnt[dst[e]], 1);
}

__global__ void __launch_bounds__(256) scan_partial_kernel(
    const int* __restrict__ cnt, int* __restrict__ partial)
{
    __shared__ int sh[8];
    int i = blockIdx.x * 256 + threadIdx.x;
    int v = (i < N_NODES) ? cnt[i] : 0;
#pragma unroll
    for (int o = 16; o; o >>= 1) v += __shfl_xor_sync(0xffffffffu, v, o);
    if ((threadIdx.x & 31) == 0) sh[threadIdx.x >> 5] = v;
    __syncthreads();
    if (threadIdx.x < 8) {
        int t = sh[threadIdx.x];
#pragma unroll
        for (int o = 4; o; o >>= 1) t += __shfl_xor_sync(0xffu, t, o);
        if (threadIdx.x == 0) partial[blockIdx.x] = t;
    }
}

__global__ void __launch_bounds__(256) scan_base_kernel(
    const int* __restrict__ partial, int* __restrict__ pbase)
{
    __shared__ int sh[256];
    int t = threadIdx.x;
    int v = (t < SCANBLK) ? partial[t] : 0;
    sh[t] = v;
    __syncthreads();
#pragma unroll
    for (int d = 1; d < 256; d <<= 1) {
        int u = (t >= d) ? sh[t - d] : 0;
        __syncthreads();
        sh[t] += u;
        __syncthreads();
    }
    pbase[t] = sh[t] - v;
}

__global__ void __launch_bounds__(256) scan_fill_kernel(
    const int* __restrict__ cnt, const int* __restrict__ pbase,
    int* __restrict__ off, int* __restrict__ cur, float* __restrict__ dinv)
{
    __shared__ int wsum[8];
    int i = blockIdx.x * 256 + threadIdx.x;
    int lane = threadIdx.x & 31, wid = threadIdx.x >> 5;
    int c = (i < N_NODES) ? cnt[i] : 0;
    int v = c;
#pragma unroll
    for (int o = 1; o < 32; o <<= 1) {
        int u = __shfl_up_sync(0xffffffffu, v, o);
        if (lane >= o) v += u;
    }
    if (lane == 31) wsum[wid] = v;
    __syncthreads();
    if (threadIdx.x < 8) {
        int w = wsum[threadIdx.x];
#pragma unroll
        for (int o = 1; o < 8; o <<= 1) {
            int u = __shfl_up_sync(0xffu, w, o);
            if (threadIdx.x >= o) w += u;
        }
        wsum[threadIdx.x] = w;
    }
    __syncthreads();
    int wpre = (wid == 0) ? 0 : wsum[wid - 1];
    int excl = v - c + wpre + pbase[blockIdx.x];
    if (i < N_NODES) {
        off[i] = excl;
        cur[i] = excl;
        dinv[i] = rsqrtf((float)(c + 1));
    }
    if (i == N_NODES - 1) off[N_NODES] = E_EDGES;
}

__global__ void fill_kernel(const int* __restrict__ src, const int* __restrict__ dst,
                            const float* __restrict__ dinv,
                            int* __restrict__ cur, int* __restrict__ csrc,
                            float* __restrict__ cw)
{
    int e = blockIdx.x * blockDim.x + threadIdx.x;
    if (e >= E_EDGES) return;
    int d = dst[e];
    int s = src[e];
    int pos = atomicAdd(&cur[d], 1);
    csrc[pos] = s;
    cw[pos] = dinv[s];
}

// ------- CSR aggregation + self loop + (affine+relu) --------
__global__ void __launch_bounds__(256) csr_agg_kernel(
    const float4* __restrict__ gw, const int* __restrict__ off,
    const int* __restrict__ csrc, const float* __restrict__ cw,
    const float* __restrict__ dinv,
    const float* __restrict__ aff_s, const float* __restrict__ aff_t,
    float4* __restrict__ outy)
{
    int row = blockIdx.x * 4 + (threadIdx.x >> 6);
    int c4 = threadIdx.x & 63;
    float di = dinv[row];
    float4 g = gw[(size_t)row * 64 + c4];
    float4 acc = make_float4(g.x * di, g.y * di, g.z * di, g.w * di);
    int e0 = off[row], e1 = off[row + 1];
    int j = e0;
    for (; j + 4 <= e1; j += 4) {
        int s0 = __ldg(&csrc[j]),     s1 = __ldg(&csrc[j + 1]);
        int s2 = __ldg(&csrc[j + 2]), s3 = __ldg(&csrc[j + 3]);
        float w0 = __ldg(&cw[j]),     w1 = __ldg(&cw[j + 1]);
        float w2 = __ldg(&cw[j + 2]), w3 = __ldg(&cw[j + 3]);
        float4 g0 = gw[(size_t)s0 * 64 + c4];
        float4 g1 = gw[(size_t)s1 * 64 + c4];
        float4 g2 = gw[(size_t)s2 * 64 + c4];
        float4 g3 = gw[(size_t)s3 * 64 + c4];
        acc.x = fmaf(w0, g0.x, fmaf(w1, g1.x, fmaf(w2, g2.x, fmaf(w3, g3.x, acc.x))));
        acc.y = fmaf(w0, g0.y, fmaf(w1, g1.y, fmaf(w2, g2.y, fmaf(w3, g3.y, acc.y))));
        acc.z = fmaf(w0, g0.z, fmaf(w1, g1.z, fmaf(w2, g2.z, fmaf(w3, g3.z, acc.z))));
        acc.w = fmaf(w0, g0.w, fmaf(w1, g1.w, fmaf(w2, g2.w, fmaf(w3, g3.w, acc.w))));
    }
    for (; j < e1; j++) {
        int s = __ldg(&csrc[j]);
        float w = __ldg(&cw[j]);
        float4 gv = gw[(size_t)s * 64 + c4];
        acc.x = fmaf(w, gv.x, acc.x);
        acc.y = fmaf(w, gv.y, acc.y);
        acc.z = fmaf(w, gv.z, acc.z);
        acc.w = fmaf(w, gv.w, acc.w);
    }
    acc.x *= di; acc.y *= di; acc.z *= di; acc.w *= di;
    if (aff_s) {
        float4 s4 = *reinterpret_cast<const float4*>(&aff_s[c4 * 4]);
        float4 t4 = *reinterpret_cast<const float4*>(&aff_t[c4 * 4]);
        acc.x = fmaxf(fmaf(acc.x, s4.x, t4.x), 0.f);
        acc.y = fmaxf(fmaf(acc.y, s4.y, t4.y), 0.f);
        acc.z = fmaxf(fmaf(acc.z, s4.z, t4.z), 0.f);
        acc.w = fmaxf(fmaf(acc.w, s4.w, t4.w), 0.f);
    }
    outy[(size_t)row * 64 + c4] = acc;
}

// ------- warp-per-row final ----------
__global__ void __launch_bounds__(256) final_w(
    const float4* __restrict__ agg, const float4* __restrict__ s4,
    const float4* __restrict__ t4, const int* __restrict__ batch,
    float4* __restrict__ out_g, float* __restrict__ out_pool)
{
    int row = blockIdx.x * 8 + (threadIdx.x >> 5);
    if (row >= N_NODES) return;
    int lane = threadIdx.x & 31;
    size_t ro = (size_t)row * 64;
    float4 a0 = agg[ro + lane], a1 = agg[ro + lane + 32];
    float4 ss0 = s4[lane], ss1 = s4[lane + 32], tt0 = t4[lane], tt1 = t4[lane + 32];
    float4 v0, v1;
    v0.x = a0.x * ss0.x + tt0.x; v0.y = a0.y * ss0.y + tt0.y;
    v0.z = a0.z * ss0.z + tt0.z; v0.w = a0.w * ss0.w + tt0.w;
    v1.x = a1.x * ss1.x + tt1.x; v1.y = a1.y * ss1.y + tt1.y;
    v1.z = a1.z * ss1.z + tt1.z; v1.w = a1.w * ss1.w + tt1.w;
    float ssn = warp_sum(sumsq8(v0, v1));
    float inv_n = 1.f / fmaxf(sqrtf(ssn), 1e-12f);
    v0.x *= inv_n; v0.y *= inv_n; v0.z *= inv_n; v0.w *= inv_n;
    v1.x *= inv_n; v1.y *= inv_n; v1.z *= inv_n; v1.w *= inv_n;
    out_g[ro + lane] = v0; out_g[ro + lane + 32] = v1;
    int grp = batch[row];
    float* p0 = &out_pool[(size_t)grp * HID + lane * 4];
    float* p1 = p0 + 128;
    asm volatile("red.global.add.v4.f32 [%0], {%1, %2, %3, %4};"
                 :: "l"(p0), "f"(v0.x), "f"(v0.y), "f"(v0.z), "f"(v0.w) : "memory");
    asm volatile("red.global.add.v4.f32 [%0], {%1, %2, %3, %4};"
                 :: "l"(p1), "f"(v1.x), "f"(v1.y), "f"(v1.z), "f"(v1.w) : "memory");
}

// ---------------- launcher ----------------
extern "C" void kernel_launch(void* const* d_in, const int* in_sizes, int n_in,
                              void* d_out, int out_size)
{
    const float* x       = (const float*)d_in[0];
    const int*   edge    = (const int*)  d_in[1];
    const int*   batch   = (const int*)  d_in[2];
    // d_in[3] = beta (unused)
    const float* fc_W    = (const float*)d_in[4];
    const float* fc_b    = (const float*)d_in[5];
    const float* ln0_g   = (const float*)d_in[6];
    const float* ln0_b   = (const float*)d_in[7];
    const float* Wq      = (const float*)d_in[8];
    const float* bq      = (const float*)d_in[9];
    const float* Wk      = (const float*)d_in[10];
    const float* bk      = (const float*)d_in[11];
    const float* Wv      = (const float*)d_in[12];
    const float* bv      = (const float*)d_in[13];
    const float* ln1_g   = (const float*)d_in[14];
    const float* ln1_b   = (const float*)d_in[15];
    const float* gcn_W0  = (const float*)d_in[16];
    const float* gcn_b0  = (const float*)d_in[17];
    const float* gcn_W   = (const float*)d_in[18];
    const float* gcn_b   = (const float*)d_in[19];
    const float* bn_g    = (const float*)d_in[20];
    const float* bn_b    = (const float*)d_in[21];
    const float* bn_mean = (const float*)d_in[22];
    const float* bn_var  = (const float*)d_in[23];

    const int* src = edge;
    const int* dst = edge + E_EDGES;

    float* out      = (float*)d_out;
    float* out_pool = out;
    float* out_g    = out + (size_t)G_GRP * HID;
    float* out_xt   = out_g + (size_t)N_NODES * HID;

    float* fbase = nullptr;
    int* ibase = nullptr;
    cudaGetSymbolAddress((void**)&fbase, d_scratch);
    cudaGetSymbolAddress((void**)&ibase, d_iscratch);

    float* p_h   = fbase;
    float* p_t   = fbase + (size_t)1 * NH;
    float* p_gw  = fbase + (size_t)2 * NH;
    float* p_y   = fbase + (size_t)3 * NH;

    float* p_sm   = fbase + (size_t)4 * NH;
    float* p_S    = p_sm;
    float* p_U    = p_S + HID * HID;
    float* p_Pk   = p_U + HID * HID;
    float* p_Pq   = p_Pk + HID * HID;
    float* p_kvs0 = p_Pq + HID * HID;
    float* p_hs   = p_kvs0 + HID * HID;
    float* p_scal = p_hs + HID;
    const int ZSM = 5 * HID * HID + HID + 16;

    float* p_kvsF  = p_scal + 16;
    float* p_wqp   = p_kvsF + HID * HID;
    float* p_Wc    = p_wqp + HID * HID;
    float* p_kssum = p_Wc + HID * HID;
    float* p_kk    = p_kssum + HID;
    float* p_wvhs  = p_kk + HID;
    float* p_kq    = p_wvhs + HID;
    float* p_bqp   = p_kq + HID;
    float* p_bc    = p_bqp + HID;
    float* p_w1    = p_bc + HID;
    float* p_dinv  = p_w1 + HID;
    float* p_cs    = p_dinv + N_NODES;
    float* p_ct    = p_cs + NUM_GC * HID;
    float* p_cw    = p_ct + NUM_GC * HID;

    int* p_cnt     = ibase;
    int* p_off     = p_cnt + N_NODES;
    int* p_cur     = p_off + N_NODES + 1;
    int* p_csrc    = p_cur + N_NODES;
    int* p_partial = p_csrc + E_EDGES;
    int* p_pbase   = p_partial + 256;

    const dim3 gg(HID / 128, (N_NODES + 127) / 128);
    const dim3 gg2(HID / 128, (N_NODES + 127) / 128, 2);
    const int THR = 256;

    // ===== CSR build + coefficients + zeroing =====
    bn_coef_kernel<<<(NUM_GC * HID + THR - 1) / THR, THR>>>(
        gcn_b0, gcn_b, bn_g, bn_b, bn_mean, bn_var, p_cs, p_ct);
    zero_int_kernel<<<(N_NODES + THR - 1) / THR, THR>>>(p_cnt, N_NODES);
    zero_kernel<<<(ZSM + THR - 1) / THR, THR>>>(p_sm, ZSM);
    count_kernel<<<(E_EDGES + THR - 1) / THR, THR>>>(dst, p_cnt);
    scan_partial_kernel<<<SCANBLK, THR>>>(p_cnt, p_partial);
    scan_base_kernel<<<1, THR>>>(p_partial, p_pbase);
    scan_fill_kernel<<<SCANBLK, THR>>>(p_cnt, p_pbase, p_off, p_cur, p_dinv);
    fill_kernel<<<(E_EDGES + THR - 1) / THR, THR>>>(src, dst, p_dinv, p_cur, p_csrc, p_cw);

    // ===== batched K=128 GEMMs: fc and gcn layer-0 (both A = x) =====
    sgemm128_b2<<<gg2, THR>>>(x, fc_W, gcn_W0, fc_b, nullptr,
                              p_t, p_gw, N_NODES, HID, F_IN);
    ln_relu_w<<<NROWBLK, THR>>>((const float4*)p_t, (const float4*)ln0_g,
                                (const float4*)ln0_b, (float4*)p_h);

    // ===== attention small-matrix algebra (no Q/V GEMMs) =====
    colsum_kernel<<<2048, THR>>>(p_h, p_hs);
    {   // S = H^T H (symmetric: upper tiles only + mirror)
        const int SPLITS = 64;
        const int rows_per_z = (N_NODES + SPLITS - 1) / SPLITS;
        atb_kernel<<<dim3(HID / 64, HID / 64, SPLITS), THR>>>(
            p_h, p_h, p_S, N_NODES, rows_per_z, 1);
    }
    symfill_kernel<<<HID, THR>>>(p_S);
    atb_kernel<<<dim3(4, 4, 1), THR>>>(p_S, Wv, p_U, HID, HID, 0);
    atb_kernel<<<dim3(4, 4, 1), THR>>>(p_S, Wk, p_Pk, HID, HID, 0);
    atb_kernel<<<dim3(4, 4, 1), THR>>>(p_S, Wq, p_Pq, HID, HID, 0);
    atb_kernel<<<dim3(4, 4, 1), THR>>>(Wk, p_U, p_kvs0, HID, HID, 0);
    matvec3_kernel<<<3, THR>>>(Wk, Wv, Wq, p_hs, p_kk, p_wvhs, p_kq);
    trace_kernel<<<1, THR>>>(p_Pk, Wk, bk, p_kk, &p_scal[1]);
    trace_kernel<<<1, THR>>>(p_Pq, Wq, bq, p_kq, &p_scal[0]);
    kvs_final_kernel<<<HID, THR>>>(p_kvs0, p_kk, p_wvhs, bk, bv, p_scal, p_kvsF, p_kssum);
    ab256_kernel<<<HID, THR>>>(Wq, p_kvsF, p_wqp);
    rowmv_kernel<<<HID / 8, THR>>>(Wq, p_kssum, p_w1);
    colmv_kernel<<<1, THR>>>(p_kvsF, bq, p_bqp);
    combine_kernel<<<HID + 1, THR>>>(p_wqp, Wv, p_bqp, bv, bq, p_kssum,
                                     p_scal, p_Wc, p_bc);

    // ===== t3 = H @ Wc + bc (the only attention N-GEMM) =====
    sgemm128<<<gg, THR>>>(p_h, p_Wc, p_bc, p_t, N_NODES, HID, HID);
    trans_epi_w<<<NROWBLK, THR>>>((const float4*)p_t, (const float4*)p_h,
                                  (const float4*)p_w1, p_scal,
                                  (const float4*)ln1_g, (const float4*)ln1_b,
                                  (float4*)out_xt);

    // ===== GCN layers =====
    csr_agg_kernel<<<N_NODES / 4, THR>>>(
        (const float4*)p_gw, p_off, p_csrc, p_cw, p_dinv,
        p_cs, p_ct, (float4*)p_y);

    for (int i = 1; i < NUM_GC; i++) {
        const float* W = gcn_W + (size_t)(i - 1) * HID * HID;
        sgemm128<<<gg, THR>>>(p_y, W, nullptr, p_gw, N_NODES, HID, HID);
        const float* as = (i < NUM_GC - 1) ? p_cs + (size_t)i * HID : nullptr;
        const float* at = (i < NUM_GC - 1) ? p_ct + (size_t)i * HID : nullptr;
        csr_agg_kernel<<<N_NODES / 4, THR>>>(
            (const float4*)p_gw, p_off, p_csrc, p_cw, p_dinv, as, at, (float4*)p_y);
    }

    // ===== outputs =====
    zero_kernel<<<(G_GRP * HID + THR - 1) / THR, THR>>>(out_pool, G_GRP * HID);
    final_w<<<NROWBLK, THR>>>((const float4*)p_y,
                              (const float4*)(p_cs + (size_t)(NUM_GC - 1) * HID),
                              (const float4*)(p_ct + (size_t)(NUM_GC - 1) * HID),
                              batch, (float4*)out_g, out_pool);
}

// round 14
// speedup vs baseline: 1.7577x; 1.0410x over previous
#include <cuda_runtime.h>
#include <cuda_bf16.h>
#include <cstdint>
#include <math.h>

// ---------------- problem constants ----------------
#define N_NODES 50000
#define E_EDGES 300000
#define F_IN    128
#define HID     256
#define G_GRP   1000
#define NUM_GC  5
#define NH      (N_NODES * HID)
#define NROWBLK ((N_NODES + 7) / 8)
#define SCANBLK ((N_NODES + 255) / 256)

typedef unsigned long long ull;

// ---------------- scratch ----------------
__device__ float d_scratch[4 * (size_t)NH + 1000000];
__device__ int d_iscratch[3 * N_NODES + 1 + E_EDGES + 512];

// ---------------- f32x2 helpers ----------------
__device__ __forceinline__ void ffma2(ull& d, ull a, ull b) {
    asm("fma.rn.f32x2 %0, %1, %2, %0;" : "+l"(d) : "l"(a), "l"(b));
}
__device__ __forceinline__ ull pack2(float x, float y) {
    ull r;
    asm("mov.b64 %0, {%1, %2};" : "=l"(r) : "f"(x), "f"(y));
    return r;
}
__device__ __forceinline__ void unpack2(float& lo, float& hi, ull v) {
    asm("mov.b64 {%0, %1}, %2;" : "=f"(lo), "=f"(hi) : "l"(v));
}

// ---------------- misc helpers ----------------
__device__ __forceinline__ float warp_sum(float v) {
#pragma unroll
    for (int o = 16; o; o >>= 1) v += __shfl_xor_sync(0xffffffffu, v, o);
    return v;
}
__device__ __forceinline__ float block_sum_256(float v, float* sh) {
    v = warp_sum(v);
    if ((threadIdx.x & 31) == 0) sh[threadIdx.x >> 5] = v;
    __syncthreads();
    if (threadIdx.x < 32) {
        float t = (threadIdx.x < 8) ? sh[threadIdx.x] : 0.f;
        t = warp_sum(t);
        if (threadIdx.x == 0) sh[8] = t;
    }
    __syncthreads();
    float r = sh[8];
    __syncthreads();
    return r;
}
__device__ __forceinline__ float sum8(float4 a, float4 b) {
    return a.x + a.y + a.z + a.w + b.x + b.y + b.z + b.w;
}
__device__ __forceinline__ float sumsq8(float4 a, float4 b) {
    return a.x*a.x + a.y*a.y + a.z*a.z + a.w*a.w
         + b.x*b.x + b.y*b.y + b.z*b.z + b.w*b.w;
}

__global__ void zero_kernel(float* __restrict__ p, int n) {
    int i = blockIdx.x * blockDim.x + threadIdx.x;
    if (i < n) p[i] = 0.f;
}
__global__ void zero_int_kernel(int* __restrict__ p, int n) {
    int i = blockIdx.x * blockDim.x + threadIdx.x;
    if (i < n) p[i] = 0;
}

// ============ 128x128x16 SGEMM (f32x2 FFMA2, plain-A layout) ============
__device__ __forceinline__ void sgemm_body(
    const float* __restrict__ A, const float* __restrict__ B,
    const float* __restrict__ bias, float* __restrict__ C,
    int M, int Nn, int K)
{
    __shared__ __align__(16) float As[2][16][128];
    __shared__ __align__(16) float Bs[2][16][128];

    const int tid = threadIdx.x;
    const int tx = tid & 15;
    const int ty = tid >> 4;
    const int row0 = blockIdx.y * 128;
    const int col0 = blockIdx.x * 128;

    const int KT = K >> 4;

    ull acc[8][4];
#pragma unroll
    for (int i = 0; i < 8; i++)
#pragma unroll
        for (int j = 0; j < 4; j++) acc[i][j] = 0ull;

    float4 av[2], bv[2];

#pragma unroll
    for (int p = 0; p < 2; p++) {
        int f4 = tid + p * 256;
        int arow = f4 >> 2, ak4 = (f4 & 3) * 4;
        int r = row0 + arow;
        float4 a;
        if (r < M) a = *reinterpret_cast<const float4*>(&A[(size_t)r * K + ak4]);
        else       a = make_float4(0.f, 0.f, 0.f, 0.f);
        As[0][ak4 + 0][arow] = a.x; As[0][ak4 + 1][arow] = a.y;
        As[0][ak4 + 2][arow] = a.z; As[0][ak4 + 3][arow] = a.w;
        int brow = f4 >> 5, bc4 = (f4 & 31) * 4;
        *reinterpret_cast<float4*>(&Bs[0][brow][bc4]) =
            *reinterpret_cast<const float4*>(&B[(size_t)brow * Nn + col0 + bc4]);
    }
    __syncthreads();

    for (int kt = 0; kt < KT; kt++) {
        const int buf = kt & 1;
        if (kt + 1 < KT) {
            const int k0 = (kt + 1) << 4;
#pragma unroll
            for (int p = 0; p < 2; p++) {
                int f4 = tid + p * 256;
                int arow = f4 >> 2, ak4 = (f4 & 3) * 4;
                int r = row0 + arow;
                if (r < M) av[p] = *reinterpret_cast<const float4*>(&A[(size_t)r * K + k0 + ak4]);
                else       av[p] = make_float4(0.f, 0.f, 0.f, 0.f);
                int brow = f4 >> 5, bc4 = (f4 & 31) * 4;
                bv[p] = *reinterpret_cast<const float4*>(&B[(size_t)(k0 + brow) * Nn + col0 + bc4]);
            }
        }

#pragma unroll
        for (int k = 0; k < 16; k++) {
            float4 a0 = *reinterpret_cast<const float4*>(&As[buf][k][ty * 4]);
            float4 a1 = *reinterpret_cast<const float4*>(&As[buf][k][64 + ty * 4]);
            ulonglong2 b0 = *reinterpret_cast<const ulonglong2*>(&Bs[buf][k][tx * 4]);
            ulonglong2 b1 = *reinterpret_cast<const ulonglong2*>(&Bs[buf][k][64 + tx * 4]);
            ull bp0 = b0.x, bp1 = b0.y, bp2 = b1.x, bp3 = b1.y;
            float aa[8] = {a0.x, a0.y, a0.z, a0.w, a1.x, a1.y, a1.z, a1.w};
#pragma unroll
            for (int i = 0; i < 8; i++) {
                ull ap = pack2(aa[i], aa[i]);
                ffma2(acc[i][0], ap, bp0);
                ffma2(acc[i][1], ap, bp1);
                ffma2(acc[i][2], ap, bp2);
                ffma2(acc[i][3], ap, bp3);
            }
        }

        if (kt + 1 < KT) {
            const int nb = buf ^ 1;
#pragma unroll
            for (int p = 0; p < 2; p++) {
                int f4 = tid + p * 256;
                int arow = f4 >> 2, ak4 = (f4 & 3) * 4;
                As[nb][ak4 + 0][arow] = av[p].x; As[nb][ak4 + 1][arow] = av[p].y;
                As[nb][ak4 + 2][arow] = av[p].z; As[nb][ak4 + 3][arow] = av[p].w;
                int brow = f4 >> 5, bc4 = (f4 & 31) * 4;
                *reinterpret_cast<float4*>(&Bs[nb][brow][bc4]) = bv[p];
            }
        }
        __syncthreads();
    }

    float4 b_lo = make_float4(0.f, 0.f, 0.f, 0.f), b_hi = b_lo;
    if (bias) {
        b_lo = *reinterpret_cast<const float4*>(&bias[col0 + tx * 4]);
        b_hi = *reinterpret_cast<const float4*>(&bias[col0 + 64 + tx * 4]);
    }
#pragma unroll
    for (int i = 0; i < 8; i++) {
        int row = row0 + ((i < 4) ? (ty * 4 + i) : (64 + ty * 4 + (i - 4)));
        if (row >= M) continue;
        float o0, o1, o2, o3, o4, o5, o6, o7;
        unpack2(o0, o1, acc[i][0]); unpack2(o2, o3, acc[i][1]);
        unpack2(o4, o5, acc[i][2]); unpack2(o6, o7, acc[i][3]);
        float4 lo = make_float4(o0 + b_lo.x, o1 + b_lo.y, o2 + b_lo.z, o3 + b_lo.w);
        float4 hi = make_float4(o4 + b_hi.x, o5 + b_hi.y, o6 + b_hi.z, o7 + b_hi.w);
        *reinterpret_cast<float4*>(&C[(size_t)row * Nn + col0 + tx * 4]) = lo;
        *reinterpret_cast<float4*>(&C[(size_t)row * Nn + col0 + 64 + tx * 4]) = hi;
    }
}

__global__ void __launch_bounds__(256, 2) sgemm128(
    const float* __restrict__ A, const float* __restrict__ B,
    const float* __restrict__ bias, float* __restrict__ C,
    int M, int Nn, int K)
{
    sgemm_body(A, B, bias, C, M, Nn, K);
}

// shared-A batch (fc + gcn0)
__global__ void __launch_bounds__(256, 2) sgemm128_b2(
    const float* __restrict__ A,
    const float* __restrict__ B0, const float* __restrict__ B1,
    const float* __restrict__ bias0, const float* __restrict__ bias1,
    float* __restrict__ C0, float* __restrict__ C1,
    int M, int Nn, int K)
{
    if (blockIdx.z == 0) sgemm_body(A, B0, bias0, C0, M, Nn, K);
    else                 sgemm_body(A, B1, bias1, C1, M, Nn, K);
}

// general 2-batch (independent GEMMs: t3 and GCN layer-1)
__global__ void __launch_bounds__(256, 2) sgemm128_g2(
    const float* __restrict__ A0, const float* __restrict__ B0,
    const float* __restrict__ bias0, float* __restrict__ C0,
    const float* __restrict__ A1, const float* __restrict__ B1,
    const float* __restrict__ bias1, float* __restrict__ C1,
    int M, int Nn, int K)
{
    if (blockIdx.z == 0) sgemm_body(A0, B0, bias0, C0, M, Nn, K);
    else                 sgemm_body(A1, B1, bias1, C1, M, Nn, K);
}

// ------ atb body: C[256,256] += A[L,256]^T @ B[L,256] (split-K atomics) ----
__device__ __forceinline__ void atb_body(
    const float* __restrict__ A, const float* __restrict__ B,
    float* __restrict__ C, int L, int lstart, int lend)
{
    __shared__ __align__(16) float As[32][128];
    __shared__ __align__(16) float Bs[32][64];

    const int tid = threadIdx.x;
    const int tx = tid & 15;
    const int ty = tid >> 4;
    const int ar0 = blockIdx.y * 64;
    const int bc0 = blockIdx.x * 64;

    ull acc[4][2];
#pragma unroll
    for (int i = 0; i < 4; i++) { acc[i][0] = 0ull; acc[i][1] = 0ull; }

    for (int l0 = lstart; l0 < lend; l0 += 32) {
#pragma unroll
        for (int p = 0; p < 2; p++) {
            int id = tid + p * 256;
            int lr = id >> 4;
            int c4 = (id & 15) * 4;
            int l = l0 + lr;
            float4 avv, bvv;
            if (l < lend) {
                avv = *reinterpret_cast<const float4*>(&A[(size_t)l * HID + ar0 + c4]);
                bvv = *reinterpret_cast<const float4*>(&B[(size_t)l * HID + bc0 + c4]);
            } else { avv = make_float4(0,0,0,0); bvv = avv; }
            float am[4] = {avv.x, avv.y, avv.z, avv.w};
#pragma unroll
            for (int m = 0; m < 4; m++)
                *reinterpret_cast<ull*>(&As[lr][2 * (c4 + m)]) = pack2(am[m], am[m]);
            *reinterpret_cast<float4*>(&Bs[lr][c4]) = bvv;
        }
        __syncthreads();

#pragma unroll
        for (int l = 0; l < 32; l++) {
            ulonglong2 a01 = *reinterpret_cast<const ulonglong2*>(&As[l][ty * 8]);
            ulonglong2 a23 = *reinterpret_cast<const ulonglong2*>(&As[l][ty * 8 + 4]);
            ulonglong2 bp  = *reinterpret_cast<const ulonglong2*>(&Bs[l][tx * 4]);
            ull ap[4] = {a01.x, a01.y, a23.x, a23.y};
#pragma unroll
            for (int i = 0; i < 4; i++) {
                ffma2(acc[i][0], ap[i], bp.x);
                ffma2(acc[i][1], ap[i], bp.y);
            }
        }
        __syncthreads();
    }

#pragma unroll
    for (int i = 0; i < 4; i++) {
        float c0, c1, c2, c3;
        unpack2(c0, c1, acc[i][0]); unpack2(c2, c3, acc[i][1]);
        float* base = &C[(size_t)(ar0 + ty * 4 + i) * HID + bc0 + tx * 4];
        atomicAdd(base + 0, c0); atomicAdd(base + 1, c1);
        atomicAdd(base + 2, c2); atomicAdd(base + 3, c3);
    }
}

// S = H^T H, split-K, symmetric (upper tiles only)
__global__ void __launch_bounds__(256) atb_sym_kernel(
    const float* __restrict__ A, float* __restrict__ C, int L, int rows_per_z)
{
    if (blockIdx.y > blockIdx.x) return;
    int lstart = blockIdx.z * rows_per_z;
    int lend = min(L, lstart + rows_per_z);
    atb_body(A, A, C, L, lstart, lend);
}

// batched small atb: z=0:S@Wv->U, z=1:S@Wk->Pk, z=2:S@Wq->Pq, z=3:Wk^T?? (no)
__global__ void __launch_bounds__(256) atb3_kernel(
    const float* __restrict__ S,
    const float* __restrict__ Wv, const float* __restrict__ Wk, const float* __restrict__ Wq,
    float* __restrict__ U, float* __restrict__ Pk, float* __restrict__ Pq)
{
    const float* B = (blockIdx.z == 0) ? Wv : (blockIdx.z == 1) ? Wk : Wq;
    float* C = (blockIdx.z == 0) ? U : (blockIdx.z == 1) ? Pk : Pq;
    atb_body(S, B, C, HID, 0, HID);
}

// single small atb: kvs0 = Wk^T U
__global__ void __launch_bounds__(256) atb1_kernel(
    const float* __restrict__ A, const float* __restrict__ B, float* __restrict__ C)
{
    atb_body(A, B, C, HID, 0, HID);
}

__global__ void symfill_kernel(float* __restrict__ C) {
    int i = blockIdx.x, j = threadIdx.x;
    if ((i >> 6) > (j >> 6))
        C[(size_t)i * HID + j] = C[(size_t)j * HID + i];
}

// ---------------- C[256,256] = A[256,256] @ B[256,256] ----------------
__global__ void __launch_bounds__(256) ab256_kernel(
    const float* __restrict__ A, const float* __restrict__ B, float* __restrict__ C)
{
    __shared__ float Ar[256];
    int i = blockIdx.x, j = threadIdx.x;
    Ar[j] = A[(size_t)i * HID + j];
    __syncthreads();
    float acc = 0.f;
    for (int l = 0; l < HID; l++) acc = fmaf(Ar[l], B[(size_t)l * HID + j], acc);
    C[(size_t)i * HID + j] = acc;
}

// ---------------- warp-per-row LN + relu ----------------
__global__ void __launch_bounds__(256) ln_relu_w(
    const float4* __restrict__ t, const float4* __restrict__ g,
    const float4* __restrict__ b, float4* __restrict__ out)
{
    int row = blockIdx.x * 8 + (threadIdx.x >> 5);
    if (row >= N_NODES) return;
    int lane = threadIdx.x & 31;
    const float4* tr = t + (size_t)row * 64;
    float4 v0 = tr[lane], v1 = tr[lane + 32];
    float s  = warp_sum(sum8(v0, v1));
    float s2 = warp_sum(sumsq8(v0, v1));
    float mean = s * (1.f / HID);
    float var  = s2 * (1.f / HID) - mean * mean;
    float r = rsqrtf(var + 1e-5f);
    float4 g0 = g[lane], g1 = g[lane + 32], b0 = b[lane], b1 = b[lane + 32];
    float4 o0, o1;
    o0.x = fmaxf((v0.x - mean) * r * g0.x + b0.x, 0.f);
    o0.y = fmaxf((v0.y - mean) * r * g0.y + b0.y, 0.f);
    o0.z = fmaxf((v0.z - mean) * r * g0.z + b0.z, 0.f);
    o0.w = fmaxf((v0.w - mean) * r * g0.w + b0.w, 0.f);
    o1.x = fmaxf((v1.x - mean) * r * g1.x + b1.x, 0.f);
    o1.y = fmaxf((v1.y - mean) * r * g1.y + b1.y, 0.f);
    o1.z = fmaxf((v1.z - mean) * r * g1.z + b1.z, 0.f);
    o1.w = fmaxf((v1.w - mean) * r * g1.w + b1.w, 0.f);
    float4* orow = out + (size_t)row * 64;
    orow[lane] = o0; orow[lane + 32] = o1;
}

// ---------------- column sum of h ----------------
__global__ void __launch_bounds__(256) colsum_kernel(
    const float* __restrict__ k, float* __restrict__ colsum)
{
    int c = threadIdx.x;
    float acc = 0.f;
    for (int r = blockIdx.x; r < N_NODES; r += gridDim.x)
        acc += k[(size_t)r * HID + c];
    atomicAdd(&colsum[c], acc);
}

// ---------------- 3-way column matvec ----------------
__global__ void matvec3_kernel(const float* __restrict__ Wk, const float* __restrict__ Wv,
                               const float* __restrict__ Wq, const float* __restrict__ hs,
                               float* __restrict__ kk, float* __restrict__ wvhs,
                               float* __restrict__ kq)
{
    const float* W = (blockIdx.x == 0) ? Wk : (blockIdx.x == 1) ? Wv : Wq;
    float* o = (blockIdx.x == 0) ? kk : (blockIdx.x == 1) ? wvhs : kq;
    int c = threadIdx.x;
    float a = 0.f;
    for (int l = 0; l < HID; l++) a = fmaf(W[(size_t)l * HID + c], hs[l], a);
    o[c] = a;
}

// -------- batched trace: z=0 -> kss (Pk,Wk,bk,kk), z=1 -> qss (Pq,Wq,bq,kq) -
__global__ void __launch_bounds__(256) trace2_kernel(
    const float* __restrict__ Pk, const float* __restrict__ Wk,
    const float* __restrict__ bk, const float* __restrict__ kk,
    const float* __restrict__ Pq, const float* __restrict__ Wq,
    const float* __restrict__ bq, const float* __restrict__ kq,
    float* __restrict__ scal)
{
    __shared__ float sh[16];
    const float* P = blockIdx.x ? Pq : Pk;
    const float* W = blockIdx.x ? Wq : Wk;
    const float* b = blockIdx.x ? bq : bk;
    const float* wv = blockIdx.x ? kq : kk;
    float s = 0.f;
    for (int i = threadIdx.x; i < HID * HID; i += 256) s = fmaf(P[i], W[i], s);
    float bc_ = b[threadIdx.x];
    s += 2.f * bc_ * wv[threadIdx.x] + (float)N_NODES * bc_ * bc_;
    float tot = block_sum_256(s, sh);
    if (threadIdx.x == 0) scal[blockIdx.x ? 0 : 1] = tot;
}

// ---------------- kvs finalize (+ kssum) ----------------
__global__ void kvs_final_kernel(const float* __restrict__ kvs0,
                                 const float* __restrict__ kk, const float* __restrict__ wvhs,
                                 const float* __restrict__ bk, const float* __restrict__ bv,
                                 const float* __restrict__ scal,
                                 float* __restrict__ kvsF, float* __restrict__ kssum)
{
    int i = blockIdx.x, j = threadIdx.x;
    float sk = rsqrtf(scal[1]);
    float bki = bk[i];
    float val = kvs0[(size_t)i * HID + j] + kk[i] * bv[j] + bki * wvhs[j]
              + (float)N_NODES * bki * bv[j];
    kvsF[(size_t)i * HID + j] = val * sk;
    if (j == 0) kssum[i] = (kk[i] + (float)N_NODES * bki) * sk;
}

// -------- w1 = Wq @ kssum, warp per row --------
__global__ void __launch_bounds__(256) rowmv_kernel(
    const float* __restrict__ Wq, const float* __restrict__ kssum,
    float* __restrict__ w1)
{
    int row = blockIdx.x * 8 + (threadIdx.x >> 5);
    int lane = threadIdx.x & 31;
    const float4* wr = reinterpret_cast<const float4*>(&Wq[(size_t)row * HID]);
    const float4* ks = reinterpret_cast<const float4*>(kssum);
    float4 a0 = wr[lane], a1 = wr[lane + 32];
    float4 k0 = __ldg(&ks[lane]), k1 = __ldg(&ks[lane + 32]);
    float d = a0.x*k0.x + a0.y*k0.y + a0.z*k0.z + a0.w*k0.w
            + a1.x*k1.x + a1.y*k1.y + a1.z*k1.z + a1.w*k1.w;
    d = warp_sum(d);
    if (lane == 0) w1[row] = d;
}

// -------- bq' = kvsF^T bq --------
__global__ void __launch_bounds__(256) colmv_kernel(
    const float* __restrict__ kvsF, const float* __restrict__ bq,
    float* __restrict__ bqp)
{
    __shared__ float bs[256];
    int j = threadIdx.x;
    bs[j] = bq[j];
    __syncthreads();
    float a = 0.f;
    for (int l = 0; l < HID; l++) a = fmaf(kvsF[(size_t)l * HID + j], bs[l], a);
    bqp[j] = a;
}

// -------- Wc = rq*Wq' + n*Wv ; bc = rq*bq' + n*bv ; scal[2] = bq.kssum -----
__global__ void __launch_bounds__(256) combine_kernel(
    const float* __restrict__ wqp, const float* __restrict__ Wv,
    const float* __restrict__ bqp, const float* __restrict__ bv,
    const float* __restrict__ bq, const float* __restrict__ kssum,
    float* __restrict__ scal, float* __restrict__ Wc, float* __restrict__ bc)
{
    __shared__ float sh[16];
    float rq = rsqrtf(scal[0]);
    int b = blockIdx.x, j = threadIdx.x;
    if (b < 256) {
        size_t o = (size_t)b * HID + j;
        Wc[o] = rq * wqp[o] + (float)N_NODES * Wv[o];
    } else {
        bc[j] = rq * bqp[j] + (float)N_NODES * bv[j];
        float s = block_sum_256(bq[j] * kssum[j], sh);
        if (j == 0) scal[2] = s;
    }
}

// ---------------- warp-per-row TransConv epilogue ----------------
__global__ void __launch_bounds__(256) trans_epi_w(
    const float4* __restrict__ t3, const float4* __restrict__ h,
    const float4* __restrict__ w1, const float* __restrict__ scal,
    const float4* __restrict__ g1, const float4* __restrict__ b1,
    float4* __restrict__ out_xt)
{
    int row = blockIdx.x * 8 + (threadIdx.x >> 5);
    if (row >= N_NODES) return;
    int lane = threadIdx.x & 31;
    size_t ro = (size_t)row * 64;
    float4 h0 = h[ro + lane], h1v = h[ro + lane + 32];
    float4 wa = w1[lane], wb = w1[lane + 32];
    float dotl = h0.x*wa.x + h0.y*wa.y + h0.z*wa.z + h0.w*wa.w
               + h1v.x*wb.x + h1v.y*wb.y + h1v.z*wb.z + h1v.w*wb.w;
    float dot = warp_sum(dotl);
    float rq = rsqrtf(scal[0]);
    float denom = rq * (dot + scal[2]) + (float)N_NODES;
    float hi = 0.5f / denom;
    float4 t0 = t3[ro + lane], t1 = t3[ro + lane + 32];
    float4 a0, a1;
    a0.x = t0.x * hi + 0.5f * h0.x;  a0.y = t0.y * hi + 0.5f * h0.y;
    a0.z = t0.z * hi + 0.5f * h0.z;  a0.w = t0.w * hi + 0.5f * h0.w;
    a1.x = t1.x * hi + 0.5f * h1v.x; a1.y = t1.y * hi + 0.5f * h1v.y;
    a1.z = t1.z * hi + 0.5f * h1v.z; a1.w = t1.w * hi + 0.5f * h1v.w;
    float s  = warp_sum(sum8(a0, a1));
    float s2 = warp_sum(sumsq8(a0, a1));
    float mean = s * (1.f / HID);
    float var  = s2 * (1.f / HID) - mean * mean;
    float r = rsqrtf(var + 1e-5f);
    float4 gg0 = g1[lane], gg1 = g1[lane + 32], bb0 = b1[lane], bb1 = b1[lane + 32];
    float4 y0, y1;
    y0.x = fmaxf((a0.x - mean) * r * gg0.x + bb0.x, 0.f);
    y0.y = fmaxf((a0.y - mean) * r * gg0.y + bb0.y, 0.f);
    y0.z = fmaxf((a0.z - mean) * r * gg0.z + bb0.z, 0.f);
    y0.w = fmaxf((a0.w - mean) * r * gg0.w + bb0.w, 0.f);
    y1.x = fmaxf((a1.x - mean) * r * gg1.x + bb1.x, 0.f);
    y1.y = fmaxf((a1.y - mean) * r * gg1.y + bb1.y, 0.f);
    y1.z = fmaxf((a1.z - mean) * r * gg1.z + bb1.z, 0.f);
    y1.w = fmaxf((a1.w - mean) * r * gg1.w + bb1.w, 0.f);
    float ssn = warp_sum(sumsq8(y0, y1));
    float inv_n = 1.f / fmaxf(sqrtf(ssn), 1e-12f);
    y0.x *= inv_n; y0.y *= inv_n; y0.z *= inv_n; y0.w *= inv_n;
    y1.x *= inv_n; y1.y *= inv_n; y1.z *= inv_n; y1.w *= inv_n;
    out_xt[ro + lane] = y0; out_xt[ro + lane + 32] = y1;
}

// ---------------- BN affine coefficients ----------------
__global__ void bn_coef_kernel(const float* __restrict__ gcn_b0, const float* __restrict__ gcn_b,
                               const float* __restrict__ bn_g, const float* __restrict__ bn_b,
                               const float* __restrict__ bn_mean, const float* __restrict__ bn_var,
                               float* __restrict__ coef_s, float* __restrict__ coef_t)
{
    int idx = blockIdx.x * blockDim.x + threadIdx.x;
    if (idx >= NUM_GC * HID) return;
    int layer = idx >> 8, c = idx & 255;
    float b = (layer == 0) ? gcn_b0[c] : gcn_b[(size_t)(layer - 1) * HID + c];
    float rs = rsqrtf(bn_var[idx] + 1e-5f);
    float sv = bn_g[idx] * rs;
    coef_s[idx] = sv;
    coef_t[idx] = (b - bn_mean[idx]) * sv + bn_b[idx];
}

// ---------------- CSR build (parallel scan) ----------------
__global__ void count_kernel(const int* __restrict__ dst, int* __restrict__ cnt) {
    int e = blockIdx.x * blockDim.x + threadIdx.x;
    if (e < E_EDGES) atomicAdd(&cnt[dst[e]], 1);
}

__global__ void __launch_bounds__(256) scan_partial_kernel(
    const int* __restrict__ cnt, int* __restrict__ partial)
{
    __shared__ int sh[8];
    int i = blockIdx.x * 256 + threadIdx.x;
    int v = (i < N_NODES) ? cnt[i] : 0;
#pragma unroll
    for (int o = 16; o; o >>= 1) v += __shfl_xor_sync(0xffffffffu, v, o);
    if ((threadIdx.x & 31) == 0) sh[threadIdx.x >> 5] = v;
    __syncthreads();
    if (threadIdx.x < 8) {
        int t = sh[threadIdx.x];
#pragma unroll
        for (int o = 4; o; o >>= 1) t += __shfl_xor_sync(0xffu, t, o);
        if (threadIdx.x == 0) partial[blockIdx.x] = t;
    }
}

__global__ void __launch_bounds__(256) scan_base_kernel(
    const int* __restrict__ partial, int* __restrict__ pbase)
{
    __shared__ int sh[256];
    int t = threadIdx.x;
    int v = (t < SCANBLK) ? partial[t] : 0;
    sh[t] = v;
    __syncthreads();
#pragma unroll
    for (int d = 1; d < 256; d <<= 1) {
        int u = (t >= d) ? sh[t - d] : 0;
        __syncthreads();
        sh[t] += u;
        __syncthreads();
    }
    pbase[t] = sh[t] - v;
}

__global__ void __launch_bounds__(256) scan_fill_kernel(
    const int* __restrict__ cnt, const int* __restrict__ pbase,
    int* __restrict__ off, int* __restrict__ cur, float* __restrict__ dinv)
{
    __shared__ int wsum[8];
    int i = blockIdx.x * 256 + threadIdx.x;
    int lane = threadIdx.x & 31, wid = threadIdx.x >> 5;
    int c = (i < N_NODES) ? cnt[i] : 0;
    int v = c;
#pragma unroll
    for (int o = 1; o < 32; o <<= 1) {
        int u = __shfl_up_sync(0xffffffffu, v, o);
        if (lane >= o) v += u;
    }
    if (lane == 31) wsum[wid] = v;
    __syncthreads();
    if (threadIdx.x < 8) {
        int w = wsum[threadIdx.x];
#pragma unroll
        for (int o = 1; o < 8; o <<= 1) {
            int u = __shfl_up_sync(0xffu, w, o);
            if (threadIdx.x >= o) w += u;
        }
        wsum[threadIdx.x] = w;
    }
    __syncthreads();
    int wpre = (wid == 0) ? 0 : wsum[wid - 1];
    int excl = v - c + wpre + pbase[blockIdx.x];
    if (i < N_NODES) {
        off[i] = excl;
        cur[i] = excl;
        dinv[i] = rsqrtf((float)(c + 1));
    }
    if (i == N_NODES - 1) off[N_NODES] = E_EDGES;
}

__global__ void fill_kernel(const int* __restrict__ src, const int* __restrict__ dst,
                            const float* __restrict__ dinv,
                            int* __restrict__ cur, int* __restrict__ csrc,
                            float* __restrict__ cw)
{
    int e = blockIdx.x * blockDim.x + threadIdx.x;
    if (e >= E_EDGES) return;
    int d = dst[e];
    int s = src[e];
    int pos = atomicAdd(&cur[d], 1);
    csrc[pos] = s;
    cw[pos] = dinv[s];
}

// ------- CSR aggregation core --------
__device__ __forceinline__ float4 csr_agg_row(
    const float4* __restrict__ gw, const int* __restrict__ off,
    const int* __restrict__ csrc, const float* __restrict__ cw,
    float di, int row, int c4)
{
    float4 g = gw[(size_t)row * 64 + c4];
    float4 acc = make_float4(g.x * di, g.y * di, g.z * di, g.w * di);
    int e0 = off[row], e1 = off[row + 1];
    int j = e0;
    for (; j + 4 <= e1; j += 4) {
        int s0 = __ldg(&csrc[j]),     s1 = __ldg(&csrc[j + 1]);
        int s2 = __ldg(&csrc[j + 2]), s3 = __ldg(&csrc[j + 3]);
        float w0 = __ldg(&cw[j]),     w1 = __ldg(&cw[j + 1]);
        float w2 = __ldg(&cw[j + 2]), w3 = __ldg(&cw[j + 3]);
        float4 g0 = gw[(size_t)s0 * 64 + c4];
        float4 g1 = gw[(size_t)s1 * 64 + c4];
        float4 g2 = gw[(size_t)s2 * 64 + c4];
        float4 g3 = gw[(size_t)s3 * 64 + c4];
        acc.x = fmaf(w0, g0.x, fmaf(w1, g1.x, fmaf(w2, g2.x, fmaf(w3, g3.x, acc.x))));
        acc.y = fmaf(w0, g0.y, fmaf(w1, g1.y, fmaf(w2, g2.y, fmaf(w3, g3.y, acc.y))));
        acc.z = fmaf(w0, g0.z, fmaf(w1, g1.z, fmaf(w2, g2.z, fmaf(w3, g3.z, acc.z))));
        acc.w = fmaf(w0, g0.w, fmaf(w1, g1.w, fmaf(w2, g2.w, fmaf(w3, g3.w, acc.w))));
    }
    for (; j < e1; j++) {
        int s = __ldg(&csrc[j]);
        float w = __ldg(&cw[j]);
        float4 gv = gw[(size_t)s * 64 + c4];
        acc.x = fmaf(w, gv.x, acc.x);
        acc.y = fmaf(w, gv.y, acc.y);
        acc.z = fmaf(w, gv.z, acc.z);
        acc.w = fmaf(w, gv.w, acc.w);
    }
    acc.x *= di; acc.y *= di; acc.z *= di; acc.w *= di;
    return acc;
}

// mid layers: aggregate + affine(+relu) for next layer input
__global__ void __launch_bounds__(256) csr_agg_kernel(
    const float4* __restrict__ gw, const int* __restrict__ off,
    const int* __restrict__ csrc, const float* __restrict__ cw,
    const float* __restrict__ dinv,
    const float* __restrict__ aff_s, const float* __restrict__ aff_t,
    float4* __restrict__ outy)
{
    int row = blockIdx.x * 4 + (threadIdx.x >> 6);
    int c4 = threadIdx.x & 63;
    float di = dinv[row];
    float4 acc = csr_agg_row(gw, off, csrc, cw, di, row, c4);
    float4 s4 = *reinterpret_cast<const float4*>(&aff_s[c4 * 4]);
    float4 t4 = *reinterpret_cast<const float4*>(&aff_t[c4 * 4]);
    acc.x = fmaxf(fmaf(acc.x, s4.x, t4.x), 0.f);
    acc.y = fmaxf(fmaf(acc.y, s4.y, t4.y), 0.f);
    acc.z = fmaxf(fmaf(acc.z, s4.z, t4.z), 0.f);
    acc.w = fmaxf(fmaf(acc.w, s4.w, t4.w), 0.f);
    outy[(size_t)row * 64 + c4] = acc;
}

// last layer: aggregate + affine (no relu) + l2-normalize + out_g + pool
__global__ void __launch_bounds__(256) csr_agg_final(
    const float4* __restrict__ gw, const int* __restrict__ off,
    const int* __restrict__ csrc, const float* __restrict__ cw,
    const float* __restrict__ dinv,
    const float* __restrict__ aff_s, const float* __restrict__ aff_t,
    const int* __restrict__ batch,
    float4* __restrict__ out_g, float* __restrict__ out_pool)
{
    __shared__ float part[8];   // per-warp sumsq partials (8 warps)
    int sub = threadIdx.x >> 6;              // 0..3 (row within block)
    int row = blockIdx.x * 4 + sub;
    int c4 = threadIdx.x & 63;
    float di = dinv[row];
    float4 acc = csr_agg_row(gw, off, csrc, cw, di, row, c4);
    float4 s4 = *reinterpret_cast<const float4*>(&aff_s[c4 * 4]);
    float4 t4 = *reinterpret_cast<const float4*>(&aff_t[c4 * 4]);
    acc.x = fmaf(acc.x, s4.x, t4.x);
    acc.y = fmaf(acc.y, s4.y, t4.y);
    acc.z = fmaf(acc.z, s4.z, t4.z);
    acc.w = fmaf(acc.w, s4.w, t4.w);
    float ss = acc.x*acc.x + acc.y*acc.y + acc.z*acc.z + acc.w*acc.w;
    ss = warp_sum(ss);
    if ((threadIdx.x & 31) == 0) part[threadIdx.x >> 5] = ss;
    __syncthreads();
    float tot = part[sub * 2] + part[sub * 2 + 1];
    float inv_n = 1.f / fmaxf(sqrtf(tot), 1e-12f);
    acc.x *= inv_n; acc.y *= inv_n; acc.z *= inv_n; acc.w *= inv_n;
    out_g[(size_t)row * 64 + c4] = acc;
    int grp = __ldg(&batch[row]);
    float* p = &out_pool[(size_t)grp * HID + c4 * 4];
    asm volatile("red.global.add.v4.f32 [%0], {%1, %2, %3, %4};"
                 :: "l"(p), "f"(acc.x), "f"(acc.y), "f"(acc.z), "f"(acc.w) : "memory");
}

// ---------------- launcher ----------------
extern "C" void kernel_launch(void* const* d_in, const int* in_sizes, int n_in,
                              void* d_out, int out_size)
{
    const float* x       = (const float*)d_in[0];
    const int*   edge    = (const int*)  d_in[1];
    const int*   batch   = (const int*)  d_in[2];
    // d_in[3] = beta (unused)
    const float* fc_W    = (const float*)d_in[4];
    const float* fc_b    = (const float*)d_in[5];
    const float* ln0_g   = (const float*)d_in[6];
    const float* ln0_b   = (const float*)d_in[7];
    const float* Wq      = (const float*)d_in[8];
    const float* bq      = (const float*)d_in[9];
    const float* Wk      = (const float*)d_in[10];
    const float* bk      = (const float*)d_in[11];
    const float* Wv      = (const float*)d_in[12];
    const float* bv      = (const float*)d_in[13];
    const float* ln1_g   = (const float*)d_in[14];
    const float* ln1_b   = (const float*)d_in[15];
    const float* gcn_W0  = (const float*)d_in[16];
    const float* gcn_b0  = (const float*)d_in[17];
    const float* gcn_W   = (const float*)d_in[18];
    const float* gcn_b   = (const float*)d_in[19];
    const float* bn_g    = (const float*)d_in[20];
    const float* bn_b    = (const float*)d_in[21];
    const float* bn_mean = (const float*)d_in[22];
    const float* bn_var  = (const float*)d_in[23];

    const int* src = edge;
    const int* dst = edge + E_EDGES;

    float* out      = (float*)d_out;
    float* out_pool = out;
    float* out_g    = out + (size_t)G_GRP * HID;
    float* out_xt   = out_g + (size_t)N_NODES * HID;

    float* fbase = nullptr;
    int* ibase = nullptr;
    cudaGetSymbolAddress((void**)&fbase, d_scratch);
    cudaGetSymbolAddress((void**)&ibase, d_iscratch);

    float* p_h   = fbase;
    float* p_t   = fbase + (size_t)1 * NH;
    float* p_gw  = fbase + (size_t)2 * NH;
    float* p_y   = fbase + (size_t)3 * NH;

    float* p_sm   = fbase + (size_t)4 * NH;
    float* p_S    = p_sm;
    float* p_U    = p_S + HID * HID;
    float* p_Pk   = p_U + HID * HID;
    float* p_Pq   = p_Pk + HID * HID;
    float* p_kvs0 = p_Pq + HID * HID;
    float* p_hs   = p_kvs0 + HID * HID;
    float* p_scal = p_hs + HID;
    const int ZSM = 5 * HID * HID + HID + 16;

    float* p_kvsF  = p_scal + 16;
    float* p_wqp   = p_kvsF + HID * HID;
    float* p_Wc    = p_wqp + HID * HID;
    float* p_kssum = p_Wc + HID * HID;
    float* p_kk    = p_kssum + HID;
    float* p_wvhs  = p_kk + HID;
    float* p_kq    = p_wvhs + HID;
    float* p_bqp   = p_kq + HID;
    float* p_bc    = p_bqp + HID;
    float* p_w1    = p_bc + HID;
    float* p_dinv  = p_w1 + HID;
    float* p_cs    = p_dinv + N_NODES;
    float* p_ct    = p_cs + NUM_GC * HID;
    float* p_cw    = p_ct + NUM_GC * HID;

    int* p_cnt     = ibase;
    int* p_off     = p_cnt + N_NODES;
    int* p_cur     = p_off + N_NODES + 1;
    int* p_csrc    = p_cur + N_NODES;
    int* p_partial = p_csrc + E_EDGES;
    int* p_pbase   = p_partial + 256;

    const dim3 gg(HID / 128, (N_NODES + 127) / 128);
    const dim3 gg2(HID / 128, (N_NODES + 127) / 128, 2);
    const int THR = 256;

    // ===== CSR build + coefficients + zeroing =====
    bn_coef_kernel<<<(NUM_GC * HID + THR - 1) / THR, THR>>>(
        gcn_b0, gcn_b, bn_g, bn_b, bn_mean, bn_var, p_cs, p_ct);
    zero_int_kernel<<<(N_NODES + THR - 1) / THR, THR>>>(p_cnt, N_NODES);
    zero_kernel<<<(ZSM + THR - 1) / THR, THR>>>(p_sm, ZSM);
    zero_kernel<<<(G_GRP * HID + THR - 1) / THR, THR>>>(out_pool, G_GRP * HID);
    count_kernel<<<(E_EDGES + THR - 1) / THR, THR>>>(dst, p_cnt);
    scan_partial_kernel<<<SCANBLK, THR>>>(p_cnt, p_partial);
    scan_base_kernel<<<1, THR>>>(p_partial, p_pbase);
    scan_fill_kernel<<<SCANBLK, THR>>>(p_cnt, p_pbase, p_off, p_cur, p_dinv);
    fill_kernel<<<(E_EDGES + THR - 1) / THR, THR>>>(src, dst, p_dinv, p_cur, p_csrc, p_cw);

    // ===== batched K=128 GEMMs: fc and gcn layer-0 (both A = x) =====
    sgemm128_b2<<<gg2, THR>>>(x, fc_W, gcn_W0, fc_b, nullptr,
                              p_t, p_gw, N_NODES, HID, F_IN);
    ln_relu_w<<<NROWBLK, THR>>>((const float4*)p_t, (const float4*)ln0_g,
                                (const float4*)ln0_b, (float4*)p_h);

    // ===== csr_agg layer 0 (independent of attention chain) =====
    csr_agg_kernel<<<N_NODES / 4, THR>>>(
        (const float4*)p_gw, p_off, p_csrc, p_cw, p_dinv,
        p_cs, p_ct, (float4*)p_y);

    // ===== attention small-matrix algebra =====
    colsum_kernel<<<2048, THR>>>(p_h, p_hs);
    {
        const int SPLITS = 64;
        const int rows_per_z = (N_NODES + SPLITS - 1) / SPLITS;
        atb_sym_kernel<<<dim3(HID / 64, HID / 64, SPLITS), THR>>>(p_h, p_S, N_NODES, rows_per_z);
    }
    symfill_kernel<<<HID, THR>>>(p_S);
    atb3_kernel<<<dim3(4, 4, 3), THR>>>(p_S, Wv, Wk, Wq, p_U, p_Pk, p_Pq);
    atb1_kernel<<<dim3(4, 4), THR>>>(Wk, p_U, p_kvs0);
    matvec3_kernel<<<3, THR>>>(Wk, Wv, Wq, p_hs, p_kk, p_wvhs, p_kq);
    trace2_kernel<<<2, THR>>>(p_Pk, Wk, bk, p_kk, p_Pq, Wq, bq, p_kq, p_scal);
    kvs_final_kernel<<<HID, THR>>>(p_kvs0, p_kk, p_wvhs, bk, bv, p_scal, p_kvsF, p_kssum);
    ab256_kernel<<<HID, THR>>>(Wq, p_kvsF, p_wqp);
    rowmv_kernel<<<HID / 8, THR>>>(Wq, p_kssum, p_w1);
    colmv_kernel<<<1, THR>>>(p_kvsF, bq, p_bqp);
    combine_kernel<<<HID + 1, THR>>>(p_wqp, Wv, p_bqp, bv, bq, p_kssum,
                                     p_scal, p_Wc, p_bc);

    // ===== batched independent GEMMs: t3 = H@Wc+bc AND GCN layer-1 =====
    sgemm128_g2<<<gg2, THR>>>(p_h, p_Wc, p_bc, p_t,
                              p_y, gcn_W, nullptr, p_gw,
                              N_NODES, HID, HID);
    trans_epi_w<<<NROWBLK, THR>>>((const float4*)p_t, (const float4*)p_h,
                                  (const float4*)p_w1, p_scal,
                                  (const float4*)ln1_g, (const float4*)ln1_b,
                                  (float4*)out_xt);

    // ===== remaining GCN layers =====
    csr_agg_kernel<<<N_NODES / 4, THR>>>(
        (const float4*)p_gw, p_off, p_csrc, p_cw, p_dinv,
        p_cs + 1 * HID, p_ct + 1 * HID, (float4*)p_y);

    for (int i = 2; i < NUM_GC; i++) {
        const float* W = gcn_W + (size_t)(i - 1) * HID * HID;
        sgemm128<<<gg, THR>>>(p_y, W, nullptr, p_gw, N_NODES, HID, HID);
        if (i < NUM_GC - 1) {
            csr_agg_kernel<<<N_NODES / 4, THR>>>(
                (const float4*)p_gw, p_off, p_csrc, p_cw, p_dinv,
                p_cs + (size_t)i * HID, p_ct + (size_t)i * HID, (float4*)p_y);
        } else {
            // layer 4: fused aggregate + affine + l2 + out_g + pool
            csr_agg_final<<<N_NODES / 4, THR>>>(
                (const float4*)p_gw, p_off, p_csrc, p_cw, p_dinv,
                p_cs + (size_t)(NUM_GC - 1) * HID, p_ct + (size_t)(NUM_GC - 1) * HID,
                batch, (float4*)out_g, out_pool);
        }
    }
}

// round 16
// speedup vs baseline: 1.7649x; 1.0041x over previous
#include <cuda_runtime.h>
#include <cuda_bf16.h>
#include <cstdint>
#include <math.h>

// ---------------- problem constants ----------------
#define N_NODES 50000
#define E_EDGES 300000
#define F_IN    128
#define HID     256
#define G_GRP   1000
#define NUM_GC  5
#define NH      (N_NODES * HID)
#define NROWBLK ((N_NODES + 7) / 8)
#define SCANBLK ((N_NODES + 255) / 256)

typedef unsigned long long ull;

// ---------------- scratch ----------------
__device__ float d_scratch[4 * (size_t)NH + 1000000];
__device__ int d_iscratch[3 * N_NODES + 1 + E_EDGES + 512];

// ---------------- f32x2 helpers ----------------
__device__ __forceinline__ void ffma2(ull& d, ull a, ull b) {
    asm("fma.rn.f32x2 %0, %1, %2, %0;" : "+l"(d) : "l"(a), "l"(b));
}
__device__ __forceinline__ ull pack2(float x, float y) {
    ull r;
    asm("mov.b64 %0, {%1, %2};" : "=l"(r) : "f"(x), "f"(y));
    return r;
}
__device__ __forceinline__ void unpack2(float& lo, float& hi, ull v) {
    asm("mov.b64 {%0, %1}, %2;" : "=f"(lo), "=f"(hi) : "l"(v));
}

// ---------------- misc helpers ----------------
__device__ __forceinline__ float warp_sum(float v) {
#pragma unroll
    for (int o = 16; o; o >>= 1) v += __shfl_xor_sync(0xffffffffu, v, o);
    return v;
}
__device__ __forceinline__ float block_sum_256(float v, float* sh) {
    v = warp_sum(v);
    if ((threadIdx.x & 31) == 0) sh[threadIdx.x >> 5] = v;
    __syncthreads();
    if (threadIdx.x < 32) {
        float t = (threadIdx.x < 8) ? sh[threadIdx.x] : 0.f;
        t = warp_sum(t);
        if (threadIdx.x == 0) sh[8] = t;
    }
    __syncthreads();
    float r = sh[8];
    __syncthreads();
    return r;
}
__device__ __forceinline__ float sum8(float4 a, float4 b) {
    return a.x + a.y + a.z + a.w + b.x + b.y + b.z + b.w;
}
__device__ __forceinline__ float sumsq8(float4 a, float4 b) {
    return a.x*a.x + a.y*a.y + a.z*a.z + a.w*a.w
         + b.x*b.x + b.y*b.y + b.z*b.z + b.w*b.w;
}

// combined init: zero cnt (ints), out_pool, small region
__global__ void init_kernel(int* __restrict__ cnt, int n1,
                            float* __restrict__ pool, int n2,
                            float* __restrict__ sm, int n3)
{
    int i = blockIdx.x * blockDim.x + threadIdx.x;
    if (i < n1) cnt[i] = 0;
    if (i < n2) pool[i] = 0.f;
    if (i < n3) sm[i] = 0.f;
}

// ============ 128x128x16 SGEMM (f32x2 FFMA2, plain-A layout) ============
__device__ __forceinline__ void sgemm_body(
    const float* __restrict__ A, const float* __restrict__ B,
    const float* __restrict__ bias, float* __restrict__ C,
    int M, int Nn, int K)
{
    __shared__ __align__(16) float As[2][16][128];
    __shared__ __align__(16) float Bs[2][16][128];

    const int tid = threadIdx.x;
    const int tx = tid & 15;
    const int ty = tid >> 4;
    const int row0 = blockIdx.y * 128;
    const int col0 = blockIdx.x * 128;

    const int KT = K >> 4;

    ull acc[8][4];
#pragma unroll
    for (int i = 0; i < 8; i++)
#pragma unroll
        for (int j = 0; j < 4; j++) acc[i][j] = 0ull;

    float4 av[2], bv[2];

#pragma unroll
    for (int p = 0; p < 2; p++) {
        int f4 = tid + p * 256;
        int arow = f4 >> 2, ak4 = (f4 & 3) * 4;
        int r = row0 + arow;
        float4 a;
        if (r < M) a = *reinterpret_cast<const float4*>(&A[(size_t)r * K + ak4]);
        else       a = make_float4(0.f, 0.f, 0.f, 0.f);
        As[0][ak4 + 0][arow] = a.x; As[0][ak4 + 1][arow] = a.y;
        As[0][ak4 + 2][arow] = a.z; As[0][ak4 + 3][arow] = a.w;
        int brow = f4 >> 5, bc4 = (f4 & 31) * 4;
        *reinterpret_cast<float4*>(&Bs[0][brow][bc4]) =
            *reinterpret_cast<const float4*>(&B[(size_t)brow * Nn + col0 + bc4]);
    }
    __syncthreads();

    for (int kt = 0; kt < KT; kt++) {
        const int buf = kt & 1;
        if (kt + 1 < KT) {
            const int k0 = (kt + 1) << 4;
#pragma unroll
            for (int p = 0; p < 2; p++) {
                int f4 = tid + p * 256;
                int arow = f4 >> 2, ak4 = (f4 & 3) * 4;
                int r = row0 + arow;
                if (r < M) av[p] = *reinterpret_cast<const float4*>(&A[(size_t)r * K + k0 + ak4]);
                else       av[p] = make_float4(0.f, 0.f, 0.f, 0.f);
                int brow = f4 >> 5, bc4 = (f4 & 31) * 4;
                bv[p] = *reinterpret_cast<const float4*>(&B[(size_t)(k0 + brow) * Nn + col0 + bc4]);
            }
        }

#pragma unroll
        for (int k = 0; k < 16; k++) {
            float4 a0 = *reinterpret_cast<const float4*>(&As[buf][k][ty * 4]);
            float4 a1 = *reinterpret_cast<const float4*>(&As[buf][k][64 + ty * 4]);
            ulonglong2 b0 = *reinterpret_cast<const ulonglong2*>(&Bs[buf][k][tx * 4]);
            ulonglong2 b1 = *reinterpret_cast<const ulonglong2*>(&Bs[buf][k][64 + tx * 4]);
            ull bp0 = b0.x, bp1 = b0.y, bp2 = b1.x, bp3 = b1.y;
            float aa[8] = {a0.x, a0.y, a0.z, a0.w, a1.x, a1.y, a1.z, a1.w};
#pragma unroll
            for (int i = 0; i < 8; i++) {
                ull ap = pack2(aa[i], aa[i]);
                ffma2(acc[i][0], ap, bp0);
                ffma2(acc[i][1], ap, bp1);
                ffma2(acc[i][2], ap, bp2);
                ffma2(acc[i][3], ap, bp3);
            }
        }

        if (kt + 1 < KT) {
            const int nb = buf ^ 1;
#pragma unroll
            for (int p = 0; p < 2; p++) {
                int f4 = tid + p * 256;
                int arow = f4 >> 2, ak4 = (f4 & 3) * 4;
                As[nb][ak4 + 0][arow] = av[p].x; As[nb][ak4 + 1][arow] = av[p].y;
                As[nb][ak4 + 2][arow] = av[p].z; As[nb][ak4 + 3][arow] = av[p].w;
                int brow = f4 >> 5, bc4 = (f4 & 31) * 4;
                *reinterpret_cast<float4*>(&Bs[nb][brow][bc4]) = bv[p];
            }
        }
        __syncthreads();
    }

    float4 b_lo = make_float4(0.f, 0.f, 0.f, 0.f), b_hi = b_lo;
    if (bias) {
        b_lo = *reinterpret_cast<const float4*>(&bias[col0 + tx * 4]);
        b_hi = *reinterpret_cast<const float4*>(&bias[col0 + 64 + tx * 4]);
    }
#pragma unroll
    for (int i = 0; i < 8; i++) {
        int row = row0 + ((i < 4) ? (ty * 4 + i) : (64 + ty * 4 + (i - 4)));
        if (row >= M) continue;
        float o0, o1, o2, o3, o4, o5, o6, o7;
        unpack2(o0, o1, acc[i][0]); unpack2(o2, o3, acc[i][1]);
        unpack2(o4, o5, acc[i][2]); unpack2(o6, o7, acc[i][3]);
        float4 lo = make_float4(o0 + b_lo.x, o1 + b_lo.y, o2 + b_lo.z, o3 + b_lo.w);
        float4 hi = make_float4(o4 + b_hi.x, o5 + b_hi.y, o6 + b_hi.z, o7 + b_hi.w);
        *reinterpret_cast<float4*>(&C[(size_t)row * Nn + col0 + tx * 4]) = lo;
        *reinterpret_cast<float4*>(&C[(size_t)row * Nn + col0 + 64 + tx * 4]) = hi;
    }
}

__global__ void __launch_bounds__(256, 2) sgemm128(
    const float* __restrict__ A, const float* __restrict__ B,
    const float* __restrict__ bias, float* __restrict__ C,
    int M, int Nn, int K)
{
    sgemm_body(A, B, bias, C, M, Nn, K);
}

// shared-A batch (fc + gcn0)
__global__ void __launch_bounds__(256, 2) sgemm128_b2(
    const float* __restrict__ A,
    const float* __restrict__ B0, const float* __restrict__ B1,
    const float* __restrict__ bias0, const float* __restrict__ bias1,
    float* __restrict__ C0, float* __restrict__ C1,
    int M, int Nn, int K)
{
    if (blockIdx.z == 0) sgemm_body(A, B0, bias0, C0, M, Nn, K);
    else                 sgemm_body(A, B1, bias1, C1, M, Nn, K);
}

// general 2-batch (independent GEMMs: t3 and GCN layer-1)
__global__ void __launch_bounds__(256, 2) sgemm128_g2(
    const float* __restrict__ A0, const float* __restrict__ B0,
    const float* __restrict__ bias0, float* __restrict__ C0,
    const float* __restrict__ A1, const float* __restrict__ B1,
    const float* __restrict__ bias1, float* __restrict__ C1,
    int M, int Nn, int K)
{
    if (blockIdx.z == 0) sgemm_body(A0, B0, bias0, C0, M, Nn, K);
    else                 sgemm_body(A1, B1, bias1, C1, M, Nn, K);
}

// ------ atb body: C[256,256] += A[L,256]^T @ B[L,256] (split-K atomics) ----
__device__ __forceinline__ void atb_body(
    const float* __restrict__ A, const float* __restrict__ B,
    float* __restrict__ C, int L, int lstart, int lend)
{
    __shared__ __align__(16) float As[32][128];
    __shared__ __align__(16) float Bs[32][64];

    const int tid = threadIdx.x;
    const int tx = tid & 15;
    const int ty = tid >> 4;
    const int ar0 = blockIdx.y * 64;
    const int bc0 = blockIdx.x * 64;

    ull acc[4][2];
#pragma unroll
    for (int i = 0; i < 4; i++) { acc[i][0] = 0ull; acc[i][1] = 0ull; }

    for (int l0 = lstart; l0 < lend; l0 += 32) {
#pragma unroll
        for (int p = 0; p < 2; p++) {
            int id = tid + p * 256;
            int lr = id >> 4;
            int c4 = (id & 15) * 4;
            int l = l0 + lr;
            float4 avv, bvv;
            if (l < lend) {
                avv = *reinterpret_cast<const float4*>(&A[(size_t)l * HID + ar0 + c4]);
                bvv = *reinterpret_cast<const float4*>(&B[(size_t)l * HID + bc0 + c4]);
            } else { avv = make_float4(0,0,0,0); bvv = avv; }
            float am[4] = {avv.x, avv.y, avv.z, avv.w};
#pragma unroll
            for (int m = 0; m < 4; m++)
                *reinterpret_cast<ull*>(&As[lr][2 * (c4 + m)]) = pack2(am[m], am[m]);
            *reinterpret_cast<float4*>(&Bs[lr][c4]) = bvv;
        }
        __syncthreads();

#pragma unroll
        for (int l = 0; l < 32; l++) {
            ulonglong2 a01 = *reinterpret_cast<const ulonglong2*>(&As[l][ty * 8]);
            ulonglong2 a23 = *reinterpret_cast<const ulonglong2*>(&As[l][ty * 8 + 4]);
            ulonglong2 bp  = *reinterpret_cast<const ulonglong2*>(&Bs[l][tx * 4]);
            ull ap[4] = {a01.x, a01.y, a23.x, a23.y};
#pragma unroll
            for (int i = 0; i < 4; i++) {
                ffma2(acc[i][0], ap[i], bp.x);
                ffma2(acc[i][1], ap[i], bp.y);
            }
        }
        __syncthreads();
    }

#pragma unroll
    for (int i = 0; i < 4; i++) {
        float c0, c1, c2, c3;
        unpack2(c0, c1, acc[i][0]); unpack2(c2, c3, acc[i][1]);
        float* base = &C[(size_t)(ar0 + ty * 4 + i) * HID + bc0 + tx * 4];
        atomicAdd(base + 0, c0); atomicAdd(base + 1, c1);
        atomicAdd(base + 2, c2); atomicAdd(base + 3, c3);
    }
}

__global__ void __launch_bounds__(256) atb_sym_kernel(
    const float* __restrict__ A, float* __restrict__ C, int L, int rows_per_z)
{
    if (blockIdx.y > blockIdx.x) return;
    int lstart = blockIdx.z * rows_per_z;
    int lend = min(L, lstart + rows_per_z);
    atb_body(A, A, C, L, lstart, lend);
}

__global__ void __launch_bounds__(256) atb3_kernel(
    const float* __restrict__ S,
    const float* __restrict__ Wv, const float* __restrict__ Wk, const float* __restrict__ Wq,
    float* __restrict__ U, float* __restrict__ Pk, float* __restrict__ Pq)
{
    const float* B = (blockIdx.z == 0) ? Wv : (blockIdx.z == 1) ? Wk : Wq;
    float* C = (blockIdx.z == 0) ? U : (blockIdx.z == 1) ? Pk : Pq;
    atb_body(S, B, C, HID, 0, HID);
}

__global__ void __launch_bounds__(256) atb1_kernel(
    const float* __restrict__ A, const float* __restrict__ B, float* __restrict__ C)
{
    atb_body(A, B, C, HID, 0, HID);
}

// merged: symfill (blocks 0..255) + matvec3 (blocks 256..258)
__global__ void __launch_bounds__(256) smalls1_kernel(
    float* __restrict__ S,
    const float* __restrict__ Wk, const float* __restrict__ Wv,
    const float* __restrict__ Wq, const float* __restrict__ hs,
    float* __restrict__ kk, float* __restrict__ wvhs, float* __restrict__ kq)
{
    int b = blockIdx.x, j = threadIdx.x;
    if (b < 256) {
        if ((b >> 6) > (j >> 6))
            S[(size_t)b * HID + j] = S[(size_t)j * HID + b];
    } else {
        int w = b - 256;   // 0,1,2
        const float* W = (w == 0) ? Wk : (w == 1) ? Wv : Wq;
        float* o = (w == 0) ? kk : (w == 1) ? wvhs : kq;
        float a = 0.f;
        for (int l = 0; l < HID; l++) a = fmaf(W[(size_t)l * HID + j], hs[l], a);
        o[j] = a;
    }
}

// ---------------- warp-per-row LN + relu ----------------
__global__ void __launch_bounds__(256) ln_relu_w(
    const float4* __restrict__ t, const float4* __restrict__ g,
    const float4* __restrict__ b, float4* __restrict__ out)
{
    int row = blockIdx.x * 8 + (threadIdx.x >> 5);
    if (row >= N_NODES) return;
    int lane = threadIdx.x & 31;
    const float4* tr = t + (size_t)row * 64;
    float4 v0 = tr[lane], v1 = tr[lane + 32];
    float s  = warp_sum(sum8(v0, v1));
    float s2 = warp_sum(sumsq8(v0, v1));
    float mean = s * (1.f / HID);
    float var  = s2 * (1.f / HID) - mean * mean;
    float r = rsqrtf(var + 1e-5f);
    float4 g0 = g[lane], g1 = g[lane + 32], b0 = b[lane], b1 = b[lane + 32];
    float4 o0, o1;
    o0.x = fmaxf((v0.x - mean) * r * g0.x + b0.x, 0.f);
    o0.y = fmaxf((v0.y - mean) * r * g0.y + b0.y, 0.f);
    o0.z = fmaxf((v0.z - mean) * r * g0.z + b0.z, 0.f);
    o0.w = fmaxf((v0.w - mean) * r * g0.w + b0.w, 0.f);
    o1.x = fmaxf((v1.x - mean) * r * g1.x + b1.x, 0.f);
    o1.y = fmaxf((v1.y - mean) * r * g1.y + b1.y, 0.f);
    o1.z = fmaxf((v1.z - mean) * r * g1.z + b1.z, 0.f);
    o1.w = fmaxf((v1.w - mean) * r * g1.w + b1.w, 0.f);
    float4* orow = out + (size_t)row * 64;
    orow[lane] = o0; orow[lane + 32] = o1;
}

__global__ void __launch_bounds__(256) colsum_kernel(
    const float* __restrict__ k, float* __restrict__ colsum)
{
    int c = threadIdx.x;
    float acc = 0.f;
    for (int r = blockIdx.x; r < N_NODES; r += gridDim.x)
        acc += k[(size_t)r * HID + c];
    atomicAdd(&colsum[c], acc);
}

__global__ void __launch_bounds__(256) trace2_kernel(
    const float* __restrict__ Pk, const float* __restrict__ Wk,
    const float* __restrict__ bk, const float* __restrict__ kk,
    const float* __restrict__ Pq, const float* __restrict__ Wq,
    const float* __restrict__ bq, const float* __restrict__ kq,
    float* __restrict__ scal)
{
    __shared__ float sh[16];
    const float* P = blockIdx.x ? Pq : Pk;
    const float* W = blockIdx.x ? Wq : Wk;
    const float* b = blockIdx.x ? bq : bk;
    const float* wv = blockIdx.x ? kq : kk;
    float s = 0.f;
    for (int i = threadIdx.x; i < HID * HID; i += 256) s = fmaf(P[i], W[i], s);
    float bc_ = b[threadIdx.x];
    s += 2.f * bc_ * wv[threadIdx.x] + (float)N_NODES * bc_ * bc_;
    float tot = block_sum_256(s, sh);
    if (threadIdx.x == 0) scal[blockIdx.x ? 0 : 1] = tot;
}

__global__ void kvs_final_kernel(const float* __restrict__ kvs0,
                                 const float* __restrict__ kk, const float* __restrict__ wvhs,
                                 const float* __restrict__ bk, const float* __restrict__ bv,
                                 const float* __restrict__ scal,
                                 float* __restrict__ kvsF, float* __restrict__ kssum)
{
    int i = blockIdx.x, j = threadIdx.x;
    float sk = rsqrtf(scal[1]);
    float bki = bk[i];
    float val = kvs0[(size_t)i * HID + j] + kk[i] * bv[j] + bki * wvhs[j]
              + (float)N_NODES * bki * bv[j];
    kvsF[(size_t)i * HID + j] = val * sk;
    if (j == 0) kssum[i] = (kk[i] + (float)N_NODES * bki) * sk;
}

// merged q-prep: blocks 0..255 -> wqp row; block 256 -> bqp; blocks 257..288 -> w1
__global__ void __launch_bounds__(256) qprep_kernel(
    const float* __restrict__ Wq, const float* __restrict__ kvsF,
    const float* __restrict__ kssum, const float* __restrict__ bq,
    float* __restrict__ wqp, float* __restrict__ bqp, float* __restrict__ w1)
{
    int b = blockIdx.x, j = threadIdx.x;
    if (b < 256) {
        __shared__ float Ar[256];
        Ar[j] = Wq[(size_t)b * HID + j];
        __syncthreads();
        float acc = 0.f;
        for (int l = 0; l < HID; l++) acc = fmaf(Ar[l], kvsF[(size_t)l * HID + j], acc);
        wqp[(size_t)b * HID + j] = acc;
    } else if (b == 256) {
        __shared__ float bs[256];
        bs[j] = bq[j];
        __syncthreads();
        float a = 0.f;
        for (int l = 0; l < HID; l++) a = fmaf(kvsF[(size_t)l * HID + j], bs[l], a);
        bqp[j] = a;
    } else {
        int row = (b - 257) * 8 + (j >> 5);
        int lane = j & 31;
        const float4* wr = reinterpret_cast<const float4*>(&Wq[(size_t)row * HID]);
        const float4* ks = reinterpret_cast<const float4*>(kssum);
        float4 a0 = wr[lane], a1 = wr[lane + 32];
        float4 k0 = __ldg(&ks[lane]), k1 = __ldg(&ks[lane + 32]);
        float d = a0.x*k0.x + a0.y*k0.y + a0.z*k0.z + a0.w*k0.w
                + a1.x*k1.x + a1.y*k1.y + a1.z*k1.z + a1.w*k1.w;
        d = warp_sum(d);
        if (lane == 0) w1[row] = d;
    }
}

__global__ void __launch_bounds__(256) combine_kernel(
    const float* __restrict__ wqp, const float* __restrict__ Wv,
    const float* __restrict__ bqp, const float* __restrict__ bv,
    const float* __restrict__ bq, const float* __restrict__ kssum,
    float* __restrict__ scal, float* __restrict__ Wc, float* __restrict__ bc)
{
    __shared__ float sh[16];
    float rq = rsqrtf(scal[0]);
    int b = blockIdx.x, j = threadIdx.x;
    if (b < 256) {
        size_t o = (size_t)b * HID + j;
        Wc[o] = rq * wqp[o] + (float)N_NODES * Wv[o];
    } else {
        bc[j] = rq * bqp[j] + (float)N_NODES * bv[j];
        float s = block_sum_256(bq[j] * kssum[j], sh);
        if (j == 0) scal[2] = s;
    }
}

__global__ void __launch_bounds__(256) trans_epi_w(
    const float4* __restrict__ t3, const float4* __restrict__ h,
    const float4* __restrict__ w1, const float* __restrict__ scal,
    const float4* __restrict__ g1, const float4* __restrict__ b1,
    float4* __restrict__ out_xt)
{
    int row = blockIdx.x * 8 + (threadIdx.x >> 5);
    if (row >= N_NODES) return;
    int lane = threadIdx.x & 31;
    size_t ro = (size_t)row * 64;
    float4 h0 = h[ro + lane], h1v = h[ro + lane + 32];
    float4 wa = w1[lane], wb = w1[lane + 32];
    float dotl = h0.x*wa.x + h0.y*wa.y + h0.z*wa.z + h0.w*wa.w
               + h1v.x*wb.x + h1v.y*wb.y + h1v.z*wb.z + h1v.w*wb.w;
    float dot = warp_sum(dotl);
    float rq = rsqrtf(scal[0]);
    float denom = rq * (dot + scal[2]) + (float)N_NODES;
    float hi = 0.5f / denom;
    float4 t0 = t3[ro + lane], t1 = t3[ro + lane + 32];
    float4 a0, a1;
    a0.x = t0.x * hi + 0.5f * h0.x;  a0.y = t0.y * hi + 0.5f * h0.y;
    a0.z = t0.z * hi + 0.5f * h0.z;  a0.w = t0.w * hi + 0.5f * h0.w;
    a1.x = t1.x * hi + 0.5f * h1v.x; a1.y = t1.y * hi + 0.5f * h1v.y;
    a1.z = t1.z * hi + 0.5f * h1v.z; a1.w = t1.w * hi + 0.5f * h1v.w;
    float s  = warp_sum(sum8(a0, a1));
    float s2 = warp_sum(sumsq8(a0, a1));
    float mean = s * (1.f / HID);
    float var  = s2 * (1.f / HID) - mean * mean;
    float r = rsqrtf(var + 1e-5f);
    float4 gg0 = g1[lane], gg1 = g1[lane + 32], bb0 = b1[lane], bb1 = b1[lane + 32];
    float4 y0, y1;
    y0.x = fmaxf((a0.x - mean) * r * gg0.x + bb0.x, 0.f);
    y0.y = fmaxf((a0.y - mean) * r * gg0.y + bb0.y, 0.f);
    y0.z = fmaxf((a0.z - mean) * r * gg0.z + bb0.z, 0.f);
    y0.w = fmaxf((a0.w - mean) * r * gg0.w + bb0.w, 0.f);
    y1.x = fmaxf((a1.x - mean) * r * gg1.x + bb1.x, 0.f);
    y1.y = fmaxf((a1.y - mean) * r * gg1.y + bb1.y, 0.f);
    y1.z = fmaxf((a1.z - mean) * r * gg1.z + bb1.z, 0.f);
    y1.w = fmaxf((a1.w - mean) * r * gg1.w + bb1.w, 0.f);
    float ssn = warp_sum(sumsq8(y0, y1));
    float inv_n = 1.f / fmaxf(sqrtf(ssn), 1e-12f);
    y0.x *= inv_n; y0.y *= inv_n; y0.z *= inv_n; y0.w *= inv_n;
    y1.x *= inv_n; y1.y *= inv_n; y1.z *= inv_n; y1.w *= inv_n;
    out_xt[ro + lane] = y0; out_xt[ro + lane + 32] = y1;
}

__global__ void bn_coef_kernel(const float* __restrict__ gcn_b0, const float* __restrict__ gcn_b,
                               const float* __restrict__ bn_g, const float* __restrict__ bn_b,
                               const float* __restrict__ bn_mean, const float* __restrict__ bn_var,
                               float* __restrict__ coef_s, float* __restrict__ coef_t)
{
    int idx = blockIdx.x * blockDim.x + threadIdx.x;
    if (idx >= NUM_GC * HID) return;
    int layer = idx >> 8, c = idx & 255;
    float b = (layer == 0) ? gcn_b0[c] : gcn_b[(size_t)(layer - 1) * HID + c];
    float rs = rsqrtf(bn_var[idx] + 1e-5f);
    float sv = bn_g[idx] * rs;
    coef_s[idx] = sv;
    coef_t[idx] = (b - bn_mean[idx]) * sv + bn_b[idx];
}

// ---------------- CSR build ----------------
__global__ void count_kernel(const int* __restrict__ dst, int* __restrict__ cnt) {
    int e = blockIdx.x * blockDim.x + threadIdx.x;
    if (e < E_EDGES) atomicAdd(&cnt[dst[e]], 1);
}

__global__ void __launch_bounds__(256) scan_partial_kernel(
    const int* __restrict__ cnt, int* __restrict__ partial)
{
    __shared__ int sh[8];
    int i = blockIdx.x * 256 + threadIdx.x;
    int v = (i < N_NODES) ? cnt[i] : 0;
#pragma unroll
    for (int o = 16; o; o >>= 1) v += __shfl_xor_sync(0xffffffffu, v, o);
    if ((threadIdx.x & 31) == 0) sh[threadIdx.x >> 5] = v;
    __syncthreads();
    if (threadIdx.x < 8) {
        int t = sh[threadIdx.x];
#pragma unroll
        for (int o = 4; o; o >>= 1) t += __shfl_xor_sync(0xffu, t, o);
        if (threadIdx.x == 0) partial[blockIdx.x] = t;
    }
}

__global__ void __launch_bounds__(256) scan_base_kernel(
    const int* __restrict__ partial, int* __restrict__ pbase)
{
    __shared__ int sh[256];
    int t = threadIdx.x;
    int v = (t < SCANBLK) ? partial[t] : 0;
    sh[t] = v;
    __syncthreads();
#pragma unroll
    for (int d = 1; d < 256; d <<= 1) {
        int u = (t >= d) ? sh[t - d] : 0;
        __syncthreads();
        sh[t] += u;
        __syncthreads();
    }
    pbase[t] = sh[t] - v;
}

__global__ void __launch_bounds__(256) scan_fill_kernel(
    const int* __restrict__ cnt, const int* __restrict__ pbase,
    int* __restrict__ off, int* __restrict__ cur, float* __restrict__ dinv)
{
    __shared__ int wsum[8];
    int i = blockIdx.x * 256 + threadIdx.x;
    int lane = threadIdx.x & 31, wid = threadIdx.x >> 5;
    int c = (i < N_NODES) ? cnt[i] : 0;
    int v = c;
#pragma unroll
    for (int o = 1; o < 32; o <<= 1) {
        int u = __shfl_up_sync(0xffffffffu, v, o);
        if (lane >= o) v += u;
    }
    if (lane == 31) wsum[wid] = v;
    __syncthreads();
    if (threadIdx.x < 8) {
        int w = wsum[threadIdx.x];
#pragma unroll
        for (int o = 1; o < 8; o <<= 1) {
            int u = __shfl_up_sync(0xffu, w, o);
            if (threadIdx.x >= o) w += u;
        }
        wsum[threadIdx.x] = w;
    }
    __syncthreads();
    int wpre = (wid == 0) ? 0 : wsum[wid - 1];
    int excl = v - c + wpre + pbase[blockIdx.x];
    if (i < N_NODES) {
        off[i] = excl;
        cur[i] = excl;
        dinv[i] = rsqrtf((float)(c + 1));
    }
    if (i == N_NODES - 1) off[N_NODES] = E_EDGES;
}

__global__ void fill_kernel(const int* __restrict__ src, const int* __restrict__ dst,
                            const float* __restrict__ dinv,
                            int* __restrict__ cur, int* __restrict__ csrc,
                            float* __restrict__ cw)
{
    int e = blockIdx.x * blockDim.x + threadIdx.x;
    if (e >= E_EDGES) return;
    int d = dst[e];
    int s = src[e];
    int pos = atomicAdd(&cur[d], 1);
    csrc[pos] = s;
    cw[pos] = dinv[s];
}

// ------- CSR aggregation core --------
__device__ __forceinline__ float4 csr_agg_row(
    const float4* __restrict__ gw, const int* __restrict__ off,
    const int* __restrict__ csrc, const float* __restrict__ cw,
    float di, int row, int c4)
{
    float4 g = gw[(size_t)row * 64 + c4];
    float4 acc = make_float4(g.x * di, g.y * di, g.z * di, g.w * di);
    int e0 = off[row], e1 = off[row + 1];
    int j = e0;
    for (; j + 4 <= e1; j += 4) {
        int s0 = __ldg(&csrc[j]),     s1 = __ldg(&csrc[j + 1]);
        int s2 = __ldg(&csrc[j + 2]), s3 = __ldg(&csrc[j + 3]);
        float w0 = __ldg(&cw[j]),     w1 = __ldg(&cw[j + 1]);
        float w2 = __ldg(&cw[j + 2]), w3 = __ldg(&cw[j + 3]);
        float4 g0 = gw[(size_t)s0 * 64 + c4];
        float4 g1 = gw[(size_t)s1 * 64 + c4];
        float4 g2 = gw[(size_t)s2 * 64 + c4];
        float4 g3 = gw[(size_t)s3 * 64 + c4];
        acc.x = fmaf(w0, g0.x, fmaf(w1, g1.x, fmaf(w2, g2.x, fmaf(w3, g3.x, acc.x))));
        acc.y = fmaf(w0, g0.y, fmaf(w1, g1.y, fmaf(w2, g2.y, fmaf(w3, g3.y, acc.y))));
        acc.z = fmaf(w0, g0.z, fmaf(w1, g1.z, fmaf(w2, g2.z, fmaf(w3, g3.z, acc.z))));
        acc.w = fmaf(w0, g0.w, fmaf(w1, g1.w, fmaf(w2, g2.w, fmaf(w3, g3.w, acc.w))));
    }
    for (; j < e1; j++) {
        int s = __ldg(&csrc[j]);
        float w = __ldg(&cw[j]);
        float4 gv = gw[(size_t)s * 64 + c4];
        acc.x = fmaf(w, gv.x, acc.x);
        acc.y = fmaf(w, gv.y, acc.y);
        acc.z = fmaf(w, gv.z, acc.z);
        acc.w = fmaf(w, gv.w, acc.w);
    }
    acc.x *= di; acc.y *= di; acc.z *= di; acc.w *= di;
    return acc;
}

__global__ void __launch_bounds__(256) csr_agg_kernel(
    const float4* __restrict__ gw, const int* __restrict__ off,
    const int* __restrict__ csrc, const float* __restrict__ cw,
    const float* __restrict__ dinv,
    const float* __restrict__ aff_s, const float* __restrict__ aff_t,
    float4* __restrict__ outy)
{
    int row = blockIdx.x * 4 + (threadIdx.x >> 6);
    int c4 = threadIdx.x & 63;
    float di = dinv[row];
    float4 acc = csr_agg_row(gw, off, csrc, cw, di, row, c4);
    float4 s4 = *reinterpret_cast<const float4*>(&aff_s[c4 * 4]);
    float4 t4 = *reinterpret_cast<const float4*>(&aff_t[c4 * 4]);
    acc.x = fmaxf(fmaf(acc.x, s4.x, t4.x), 0.f);
    acc.y = fmaxf(fmaf(acc.y, s4.y, t4.y), 0.f);
    acc.z = fmaxf(fmaf(acc.z, s4.z, t4.z), 0.f);
    acc.w = fmaxf(fmaf(acc.w, s4.w, t4.w), 0.f);
    outy[(size_t)row * 64 + c4] = acc;
}

__global__ void __launch_bounds__(256) csr_agg_final(
    const float4* __restrict__ gw, const int* __restrict__ off,
    const int* __restrict__ csrc, const float* __restrict__ cw,
    const float* __restrict__ dinv,
    const float* __restrict__ aff_s, const float* __restrict__ aff_t,
    const int* __restrict__ batch,
    float4* __restrict__ out_g, float* __restrict__ out_pool)
{
    __shared__ float part[8];
    int sub = threadIdx.x >> 6;
    int row = blockIdx.x * 4 + sub;
    int c4 = threadIdx.x & 63;
    float di = dinv[row];
    float4 acc = csr_agg_row(gw, off, csrc, cw, di, row, c4);
    float4 s4 = *reinterpret_cast<const float4*>(&aff_s[c4 * 4]);
    float4 t4 = *reinterpret_cast<const float4*>(&aff_t[c4 * 4]);
    acc.x = fmaf(acc.x, s4.x, t4.x);
    acc.y = fmaf(acc.y, s4.y, t4.y);
    acc.z = fmaf(acc.z, s4.z, t4.z);
    acc.w = fmaf(acc.w, s4.w, t4.w);
    float ss = acc.x*acc.x + acc.y*acc.y + acc.z*acc.z + acc.w*acc.w;
    ss = warp_sum(ss);
    if ((threadIdx.x & 31) == 0) part[threadIdx.x >> 5] = ss;
    __syncthreads();
    float tot = part[sub * 2] + part[sub * 2 + 1];
    float inv_n = 1.f / fmaxf(sqrtf(tot), 1e-12f);
    acc.x *= inv_n; acc.y *= inv_n; acc.z *= inv_n; acc.w *= inv_n;
    out_g[(size_t)row * 64 + c4] = acc;
    int grp = __ldg(&batch[row]);
    float* p = &out_pool[(size_t)grp * HID + c4 * 4];
    asm volatile("red.global.add.v4.f32 [%0], {%1, %2, %3, %4};"
                 :: "l"(p), "f"(acc.x), "f"(acc.y), "f"(acc.z), "f"(acc.w) : "memory");
}

// ---------------- launcher ----------------
extern "C" void kernel_launch(void* const* d_in, const int* in_sizes, int n_in,
                              void* d_out, int out_size)
{
    const float* x       = (const float*)d_in[0];
    const int*   edge    = (const int*)  d_in[1];
    const int*   batch   = (const int*)  d_in[2];
    // d_in[3] = beta (unused)
    const float* fc_W    = (const float*)d_in[4];
    const float* fc_b    = (const float*)d_in[5];
    const float* ln0_g   = (const float*)d_in[6];
    const float* ln0_b   = (const float*)d_in[7];
    const float* Wq      = (const float*)d_in[8];
    const float* bq      = (const float*)d_in[9];
    const float* Wk      = (const float*)d_in[10];
    const float* bk      = (const float*)d_in[11];
    const float* Wv      = (const float*)d_in[12];
    const float* bv      = (const float*)d_in[13];
    const float* ln1_g   = (const float*)d_in[14];
    const float* ln1_b   = (const float*)d_in[15];
    const float* gcn_W0  = (const float*)d_in[16];
    const float* gcn_b0  = (const float*)d_in[17];
    const float* gcn_W   = (const float*)d_in[18];
    const float* gcn_b   = (const float*)d_in[19];
    const float* bn_g    = (const float*)d_in[20];
    const float* bn_b    = (const float*)d_in[21];
    const float* bn_mean = (const float*)d_in[22];
    const float* bn_var  = (const float*)d_in[23];

    const int* src = edge;
    const int* dst = edge + E_EDGES;

    float* out      = (float*)d_out;
    float* out_pool = out;
    float* out_g    = out + (size_t)G_GRP * HID;
    float* out_xt   = out_g + (size_t)N_NODES * HID;

    float* fbase = nullptr;
    int* ibase = nullptr;
    cudaGetSymbolAddress((void**)&fbase, d_scratch);
    cudaGetSymbolAddress((void**)&ibase, d_iscratch);

    float* p_h   = fbase;
    float* p_t   = fbase + (size_t)1 * NH;
    float* p_gw  = fbase + (size_t)2 * NH;
    float* p_y   = fbase + (size_t)3 * NH;

    float* p_sm   = fbase + (size_t)4 * NH;
    float* p_S    = p_sm;
    float* p_U    = p_S + HID * HID;
    float* p_Pk   = p_U + HID * HID;
    float* p_Pq   = p_Pk + HID * HID;
    float* p_kvs0 = p_Pq + HID * HID;
    float* p_hs   = p_kvs0 + HID * HID;
    float* p_scal = p_hs + HID;
    const int ZSM = 5 * HID * HID + HID + 16;

    float* p_kvsF  = p_scal + 16;
    float* p_wqp   = p_kvsF + HID * HID;
    float* p_Wc    = p_wqp + HID * HID;
    float* p_kssum = p_Wc + HID * HID;
    float* p_kk    = p_kssum + HID;
    float* p_wvhs  = p_kk + HID;
    float* p_kq    = p_wvhs + HID;
    float* p_bqp   = p_kq + HID;
    float* p_bc    = p_bqp + HID;
    float* p_w1    = p_bc + HID;
    float* p_dinv  = p_w1 + HID;
    float* p_cs    = p_dinv + N_NODES;
    float* p_ct    = p_cs + NUM_GC * HID;
    float* p_cw    = p_ct + NUM_GC * HID;

    int* p_cnt     = ibase;
    int* p_off     = p_cnt + N_NODES;
    int* p_cur     = p_off + N_NODES + 1;
    int* p_csrc    = p_cur + N_NODES;
    int* p_partial = p_csrc + E_EDGES;
    int* p_pbase   = p_partial + 256;

    const dim3 gg(HID / 128, (N_NODES + 127) / 128);
    const dim3 gg2(HID / 128, (N_NODES + 127) / 128, 2);
    const int THR = 256;

    // ===== init + CSR build + coefficients =====
    bn_coef_kernel<<<(NUM_GC * HID + THR - 1) / THR, THR>>>(
        gcn_b0, gcn_b, bn_g, bn_b, bn_mean, bn_var, p_cs, p_ct);
    {
        int nmax = ZSM;
        if (G_GRP * HID > nmax) nmax = G_GRP * HID;
        if (N_NODES > nmax) nmax = N_NODES;
        init_kernel<<<(nmax + THR - 1) / THR, THR>>>(
            p_cnt, N_NODES, out_pool, G_GRP * HID, p_sm, ZSM);
    }
    count_kernel<<<(E_EDGES + THR - 1) / THR, THR>>>(dst, p_cnt);
    scan_partial_kernel<<<SCANBLK, THR>>>(p_cnt, p_partial);
    scan_base_kernel<<<1, THR>>>(p_partial, p_pbase);
    scan_fill_kernel<<<SCANBLK, THR>>>(p_cnt, p_pbase, p_off, p_cur, p_dinv);
    fill_kernel<<<(E_EDGES + THR - 1) / THR, THR>>>(src, dst, p_dinv, p_cur, p_csrc, p_cw);

    // ===== batched K=128 GEMMs: fc and gcn layer-0 (both A = x) =====
    sgemm128_b2<<<gg2, THR>>>(x, fc_W, gcn_W0, fc_b, nullptr,
                              p_t, p_gw, N_NODES, HID, F_IN);
    ln_relu_w<<<NROWBLK, THR>>>((const float4*)p_t, (const float4*)ln0_g,
                                (const float4*)ln0_b, (float4*)p_h);

    // ===== csr_agg layer 0 =====
    csr_agg_kernel<<<N_NODES / 4, THR>>>(
        (const float4*)p_gw, p_off, p_csrc, p_cw, p_dinv,
        p_cs, p_ct, (float4*)p_y);

    // ===== attention small-matrix algebra =====
    colsum_kernel<<<2048, THR>>>(p_h, p_hs);
    {
        const int SPLITS = 64;
        const int rows_per_z = (N_NODES + SPLITS - 1) / SPLITS;
        atb_sym_kernel<<<dim3(HID / 64, HID / 64, SPLITS), THR>>>(p_h, p_S, N_NODES, rows_per_z);
    }
    smalls1_kernel<<<HID + 3, THR>>>(p_S, Wk, Wv, Wq, p_hs, p_kk, p_wvhs, p_kq);
    atb3_kernel<<<dim3(4, 4, 3), THR>>>(p_S, Wv, Wk, Wq, p_U, p_Pk, p_Pq);
    atb1_kernel<<<dim3(4, 4), THR>>>(Wk, p_U, p_kvs0);
    trace2_kernel<<<2, THR>>>(p_Pk, Wk, bk, p_kk, p_Pq, Wq, bq, p_kq, p_scal);
    kvs_final_kernel<<<HID, THR>>>(p_kvs0, p_kk, p_wvhs, bk, bv, p_scal, p_kvsF, p_kssum);
    qprep_kernel<<<HID + 1 + HID / 8, THR>>>(Wq, p_kvsF, p_kssum, bq, p_wqp, p_bqp, p_w1);
    combine_kernel<<<HID + 1, THR>>>(p_wqp, Wv, p_bqp, bv, bq, p_kssum,
                                     p_scal, p_Wc, p_bc);

    // ===== batched independent GEMMs: t3 = H@Wc+bc AND GCN layer-1 =====
    sgemm128_g2<<<gg2, THR>>>(p_h, p_Wc, p_bc, p_t,
                              p_y, gcn_W, nullptr, p_gw,
                              N_NODES, HID, HID);
    trans_epi_w<<<NROWBLK, THR>>>((const float4*)p_t, (const float4*)p_h,
                                  (const float4*)p_w1, p_scal,
                                  (const float4*)ln1_g, (const float4*)ln1_b,
                                  (float4*)out_xt);

    // ===== remaining GCN layers =====
    csr_agg_kernel<<<N_NODES / 4, THR>>>(
        (const float4*)p_gw, p_off, p_csrc, p_cw, p_dinv,
        p_cs + 1 * HID, p_ct + 1 * HID, (float4*)p_y);

    for (int i = 2; i < NUM_GC; i++) {
        const float* W = gcn_W + (size_t)(i - 1) * HID * HID;
        sgemm128<<<gg, THR>>>(p_y, W, nullptr, p_gw, N_NODES, HID, HID);
        if (i < NUM_GC - 1) {
            csr_agg_kernel<<<N_NODES / 4, THR>>>(
                (const float4*)p_gw, p_off, p_csrc, p_cw, p_dinv,
                p_cs + (size_t)i * HID, p_ct + (size_t)i * HID, (float4*)p_y);
        } else {
            csr_agg_final<<<N_NODES / 4, THR>>>(
                (const float4*)p_gw, p_off, p_csrc, p_cw, p_dinv,
                p_cs + (size_t)(NUM_GC - 1) * HID, p_ct + (size_t)(NUM_GC - 1) * HID,
                batch, (float4*)out_g, out_pool);
        }
    }
}